// round 9
// baseline (speedup 1.0000x reference)
#include <cuda_runtime.h>
#include <cuda_bf16.h>
#include <math.h>
#include <stdint.h>

// Problem constants
constexpr int B_  = 2;
constexpr int S_  = 2048;
constexpr int H_  = 1024;
constexpr int NH_ = 16;
constexpr int HD_ = 64;
constexpr int M_  = B_ * S_;   // 4096
constexpr int K_  = H_;        // 1024

// ---------------- scratch (device globals; no allocation allowed) ----------
__device__ __align__(16) __nv_bfloat16 g_qh[(size_t)B_ * NH_ * S_ * HD_];
__device__ __align__(16) __nv_bfloat16 g_ql[(size_t)B_ * NH_ * S_ * HD_];
__device__ __align__(16) __nv_bfloat16 g_kh[(size_t)B_ * NH_ * S_ * HD_];
__device__ __align__(16) __nv_bfloat16 g_kl[(size_t)B_ * NH_ * S_ * HD_];
__device__ __align__(16) __nv_bfloat16 g_vh[(size_t)B_ * NH_ * HD_ * S_];
__device__ __align__(16) __nv_bfloat16 g_vl[(size_t)B_ * NH_ * HD_ * S_];

__device__ __align__(16) __nv_bfloat16 g_xh[(size_t)M_ * K_];
__device__ __align__(16) __nv_bfloat16 g_xl[(size_t)M_ * K_];
__device__ __align__(16) __nv_bfloat16 g_wh[4][(size_t)H_ * K_];   // q,k,v,o
__device__ __align__(16) __nv_bfloat16 g_wl[4][(size_t)H_ * K_];
__device__ __align__(16) __nv_bfloat16 g_ah[(size_t)M_ * H_];
__device__ __align__(16) __nv_bfloat16 g_al[(size_t)M_ * H_];

// ---------------- PTX helpers ----------------------------------------------
__device__ __forceinline__ uint32_t smem_u32(const void* p) {
    uint32_t a;
    asm("{ .reg .u64 t; cvta.to.shared.u64 t, %1; cvt.u32.u64 %0, t; }"
        : "=r"(a) : "l"(p));
    return a;
}

#define CPA16(dst, src) \
    asm volatile("cp.async.ca.shared.global [%0], [%1], 16;" \
                 :: "r"(dst), "l"(src) : "memory")
#define CP_COMMIT() asm volatile("cp.async.commit_group;" ::: "memory")
#define CP_WAIT(n)  asm volatile("cp.async.wait_group %0;" :: "n"(n) : "memory")

#define LDSM4(r, addr) \
    asm volatile("ldmatrix.sync.aligned.m8n8.x4.shared.b16 {%0,%1,%2,%3}, [%4];" \
                 : "=r"((r)[0]), "=r"((r)[1]), "=r"((r)[2]), "=r"((r)[3])        \
                 : "r"(addr))

#define MMA16816(c, a, b) \
    asm volatile("mma.sync.aligned.m16n8k16.row.col.f32.bf16.bf16.f32 "          \
                 "{%0,%1,%2,%3}, {%4,%5,%6,%7}, {%8,%9}, {%0,%1,%2,%3};"         \
                 : "+f"((c)[0]), "+f"((c)[1]), "+f"((c)[2]), "+f"((c)[3])        \
                 : "r"((a)[0]), "r"((a)[1]), "r"((a)[2]), "r"((a)[3]),           \
                   "r"((b)[0]), "r"((b)[1]))

__device__ __forceinline__ uint32_t bf2pack(float a, float b) {
    __nv_bfloat162 t = __floats2bfloat162_rn(a, b);
    return *(uint32_t*)&t;
}

// ---------------------------------------------------------------------------
// fp32 -> bf16 hi/lo split, all 5 inputs in one launch.
// ---------------------------------------------------------------------------
__global__ void __launch_bounds__(256) cvt_all(const float* __restrict__ x,
                                               const float* __restrict__ wq,
                                               const float* __restrict__ wk,
                                               const float* __restrict__ wv,
                                               const float* __restrict__ wo)
{
    int i = (blockIdx.x * blockDim.x + threadIdx.x) * 4;
    const float* s;
    __nv_bfloat16 *dh, *dl;
    int off;
    if (i < M_ * K_) {
        s = x; dh = g_xh; dl = g_xl; off = i;
    } else {
        const int j = i - M_ * K_;
        const int r = j >> 20;               // / (H_*K_)
        off = j & (H_ * K_ - 1);
        s = (r == 0) ? wq : (r == 1) ? wk : (r == 2) ? wv : wo;
        dh = g_wh[r]; dl = g_wl[r];
    }

    float4 v = *(const float4*)(s + off);
    float vv[4] = {v.x, v.y, v.z, v.w};
    __nv_bfloat16 h[4], l[4];
#pragma unroll
    for (int j = 0; j < 4; j++) {
        h[j] = __float2bfloat16(vv[j]);
        l[j] = __float2bfloat16(vv[j] - __bfloat162float(h[j]));
    }
    *(__nv_bfloat162*)&dh[off]     = __nv_bfloat162(h[0], h[1]);
    *(__nv_bfloat162*)&dh[off + 2] = __nv_bfloat162(h[2], h[3]);
    *(__nv_bfloat162*)&dl[off]     = __nv_bfloat162(l[0], l[1]);
    *(__nv_bfloat162*)&dl[off + 2] = __nv_bfloat162(l[2], l[3]);
}

// ---------------------------------------------------------------------------
// HMMA GEMM, bf16 3-way split. CTA 128x128, BK=32, 128 thr (4 warps),
// warp tile 64x64 (MMA:LDSM = 6:1), cp.async double buffer, 2 CTAs/SM.
// ---------------------------------------------------------------------------
constexpr int LDS_B  = 80;
constexpr int ASZ    = 128 * LDS_B;    // 10240
constexpr int STAGE  = 4 * ASZ;
constexpr int GEMM_SMEM = 2 * STAGE;   // 81920

__global__ void __launch_bounds__(128, 2) hgemm(const float* __restrict__ bias0,
                                                const float* __restrict__ bias1,
                                                const float* __restrict__ bias2,
                                                float* __restrict__ Cext,
                                                const float* __restrict__ cosb,
                                                const float* __restrict__ sinb,
                                                int fixed_mode)
{
    extern __shared__ char sm[];
    const int mode = (fixed_mode >= 0) ? fixed_mode : (int)blockIdx.z;
    const float* bias = (mode == 1) ? bias1 : (mode == 2) ? bias2 : bias0;

    const int tid  = threadIdx.x;
    const int lane = tid & 31;
    const int wid  = tid >> 5;           // 0..3
    const int wm   = (wid >> 1) * 64;    // 0 / 64
    const int wn   = (wid & 1) * 64;     // 0 / 64
    const int n0 = blockIdx.x * 128, m0 = blockIdx.y * 128;

    const __nv_bfloat16* Ah = (mode == 3) ? g_ah : g_xh;
    const __nv_bfloat16* Al = (mode == 3) ? g_al : g_xl;
    const __nv_bfloat16* Wh = g_wh[mode];
    const __nv_bfloat16* Wl = g_wl[mode];

    const uint32_t sbase = smem_u32(sm);

    // loader: thread owns one full 64B row per array per chunk
    const size_t gA = (size_t)(m0 + tid) * K_;
    const size_t gW = (size_t)(n0 + tid) * K_;
    const uint32_t srow = (uint32_t)(tid * LDS_B);

    float acc[4][8][4];
#pragma unroll
    for (int a = 0; a < 4; a++)
#pragma unroll
        for (int b = 0; b < 8; b++)
#pragma unroll
            for (int c = 0; c < 4; c++) acc[a][b][c] = 0.0f;

#define LOAD_CHUNK(ch) do {                                                   \
    const uint32_t st = sbase + ((ch) & 1) * STAGE + srow;                    \
    const char* pa = (const char*)(Ah + gA + (ch) * 32);                      \
    const char* pl = (const char*)(Al + gA + (ch) * 32);                      \
    const char* pw = (const char*)(Wh + gW + (ch) * 32);                      \
    const char* pv = (const char*)(Wl + gW + (ch) * 32);                      \
    CPA16(st,           pa);      CPA16(st + 16,           pa + 16);          \
    CPA16(st + 32,      pa + 32); CPA16(st + 48,           pa + 48);          \
    CPA16(st + ASZ,     pl);      CPA16(st + ASZ + 16,     pl + 16);          \
    CPA16(st + ASZ + 32, pl + 32); CPA16(st + ASZ + 48,    pl + 48);          \
    CPA16(st + 2 * ASZ, pw);      CPA16(st + 2 * ASZ + 16, pw + 16);          \
    CPA16(st + 2 * ASZ + 32, pw + 32); CPA16(st + 2 * ASZ + 48, pw + 48);     \
    CPA16(st + 3 * ASZ, pv);      CPA16(st + 3 * ASZ + 16, pv + 16);          \
    CPA16(st + 3 * ASZ + 32, pv + 32); CPA16(st + 3 * ASZ + 48, pv + 48);     \
    CP_COMMIT();                                                              \
} while (0)

    LOAD_CHUNK(0);

    for (int ch = 0; ch < 32; ch++) {
        if (ch < 31) { LOAD_CHUNK(ch + 1); CP_WAIT(1); }
        else         { CP_WAIT(0); }
        __syncthreads();

        const uint32_t stg = sbase + (ch & 1) * STAGE;
#pragma unroll
        for (int ks = 0; ks < 2; ks++) {
            const int kb = ks * 32;
            // B fragments: 64 cols -> 4 LDSM.x4 hi + 4 lo
            uint32_t bH[8][2], bL[8][2];
#pragma unroll
            for (int nh = 0; nh < 4; nh++) {
                uint32_t bd = stg + 2 * ASZ
                    + (uint32_t)((wn + nh * 16 + ((lane >> 4) << 3) + (lane & 7)) * LDS_B
                                 + kb + (((lane >> 3) & 1) << 4));
                uint32_t r[4];
                LDSM4(r, bd);
                bH[nh * 2][0] = r[0]; bH[nh * 2][1] = r[1];
                bH[nh * 2 + 1][0] = r[2]; bH[nh * 2 + 1][1] = r[3];
                LDSM4(r, bd + ASZ);
                bL[nh * 2][0] = r[0]; bL[nh * 2][1] = r[1];
                bL[nh * 2 + 1][0] = r[2]; bL[nh * 2 + 1][1] = r[3];
            }
#pragma unroll
            for (int mi = 0; mi < 4; mi++) {
                uint32_t aH[4], aL[4];
                const uint32_t ad = stg + (uint32_t)((wm + mi * 16 + (lane & 15)) * LDS_B
                                                     + kb + ((lane >> 4) << 4));
                LDSM4(aH, ad);
                LDSM4(aL, ad + ASZ);
#pragma unroll
                for (int ni = 0; ni < 8; ni++) MMA16816(acc[mi][ni], aH, bH[ni]);
#pragma unroll
                for (int ni = 0; ni < 8; ni++) MMA16816(acc[mi][ni], aH, bL[ni]);
#pragma unroll
                for (int ni = 0; ni < 8; ni++) MMA16816(acc[mi][ni], aL, bH[ni]);
            }
        }
        __syncthreads();
    }

    // ---- epilogue: stage C tile in smem, then fused writeout
    constexpr int LDC = 132;
    float* Csm = (float*)sm;
#pragma unroll
    for (int mi = 0; mi < 4; mi++) {
        const int row = wm + mi * 16 + (lane >> 2);
#pragma unroll
        for (int ni = 0; ni < 8; ni++) {
            const int col = wn + ni * 8 + (lane & 3) * 2;
            *(float2*)&Csm[row * LDC + col] =
                make_float2(acc[mi][ni][0], acc[mi][ni][1]);
            *(float2*)&Csm[(row + 8) * LDC + col] =
                make_float2(acc[mi][ni][2], acc[mi][ni][3]);
        }
    }
    __syncthreads();

    if (mode <= 1) {
        __nv_bfloat16* Ch = (mode == 0) ? g_qh : g_kh;
        __nv_bfloat16* Cl = (mode == 0) ? g_ql : g_kl;
#pragma unroll 2
        for (int i = 0; i < 32; i++) {
            const int id  = tid + 128 * i;        // 4096 tasks
            const int dp  = id & 15;
            const int hh  = (id >> 4) & 1;
            const int row = id >> 5;
            const int d0  = dp * 2;
            const int m   = m0 + row;
            const int s   = m & (S_ - 1);
            const int bb  = m >> 11;
            float oA[2], oB[2];
#pragma unroll
            for (int e = 0; e < 2; e++) {
                const int d = d0 + e, c = hh * 64 + d;
                const float v0 = Csm[row * LDC + c]      + bias[n0 + c];
                const float v1 = Csm[row * LDC + c + 32] + bias[n0 + c + 32];
                const float cs0 = cosb[s * HD_ + d],      sn0 = sinb[s * HD_ + d];
                const float cs1 = cosb[s * HD_ + d + 32], sn1 = sinb[s * HD_ + d + 32];
                oA[e] = v0 * cs0 - v1 * sn0;
                oB[e] = v1 * cs1 + v0 * sn1;
            }
            const int hidx = (n0 >> 6) + hh;
            const size_t base = ((size_t)(bb * NH_ + hidx) * S_ + s) * HD_;
            const __nv_bfloat16 a0 = __float2bfloat16(oA[0]);
            const __nv_bfloat16 a1 = __float2bfloat16(oA[1]);
            const __nv_bfloat16 c0 = __float2bfloat16(oB[0]);
            const __nv_bfloat16 c1 = __float2bfloat16(oB[1]);
            *(__nv_bfloat162*)&Ch[base + d0]      = __nv_bfloat162(a0, a1);
            *(__nv_bfloat162*)&Ch[base + d0 + 32] = __nv_bfloat162(c0, c1);
            *(__nv_bfloat162*)&Cl[base + d0] = __nv_bfloat162(
                __float2bfloat16(oA[0] - __bfloat162float(a0)),
                __float2bfloat16(oA[1] - __bfloat162float(a1)));
            *(__nv_bfloat162*)&Cl[base + d0 + 32] = __nv_bfloat162(
                __float2bfloat16(oB[0] - __bfloat162float(c0)),
                __float2bfloat16(oB[1] - __bfloat162float(c1)));
        }
    } else if (mode == 2) {
#pragma unroll 2
        for (int i = 0; i < 64; i++) {
            const int id  = tid + 128 * i;        // 8192 tasks
            const int sp  = id & 63;
            const int c   = id >> 6;
            const int row0 = sp * 2;
            const int m   = m0 + row0;
            const int s   = m & (S_ - 1);
            const int bb  = m >> 11;
            const int n   = n0 + c;
            const int hidx = n >> 6, d = n & 63;
            const float v0 = Csm[row0 * LDC + c]       + bias[n];
            const float v1 = Csm[(row0 + 1) * LDC + c] + bias[n];
            const __nv_bfloat16 h0 = __float2bfloat16(v0);
            const __nv_bfloat16 h1 = __float2bfloat16(v1);
            const size_t o = ((size_t)(bb * NH_ + hidx) * HD_ + d) * S_ + s;
            *(__nv_bfloat162*)&g_vh[o] = __nv_bfloat162(h0, h1);
            *(__nv_bfloat162*)&g_vl[o] = __nv_bfloat162(
                __float2bfloat16(v0 - __bfloat162float(h0)),
                __float2bfloat16(v1 - __bfloat162float(h1)));
        }
    } else {
#pragma unroll 4
        for (int i = 0; i < 32; i++) {
            const int id  = tid + 128 * i;        // 4096 float4 tasks
            const int c4  = (id & 31) * 4;
            const int row = id >> 5;
            const int m   = m0 + row;
            const int n   = n0 + c4;
            float4 v;
            v.x = Csm[row * LDC + c4 + 0] + bias[n + 0];
            v.y = Csm[row * LDC + c4 + 1] + bias[n + 1];
            v.z = Csm[row * LDC + c4 + 2] + bias[n + 2];
            v.w = Csm[row * LDC + c4 + 3] + bias[n + 3];
            *(float4*)&Cext[(size_t)m * H_ + n] = v;
        }
    }
}

// ---------------------------------------------------------------------------
// Flash attention, HMMA bf16 3-way split (unchanged from round 8).
// ---------------------------------------------------------------------------
constexpr int LDSA     = 144;
constexpr int QBYTES   = 2 * 128 * LDSA;        // 36864
constexpr int KVSTAGE  = 4 * 64 * LDSA;         // 36864
constexpr int ATT2_SMEM = QBYTES + 3 * KVSTAGE; // 147456

__global__ void __launch_bounds__(256) attn_hmma(const int* __restrict__ mask)
{
    extern __shared__ char sm[];
    const uint32_t sb = smem_u32(sm);
    __shared__ int msk[3][64];

    const int tid = threadIdx.x, lane = tid & 31, w = tid >> 5;
    const int bh = blockIdx.y, b = bh >> 4, h = bh & 15;
    const int q0 = blockIdx.x * 128;

    const __nv_bfloat16* Qhp = g_qh + (size_t)bh * S_ * HD_;
    const __nv_bfloat16* Qlp = g_ql + (size_t)bh * S_ * HD_;
    const __nv_bfloat16* Khp = g_kh + (size_t)bh * S_ * HD_;
    const __nv_bfloat16* Klp = g_kl + (size_t)bh * S_ * HD_;
    const __nv_bfloat16* Vhp = g_vh + (size_t)bh * HD_ * S_;
    const __nv_bfloat16* Vlp = g_vl + (size_t)bh * HD_ * S_;
    const int* maskp = mask + b * S_;

#pragma unroll
    for (int i = 0; i < 4; i++) {
        const int idx = tid + 256 * i;
        const int row = idx >> 3, chk = idx & 7;
        const uint32_t dst = sb + (uint32_t)(row * LDSA + chk * 16);
        CPA16(dst,         (const char*)(Qhp + (size_t)(q0 + row) * HD_ + chk * 8));
        CPA16(dst + 18432, (const char*)(Qlp + (size_t)(q0 + row) * HD_ + chk * 8));
    }

#define LOADKV(t) do {                                                          \
    const int kt_ = (t) * 64;                                                   \
    const uint32_t st = sb + QBYTES + ((t) % 3) * KVSTAGE;                      \
    _Pragma("unroll")                                                           \
    for (int i_ = 0; i_ < 2; i_++) {                                            \
        const int idx_ = tid + 256 * i_;                                        \
        const int row_ = idx_ >> 3, ch_ = idx_ & 7;                             \
        const uint32_t ro_ = (uint32_t)(row_ * LDSA + ch_ * 16);                \
        CPA16(st + ro_,          (const char*)(Khp + (size_t)(kt_ + row_) * HD_ + ch_ * 8)); \
        CPA16(st + 9216 + ro_,   (const char*)(Klp + (size_t)(kt_ + row_) * HD_ + ch_ * 8)); \
        CPA16(st + 18432 + ro_,  (const char*)(Vhp + (size_t)row_ * S_ + kt_ + ch_ * 8));    \
        CPA16(st + 27648 + ro_,  (const char*)(Vlp + (size_t)row_ * S_ + kt_ + ch_ * 8));    \
    }                                                                           \
    if (tid < 64) msk[(t) % 3][tid] = maskp[kt_ + tid];                         \
    CP_COMMIT();                                                                \
} while (0)

    LOADKV(0);
    LOADKV(1);

    float m_[2] = {-1e30f, -1e30f}, l_[2] = {0.0f, 0.0f};
    float oacc[8][4];
#pragma unroll
    for (int n = 0; n < 8; n++)
#pragma unroll
        for (int j = 0; j < 4; j++) oacc[n][j] = 0.0f;

    uint32_t qfh[4][4], qfl[4][4];
    const int c01 = (lane & 3) * 2;
    constexpr int NT = S_ / 64;

    for (int t = 0; t < NT; t++) {
        if (t >= NT - 2) { CP_WAIT(0); }
        else             { CP_WAIT(1); }
        __syncthreads();
        if (t + 2 < NT) LOADKV(t + 2);

        if (t == 0) {
#pragma unroll
            for (int kk = 0; kk < 4; kk++) {
                const uint32_t ad = sb + (uint32_t)((w * 16 + (lane & 15)) * LDSA
                                                    + kk * 32 + ((lane >> 4) << 4));
                LDSM4(qfh[kk], ad);
                LDSM4(qfl[kk], ad + 18432);
            }
        }

        const uint32_t kst = sb + QBYTES + (t % 3) * KVSTAGE;

        float sacc[8][4];
#pragma unroll
        for (int n = 0; n < 8; n++)
#pragma unroll
            for (int j = 0; j < 4; j++) sacc[n][j] = 0.0f;

#pragma unroll
        for (int kk = 0; kk < 4; kk++) {
#pragma unroll
            for (int np = 0; np < 2; np++) {
                const int nh0 = np * 2, nh1 = np * 2 + 1;
                const uint32_t bd0 = kst
                    + (uint32_t)((nh0 * 16 + ((lane >> 4) << 3) + (lane & 7)) * LDSA
                                 + kk * 32 + (((lane >> 3) & 1) << 4));
                const uint32_t bd1 = bd0 + 16 * LDSA;
                uint32_t rh0[4], rl0[4], rh1[4], rl1[4];
                LDSM4(rh0, bd0); LDSM4(rl0, bd0 + 9216);
                LDSM4(rh1, bd1); LDSM4(rl1, bd1 + 9216);
                uint32_t b00[2] = {rh0[0], rh0[1]}, b01[2] = {rh0[2], rh0[3]};
                uint32_t b10[2] = {rh1[0], rh1[1]}, b11[2] = {rh1[2], rh1[3]};
                uint32_t d00[2] = {rl0[0], rl0[1]}, d01[2] = {rl0[2], rl0[3]};
                uint32_t d10[2] = {rl1[0], rl1[1]}, d11[2] = {rl1[2], rl1[3]};
                float* s0 = sacc[nh0 * 2];     float* s1 = sacc[nh0 * 2 + 1];
                float* s2 = sacc[nh1 * 2];     float* s3 = sacc[nh1 * 2 + 1];
                MMA16816(s0, qfh[kk], b00); MMA16816(s1, qfh[kk], b01);
                MMA16816(s2, qfh[kk], b10); MMA16816(s3, qfh[kk], b11);
                MMA16816(s0, qfh[kk], d00); MMA16816(s1, qfh[kk], d01);
                MMA16816(s2, qfh[kk], d10); MMA16816(s3, qfh[kk], d11);
                MMA16816(s0, qfl[kk], b00); MMA16816(s1, qfl[kk], b01);
                MMA16816(s2, qfl[kk], b10); MMA16816(s3, qfl[kk], b11);
            }
        }

        float mx[2] = {-1e30f, -1e30f};
#pragma unroll
        for (int n = 0; n < 8; n++) {
            const int cc = n * 8 + c01;
            const int mk0 = msk[t % 3][cc], mk1 = msk[t % 3][cc + 1];
#pragma unroll
            for (int j = 0; j < 4; j++) {
                float v = sacc[n][j] * 0.125f;
                v = ((j & 1) ? mk1 : mk0) ? v : -1e30f;
                sacc[n][j] = v;
                mx[j >> 1] = fmaxf(mx[j >> 1], v);
            }
        }
        float corr[2], rs[2] = {0.0f, 0.0f};
#pragma unroll
        for (int r = 0; r < 2; r++) {
            mx[r] = fmaxf(mx[r], __shfl_xor_sync(0xffffffffu, mx[r], 1, 4));
            mx[r] = fmaxf(mx[r], __shfl_xor_sync(0xffffffffu, mx[r], 2, 4));
            const float mn = fmaxf(m_[r], mx[r]);
            corr[r] = __expf(m_[r] - mn);
            m_[r] = mn;
        }
#pragma unroll
        for (int n = 0; n < 8; n++)
#pragma unroll
            for (int j = 0; j < 4; j++) {
                const float p = __expf(sacc[n][j] - m_[j >> 1]);
                sacc[n][j] = p;
                rs[j >> 1] += p;
            }
#pragma unroll
        for (int r = 0; r < 2; r++) {
            rs[r] += __shfl_xor_sync(0xffffffffu, rs[r], 1, 4);
            rs[r] += __shfl_xor_sync(0xffffffffu, rs[r], 2, 4);
            l_[r] = l_[r] * corr[r] + rs[r];
        }
#pragma unroll
        for (int n = 0; n < 8; n++)
#pragma unroll
            for (int j = 0; j < 4; j++) oacc[n][j] *= corr[j >> 1];

#pragma unroll
        for (int j = 0; j < 4; j++) {
            uint32_t aPh[4], aPl[4];
#pragma unroll
            for (int half = 0; half < 2; half++) {
                const float p0 = sacc[2 * j + half][0];
                const float p1 = sacc[2 * j + half][1];
                const float p2 = sacc[2 * j + half][2];
                const float p3 = sacc[2 * j + half][3];
                const float q0f = __bfloat162float(__float2bfloat16(p0));
                const float q1f = __bfloat162float(__float2bfloat16(p1));
                const float q2f = __bfloat162float(__float2bfloat16(p2));
                const float q3f = __bfloat162float(__float2bfloat16(p3));
                aPh[half * 2]     = bf2pack(p0, p1);
                aPh[half * 2 + 1] = bf2pack(p2, p3);
                aPl[half * 2]     = bf2pack(p0 - q0f, p1 - q1f);
                aPl[half * 2 + 1] = bf2pack(p2 - q2f, p3 - q3f);
            }
#pragma unroll
            for (int np = 0; np < 2; np++) {
                const int nh0 = np * 2, nh1 = np * 2 + 1;
                const uint32_t bd0 = kst + 18432
                    + (uint32_t)((nh0 * 16 + ((lane >> 4) << 3) + (lane & 7)) * LDSA
                                 + j * 32 + (((lane >> 3) & 1) << 4));
                const uint32_t bd1 = bd0 + 16 * LDSA;
                uint32_t rh0[4], rl0[4], rh1[4], rl1[4];
                LDSM4(rh0, bd0); LDSM4(rl0, bd0 + 9216);
                LDSM4(rh1, bd1); LDSM4(rl1, bd1 + 9216);
                uint32_t b00[2] = {rh0[0], rh0[1]}, b01[2] = {rh0[2], rh0[3]};
                uint32_t b10[2] = {rh1[0], rh1[1]}, b11[2] = {rh1[2], rh1[3]};
                uint32_t d00[2] = {rl0[0], rl0[1]}, d01[2] = {rl0[2], rl0[3]};
                uint32_t d10[2] = {rl1[0], rl1[1]}, d11[2] = {rl1[2], rl1[3]};
                float* o0 = oacc[nh0 * 2];     float* o1 = oacc[nh0 * 2 + 1];
                float* o2 = oacc[nh1 * 2];     float* o3 = oacc[nh1 * 2 + 1];
                MMA16816(o0, aPh, b00); MMA16816(o1, aPh, b01);
                MMA16816(o2, aPh, b10); MMA16816(o3, aPh, b11);
                MMA16816(o0, aPh, d00); MMA16816(o1, aPh, d01);
                MMA16816(o2, aPh, d10); MMA16816(o3, aPh, d11);
                MMA16816(o0, aPl, b00); MMA16816(o1, aPl, b01);
                MMA16816(o2, aPl, b10); MMA16816(o3, aPl, b11);
            }
        }
    }

    const int r0 = lane >> 2;
#pragma unroll
    for (int r = 0; r < 2; r++) {
        const float inv = 1.0f / l_[r];
        const int srow = q0 + w * 16 + r0 + 8 * r;
        const size_t base = ((size_t)b * S_ + srow) * H_ + h * 64 + c01;
#pragma unroll
        for (int n = 0; n < 8; n++) {
            const float v0 = oacc[n][2 * r]     * inv;
            const float v1 = oacc[n][2 * r + 1] * inv;
            const __nv_bfloat16 h0 = __float2bfloat16(v0);
            const __nv_bfloat16 h1 = __float2bfloat16(v1);
            *(__nv_bfloat162*)&g_ah[base + n * 8] = __nv_bfloat162(h0, h1);
            *(__nv_bfloat162*)&g_al[base + n * 8] = __nv_bfloat162(
                __float2bfloat16(v0 - __bfloat162float(h0)),
                __float2bfloat16(v1 - __bfloat162float(h1)));
        }
    }
}

// ---------------------------------------------------------------------------
extern "C" void kernel_launch(void* const* d_in, const int* in_sizes, int n_in,
                              void* d_out, int out_size)
{
    const float* x    = (const float*)d_in[0];
    const int*   mask = (const int*)  d_in[1];
    const float* cosb = (const float*)d_in[2];
    const float* sinb = (const float*)d_in[3];
    const float* Wq   = (const float*)d_in[4];
    const float* bq   = (const float*)d_in[5];
    const float* Wk   = (const float*)d_in[6];
    const float* bk   = (const float*)d_in[7];
    const float* Wv   = (const float*)d_in[8];
    const float* bv   = (const float*)d_in[9];
    const float* Wo   = (const float*)d_in[10];
    const float* bo   = (const float*)d_in[11];
    float* out = (float*)d_out;

    cudaFuncSetAttribute(hgemm,
                         cudaFuncAttributeMaxDynamicSharedMemorySize, GEMM_SMEM);
    cudaFuncSetAttribute(attn_hmma,
                         cudaFuncAttributeMaxDynamicSharedMemorySize, ATT2_SMEM);

    cvt_all<<<(M_ * K_ + 4 * H_ * K_) / 1024, 256>>>(x, Wq, Wk, Wv, Wo);

    dim3 gqkv(H_ / 128, M_ / 128, 3);
    hgemm<<<gqkv, 128, GEMM_SMEM>>>(bq, bk, bv, nullptr, cosb, sinb, -1);

    dim3 ag(S_ / 128, B_ * NH_);
    attn_hmma<<<ag, 256, ATT2_SMEM>>>(mask);

    dim3 gg(H_ / 128, M_ / 128);
    hgemm<<<gg, 128, GEMM_SMEM>>>(bo, bo, bo, out, cosb, sinb, 3);
}

// round 10
// speedup vs baseline: 1.1616x; 1.1616x over previous
#include <cuda_runtime.h>
#include <cuda_bf16.h>
#include <math.h>
#include <stdint.h>

// Problem constants
constexpr int B_  = 2;
constexpr int S_  = 2048;
constexpr int H_  = 1024;
constexpr int NH_ = 16;
constexpr int HD_ = 64;
constexpr int M_  = B_ * S_;   // 4096
constexpr int K_  = H_;        // 1024

// ---------------- scratch (device globals; no allocation allowed) ----------
__device__ __align__(16) __nv_bfloat16 g_qh[(size_t)B_ * NH_ * S_ * HD_];
__device__ __align__(16) __nv_bfloat16 g_ql[(size_t)B_ * NH_ * S_ * HD_];
__device__ __align__(16) __nv_bfloat16 g_kh[(size_t)B_ * NH_ * S_ * HD_];
__device__ __align__(16) __nv_bfloat16 g_kl[(size_t)B_ * NH_ * S_ * HD_];
__device__ __align__(16) __nv_bfloat16 g_vh[(size_t)B_ * NH_ * HD_ * S_];
__device__ __align__(16) __nv_bfloat16 g_vl[(size_t)B_ * NH_ * HD_ * S_];

__device__ __align__(16) __nv_bfloat16 g_xh[(size_t)M_ * K_];
__device__ __align__(16) __nv_bfloat16 g_xl[(size_t)M_ * K_];
__device__ __align__(16) __nv_bfloat16 g_wh[4][(size_t)H_ * K_];   // q,k,v,o
__device__ __align__(16) __nv_bfloat16 g_wl[4][(size_t)H_ * K_];
__device__ __align__(16) __nv_bfloat16 g_ah[(size_t)M_ * H_];
__device__ __align__(16) __nv_bfloat16 g_al[(size_t)M_ * H_];

// ---------------- PTX helpers ----------------------------------------------
__device__ __forceinline__ uint32_t smem_u32(const void* p) {
    uint32_t a;
    asm("{ .reg .u64 t; cvta.to.shared.u64 t, %1; cvt.u32.u64 %0, t; }"
        : "=r"(a) : "l"(p));
    return a;
}

#define CPA16(dst, src) \
    asm volatile("cp.async.ca.shared.global [%0], [%1], 16;" \
                 :: "r"(dst), "l"(src) : "memory")
#define CP_COMMIT() asm volatile("cp.async.commit_group;" ::: "memory")
#define CP_WAIT(n)  asm volatile("cp.async.wait_group %0;" :: "n"(n) : "memory")

#define LDSM4(r, addr) \
    asm volatile("ldmatrix.sync.aligned.m8n8.x4.shared.b16 {%0,%1,%2,%3}, [%4];" \
                 : "=r"((r)[0]), "=r"((r)[1]), "=r"((r)[2]), "=r"((r)[3])        \
                 : "r"(addr))

#define MMA16816(c, a, b) \
    asm volatile("mma.sync.aligned.m16n8k16.row.col.f32.bf16.bf16.f32 "          \
                 "{%0,%1,%2,%3}, {%4,%5,%6,%7}, {%8,%9}, {%0,%1,%2,%3};"         \
                 : "+f"((c)[0]), "+f"((c)[1]), "+f"((c)[2]), "+f"((c)[3])        \
                 : "r"((a)[0]), "r"((a)[1]), "r"((a)[2]), "r"((a)[3]),           \
                   "r"((b)[0]), "r"((b)[1]))

__device__ __forceinline__ uint32_t bf2pack(float a, float b) {
    __nv_bfloat162 t = __floats2bfloat162_rn(a, b);
    return *(uint32_t*)&t;
}

// ---------------------------------------------------------------------------
// fp32 -> bf16 hi/lo split, all 5 inputs in one launch.
// ---------------------------------------------------------------------------
__global__ void __launch_bounds__(256) cvt_all(const float* __restrict__ x,
                                               const float* __restrict__ wq,
                                               const float* __restrict__ wk,
                                               const float* __restrict__ wv,
                                               const float* __restrict__ wo)
{
    int i = (blockIdx.x * blockDim.x + threadIdx.x) * 4;
    const float* s;
    __nv_bfloat16 *dh, *dl;
    int off;
    if (i < M_ * K_) {
        s = x; dh = g_xh; dl = g_xl; off = i;
    } else {
        const int j = i - M_ * K_;
        const int r = j >> 20;               // / (H_*K_)
        off = j & (H_ * K_ - 1);
        s = (r == 0) ? wq : (r == 1) ? wk : (r == 2) ? wv : wo;
        dh = g_wh[r]; dl = g_wl[r];
    }

    float4 v = *(const float4*)(s + off);
    float vv[4] = {v.x, v.y, v.z, v.w};
    __nv_bfloat16 h[4], l[4];
#pragma unroll
    for (int j = 0; j < 4; j++) {
        h[j] = __float2bfloat16(vv[j]);
        l[j] = __float2bfloat16(vv[j] - __bfloat162float(h[j]));
    }
    *(__nv_bfloat162*)&dh[off]     = __nv_bfloat162(h[0], h[1]);
    *(__nv_bfloat162*)&dh[off + 2] = __nv_bfloat162(h[2], h[3]);
    *(__nv_bfloat162*)&dl[off]     = __nv_bfloat162(l[0], l[1]);
    *(__nv_bfloat162*)&dl[off + 2] = __nv_bfloat162(l[2], l[3]);
}

// ---------------------------------------------------------------------------
// HMMA GEMM, bf16 3-way split. CTA 128x128, BK=32, 256 thr (8 warps),
// warp tile 64x32, cp.async double buffer, single barrier per chunk.
// ---------------------------------------------------------------------------
constexpr int LDS_B  = 80;
constexpr int ASZ    = 128 * LDS_B;    // 10240
constexpr int STAGE  = 4 * ASZ;
constexpr int GEMM_SMEM = 2 * STAGE;   // 81920

__global__ void __launch_bounds__(256, 2) hgemm(const float* __restrict__ bias0,
                                                const float* __restrict__ bias1,
                                                const float* __restrict__ bias2,
                                                float* __restrict__ Cext,
                                                const float* __restrict__ cosb,
                                                const float* __restrict__ sinb,
                                                int fixed_mode)
{
    extern __shared__ char sm[];
    const int mode = (fixed_mode >= 0) ? fixed_mode : (int)blockIdx.z;
    const float* bias = (mode == 1) ? bias1 : (mode == 2) ? bias2 : bias0;

    const int tid  = threadIdx.x;
    const int lane = tid & 31;
    const int wid  = tid >> 5;
    const int wm   = (wid >> 2) * 64;
    const int wn   = (wid & 3) * 32;
    const int n0 = blockIdx.x * 128, m0 = blockIdx.y * 128;

    const __nv_bfloat16* Ah = (mode == 3) ? g_ah : g_xh;
    const __nv_bfloat16* Al = (mode == 3) ? g_al : g_xl;
    const __nv_bfloat16* Wh = g_wh[mode];
    const __nv_bfloat16* Wl = g_wl[mode];

    const uint32_t sbase = smem_u32(sm);

    const int lr = tid >> 1;
    const size_t gA = (size_t)(m0 + lr) * K_ + (tid & 1) * 16;
    const size_t gW = (size_t)(n0 + lr) * K_ + (tid & 1) * 16;
    const uint32_t srow = (uint32_t)(lr * LDS_B + (tid & 1) * 32);

    float acc[4][4][4];
#pragma unroll
    for (int a = 0; a < 4; a++)
#pragma unroll
        for (int b = 0; b < 4; b++)
#pragma unroll
            for (int c = 0; c < 4; c++) acc[a][b][c] = 0.0f;

#define LOAD_CHUNK(ch) do {                                                   \
    const uint32_t st = sbase + ((ch) & 1) * STAGE + srow;                    \
    const char* pa = (const char*)(Ah + gA + (ch) * 32);                      \
    const char* pl = (const char*)(Al + gA + (ch) * 32);                      \
    const char* pw = (const char*)(Wh + gW + (ch) * 32);                      \
    const char* pv = (const char*)(Wl + gW + (ch) * 32);                      \
    CPA16(st,               pa); CPA16(st + 16,           pa + 16);           \
    CPA16(st + ASZ,         pl); CPA16(st + ASZ + 16,     pl + 16);           \
    CPA16(st + 2 * ASZ,     pw); CPA16(st + 2 * ASZ + 16, pw + 16);           \
    CPA16(st + 3 * ASZ,     pv); CPA16(st + 3 * ASZ + 16, pv + 16);           \
    CP_COMMIT();                                                              \
} while (0)

    LOAD_CHUNK(0);

    for (int ch = 0; ch < 32; ch++) {
        CP_WAIT(0);              // chunk ch resident
        __syncthreads();         // all warps done consuming chunk ch-1
        if (ch < 31) LOAD_CHUNK(ch + 1);   // overwrite ch-1's buffer, overlap compute

        const uint32_t stg = sbase + (ch & 1) * STAGE;
#pragma unroll
        for (int ks = 0; ks < 2; ks++) {
            const int kb = ks * 32;
            uint32_t bH[4][2], bL[4][2];
#pragma unroll
            for (int nh = 0; nh < 2; nh++) {
                uint32_t bd = stg + 2 * ASZ
                    + (uint32_t)((wn + nh * 16 + ((lane >> 4) << 3) + (lane & 7)) * LDS_B
                                 + kb + (((lane >> 3) & 1) << 4));
                uint32_t r[4];
                LDSM4(r, bd);
                bH[nh * 2][0] = r[0]; bH[nh * 2][1] = r[1];
                bH[nh * 2 + 1][0] = r[2]; bH[nh * 2 + 1][1] = r[3];
                LDSM4(r, bd + ASZ);
                bL[nh * 2][0] = r[0]; bL[nh * 2][1] = r[1];
                bL[nh * 2 + 1][0] = r[2]; bL[nh * 2 + 1][1] = r[3];
            }
#pragma unroll
            for (int mi = 0; mi < 4; mi++) {
                uint32_t aH[4], aL[4];
                const uint32_t ad = stg + (uint32_t)((wm + mi * 16 + (lane & 15)) * LDS_B
                                                     + kb + ((lane >> 4) << 4));
                LDSM4(aH, ad);
                LDSM4(aL, ad + ASZ);
#pragma unroll
                for (int ni = 0; ni < 4; ni++) MMA16816(acc[mi][ni], aH, bH[ni]);
#pragma unroll
                for (int ni = 0; ni < 4; ni++) MMA16816(acc[mi][ni], aH, bL[ni]);
#pragma unroll
                for (int ni = 0; ni < 4; ni++) MMA16816(acc[mi][ni], aL, bH[ni]);
            }
        }
    }
    __syncthreads();   // protect smem before epilogue reuse

    // ---- epilogue: stage C tile in smem, then fused writeout
    constexpr int LDC = 132;
    float* Csm = (float*)sm;
#pragma unroll
    for (int mi = 0; mi < 4; mi++) {
        const int row = wm + mi * 16 + (lane >> 2);
#pragma unroll
        for (int ni = 0; ni < 4; ni++) {
            const int col = wn + ni * 8 + (lane & 3) * 2;
            *(float2*)&Csm[row * LDC + col] =
                make_float2(acc[mi][ni][0], acc[mi][ni][1]);
            *(float2*)&Csm[(row + 8) * LDC + col] =
                make_float2(acc[mi][ni][2], acc[mi][ni][3]);
        }
    }
    __syncthreads();

    if (mode <= 1) {
        __nv_bfloat16* Ch = (mode == 0) ? g_qh : g_kh;
        __nv_bfloat16* Cl = (mode == 0) ? g_ql : g_kl;
#pragma unroll 2
        for (int i = 0; i < 16; i++) {
            const int id  = tid + 256 * i;
            const int dp  = id & 15;
            const int hh  = (id >> 4) & 1;
            const int row = id >> 5;
            const int d0  = dp * 2;
            const int m   = m0 + row;
            const int s   = m & (S_ - 1);
            const int bb  = m >> 11;
            float oA[2], oB[2];
#pragma unroll
            for (int e = 0; e < 2; e++) {
                const int d = d0 + e, c = hh * 64 + d;
                const float v0 = Csm[row * LDC + c]      + bias[n0 + c];
                const float v1 = Csm[row * LDC + c + 32] + bias[n0 + c + 32];
                const float cs0 = cosb[s * HD_ + d],      sn0 = sinb[s * HD_ + d];
                const float cs1 = cosb[s * HD_ + d + 32], sn1 = sinb[s * HD_ + d + 32];
                oA[e] = v0 * cs0 - v1 * sn0;
                oB[e] = v1 * cs1 + v0 * sn1;
            }
            const int hidx = (n0 >> 6) + hh;
            const size_t base = ((size_t)(bb * NH_ + hidx) * S_ + s) * HD_;
            const __nv_bfloat16 a0 = __float2bfloat16(oA[0]);
            const __nv_bfloat16 a1 = __float2bfloat16(oA[1]);
            const __nv_bfloat16 c0 = __float2bfloat16(oB[0]);
            const __nv_bfloat16 c1 = __float2bfloat16(oB[1]);
            *(__nv_bfloat162*)&Ch[base + d0]      = __nv_bfloat162(a0, a1);
            *(__nv_bfloat162*)&Ch[base + d0 + 32] = __nv_bfloat162(c0, c1);
            *(__nv_bfloat162*)&Cl[base + d0] = __nv_bfloat162(
                __float2bfloat16(oA[0] - __bfloat162float(a0)),
                __float2bfloat16(oA[1] - __bfloat162float(a1)));
            *(__nv_bfloat162*)&Cl[base + d0 + 32] = __nv_bfloat162(
                __float2bfloat16(oB[0] - __bfloat162float(c0)),
                __float2bfloat16(oB[1] - __bfloat162float(c1)));
        }
    } else if (mode == 2) {
#pragma unroll 2
        for (int i = 0; i < 32; i++) {
            const int id  = tid + 256 * i;
            const int sp  = id & 63;
            const int c   = id >> 6;
            const int row0 = sp * 2;
            const int m   = m0 + row0;
            const int s   = m & (S_ - 1);
            const int bb  = m >> 11;
            const int n   = n0 + c;
            const int hidx = n >> 6, d = n & 63;
            const float v0 = Csm[row0 * LDC + c]       + bias[n];
            const float v1 = Csm[(row0 + 1) * LDC + c] + bias[n];
            const __nv_bfloat16 h0 = __float2bfloat16(v0);
            const __nv_bfloat16 h1 = __float2bfloat16(v1);
            const size_t o = ((size_t)(bb * NH_ + hidx) * HD_ + d) * S_ + s;
            *(__nv_bfloat162*)&g_vh[o] = __nv_bfloat162(h0, h1);
            *(__nv_bfloat162*)&g_vl[o] = __nv_bfloat162(
                __float2bfloat16(v0 - __bfloat162float(h0)),
                __float2bfloat16(v1 - __bfloat162float(h1)));
        }
    } else {
#pragma unroll 4
        for (int i = 0; i < 16; i++) {
            const int id  = tid + 256 * i;
            const int c4  = (id & 31) * 4;
            const int row = id >> 5;
            const int m   = m0 + row;
            const int n   = n0 + c4;
            float4 v;
            v.x = Csm[row * LDC + c4 + 0] + bias[n + 0];
            v.y = Csm[row * LDC + c4 + 1] + bias[n + 1];
            v.z = Csm[row * LDC + c4 + 2] + bias[n + 2];
            v.w = Csm[row * LDC + c4 + 3] + bias[n + 3];
            *(float4*)&Cext[(size_t)m * H_ + n] = v;
        }
    }
}

// ---------------------------------------------------------------------------
// Flash attention, HMMA bf16 3-way split. 128-row Q tile, 8 warps, KV tile 64,
// 3-stage cp.async pipeline. Per k-step: ALL 8 B-fragment LDSMs issued first,
// then term-major MMAs (acc reuse distance 8) — hides LDS latency.
// ---------------------------------------------------------------------------
constexpr int LDSA     = 144;
constexpr int QBYTES   = 2 * 128 * LDSA;        // 36864
constexpr int KVSTAGE  = 4 * 64 * LDSA;         // 36864
constexpr int ATT2_SMEM = QBYTES + 3 * KVSTAGE; // 147456

__global__ void __launch_bounds__(256) attn_hmma(const int* __restrict__ mask)
{
    extern __shared__ char sm[];
    const uint32_t sb = smem_u32(sm);
    __shared__ int msk[3][64];

    const int tid = threadIdx.x, lane = tid & 31, w = tid >> 5;
    const int bh = blockIdx.y, b = bh >> 4, h = bh & 15;
    const int q0 = blockIdx.x * 128;

    const __nv_bfloat16* Qhp = g_qh + (size_t)bh * S_ * HD_;
    const __nv_bfloat16* Qlp = g_ql + (size_t)bh * S_ * HD_;
    const __nv_bfloat16* Khp = g_kh + (size_t)bh * S_ * HD_;
    const __nv_bfloat16* Klp = g_kl + (size_t)bh * S_ * HD_;
    const __nv_bfloat16* Vhp = g_vh + (size_t)bh * HD_ * S_;
    const __nv_bfloat16* Vlp = g_vl + (size_t)bh * HD_ * S_;
    const int* maskp = mask + b * S_;

#pragma unroll
    for (int i = 0; i < 4; i++) {
        const int idx = tid + 256 * i;
        const int row = idx >> 3, chk = idx & 7;
        const uint32_t dst = sb + (uint32_t)(row * LDSA + chk * 16);
        CPA16(dst,         (const char*)(Qhp + (size_t)(q0 + row) * HD_ + chk * 8));
        CPA16(dst + 18432, (const char*)(Qlp + (size_t)(q0 + row) * HD_ + chk * 8));
    }

#define LOADKV(t) do {                                                          \
    const int kt_ = (t) * 64;                                                   \
    const uint32_t st = sb + QBYTES + ((t) % 3) * KVSTAGE;                      \
    _Pragma("unroll")                                                           \
    for (int i_ = 0; i_ < 2; i_++) {                                            \
        const int idx_ = tid + 256 * i_;                                        \
        const int row_ = idx_ >> 3, ch_ = idx_ & 7;                             \
        const uint32_t ro_ = (uint32_t)(row_ * LDSA + ch_ * 16);                \
        CPA16(st + ro_,          (const char*)(Khp + (size_t)(kt_ + row_) * HD_ + ch_ * 8)); \
        CPA16(st + 9216 + ro_,   (const char*)(Klp + (size_t)(kt_ + row_) * HD_ + ch_ * 8)); \
        CPA16(st + 18432 + ro_,  (const char*)(Vhp + (size_t)row_ * S_ + kt_ + ch_ * 8));    \
        CPA16(st + 27648 + ro_,  (const char*)(Vlp + (size_t)row_ * S_ + kt_ + ch_ * 8));    \
    }                                                                           \
    if (tid < 64) msk[(t) % 3][tid] = maskp[kt_ + tid];                         \
    CP_COMMIT();                                                                \
} while (0)

    LOADKV(0);
    LOADKV(1);

    float m_[2] = {-1e30f, -1e30f}, l_[2] = {0.0f, 0.0f};
    float oacc[8][4];
#pragma unroll
    for (int n = 0; n < 8; n++)
#pragma unroll
        for (int j = 0; j < 4; j++) oacc[n][j] = 0.0f;

    uint32_t qfh[4][4], qfl[4][4];
    const int c01 = (lane & 3) * 2;
    constexpr int NT = S_ / 64;

    for (int t = 0; t < NT; t++) {
        if (t >= NT - 2) { CP_WAIT(0); }
        else             { CP_WAIT(1); }
        __syncthreads();
        if (t + 2 < NT) LOADKV(t + 2);

        if (t == 0) {
#pragma unroll
            for (int kk = 0; kk < 4; kk++) {
                const uint32_t ad = sb + (uint32_t)((w * 16 + (lane & 15)) * LDSA
                                                    + kk * 32 + ((lane >> 4) << 4));
                LDSM4(qfh[kk], ad);
                LDSM4(qfl[kk], ad + 18432);
            }
        }

        const uint32_t kst = sb + QBYTES + (t % 3) * KVSTAGE;

        // ---- S = Q K^T: per kk, 8 LDSM up front, then term-major MMAs ----
        float sacc[8][4];
#pragma unroll
        for (int n = 0; n < 8; n++)
#pragma unroll
            for (int j = 0; j < 4; j++) sacc[n][j] = 0.0f;

#pragma unroll
        for (int kk = 0; kk < 4; kk++) {
            uint32_t rh[4][4], rl[4][4];
#pragma unroll
            for (int nh = 0; nh < 4; nh++) {
                const uint32_t bd = kst
                    + (uint32_t)((nh * 16 + ((lane >> 4) << 3) + (lane & 7)) * LDSA
                                 + kk * 32 + (((lane >> 3) & 1) << 4));
                LDSM4(rh[nh], bd);
                LDSM4(rl[nh], bd + 9216);
            }
#pragma unroll
            for (int nh = 0; nh < 4; nh++) {
                uint32_t b0[2] = {rh[nh][0], rh[nh][1]}, b1[2] = {rh[nh][2], rh[nh][3]};
                MMA16816(sacc[nh * 2],     qfh[kk], b0);
                MMA16816(sacc[nh * 2 + 1], qfh[kk], b1);
            }
#pragma unroll
            for (int nh = 0; nh < 4; nh++) {
                uint32_t d0[2] = {rl[nh][0], rl[nh][1]}, d1[2] = {rl[nh][2], rl[nh][3]};
                MMA16816(sacc[nh * 2],     qfh[kk], d0);
                MMA16816(sacc[nh * 2 + 1], qfh[kk], d1);
            }
#pragma unroll
            for (int nh = 0; nh < 4; nh++) {
                uint32_t b0[2] = {rh[nh][0], rh[nh][1]}, b1[2] = {rh[nh][2], rh[nh][3]};
                MMA16816(sacc[nh * 2],     qfl[kk], b0);
                MMA16816(sacc[nh * 2 + 1], qfl[kk], b1);
            }
        }

        // ---- scale + mask + online softmax ----
        float mx[2] = {-1e30f, -1e30f};
#pragma unroll
        for (int n = 0; n < 8; n++) {
            const int cc = n * 8 + c01;
            const int mk0 = msk[t % 3][cc], mk1 = msk[t % 3][cc + 1];
#pragma unroll
            for (int j = 0; j < 4; j++) {
                float v = sacc[n][j] * 0.125f;
                v = ((j & 1) ? mk1 : mk0) ? v : -1e30f;
                sacc[n][j] = v;
                mx[j >> 1] = fmaxf(mx[j >> 1], v);
            }
        }
        float corr[2], rs[2] = {0.0f, 0.0f};
#pragma unroll
        for (int r = 0; r < 2; r++) {
            mx[r] = fmaxf(mx[r], __shfl_xor_sync(0xffffffffu, mx[r], 1, 4));
            mx[r] = fmaxf(mx[r], __shfl_xor_sync(0xffffffffu, mx[r], 2, 4));
            const float mn = fmaxf(m_[r], mx[r]);
            corr[r] = __expf(m_[r] - mn);
            m_[r] = mn;
        }
#pragma unroll
        for (int n = 0; n < 8; n++)
#pragma unroll
            for (int j = 0; j < 4; j++) {
                const float p = __expf(sacc[n][j] - m_[j >> 1]);
                sacc[n][j] = p;
                rs[j >> 1] += p;
            }
#pragma unroll
        for (int r = 0; r < 2; r++) {
            rs[r] += __shfl_xor_sync(0xffffffffu, rs[r], 1, 4);
            rs[r] += __shfl_xor_sync(0xffffffffu, rs[r], 2, 4);
            l_[r] = l_[r] * corr[r] + rs[r];
        }
#pragma unroll
        for (int n = 0; n < 8; n++)
#pragma unroll
            for (int j = 0; j < 4; j++) oacc[n][j] *= corr[j >> 1];

        // ---- O += P V: per j, convert P, 8 LDSM up front, term-major MMAs ----
#pragma unroll
        for (int j = 0; j < 4; j++) {
            uint32_t aPh[4], aPl[4];
#pragma unroll
            for (int half = 0; half < 2; half++) {
                const float p0 = sacc[2 * j + half][0];
                const float p1 = sacc[2 * j + half][1];
                const float p2 = sacc[2 * j + half][2];
                const float p3 = sacc[2 * j + half][3];
                const float q0f = __bfloat162float(__float2bfloat16(p0));
                const float q1f = __bfloat162float(__float2bfloat16(p1));
                const float q2f = __bfloat162float(__float2bfloat16(p2));
                const float q3f = __bfloat162float(__float2bfloat16(p3));
                aPh[half * 2]     = bf2pack(p0, p1);
                aPh[half * 2 + 1] = bf2pack(p2, p3);
                aPl[half * 2]     = bf2pack(p0 - q0f, p1 - q1f);
                aPl[half * 2 + 1] = bf2pack(p2 - q2f, p3 - q3f);
            }
            uint32_t rh[4][4], rl[4][4];
#pragma unroll
            for (int nh = 0; nh < 4; nh++) {
                const uint32_t bd = kst + 18432
                    + (uint32_t)((nh * 16 + ((lane >> 4) << 3) + (lane & 7)) * LDSA
                                 + j * 32 + (((lane >> 3) & 1) << 4));
                LDSM4(rh[nh], bd);
                LDSM4(rl[nh], bd + 9216);
            }
#pragma unroll
            for (int nh = 0; nh < 4; nh++) {
                uint32_t b0[2] = {rh[nh][0], rh[nh][1]}, b1[2] = {rh[nh][2], rh[nh][3]};
                MMA16816(oacc[nh * 2],     aPh, b0);
                MMA16816(oacc[nh * 2 + 1], aPh, b1);
            }
#pragma unroll
            for (int nh = 0; nh < 4; nh++) {
                uint32_t d0[2] = {rl[nh][0], rl[nh][1]}, d1[2] = {rl[nh][2], rl[nh][3]};
                MMA16816(oacc[nh * 2],     aPh, d0);
                MMA16816(oacc[nh * 2 + 1], aPh, d1);
            }
#pragma unroll
            for (int nh = 0; nh < 4; nh++) {
                uint32_t b0[2] = {rh[nh][0], rh[nh][1]}, b1[2] = {rh[nh][2], rh[nh][3]};
                MMA16816(oacc[nh * 2],     aPl, b0);
                MMA16816(oacc[nh * 2 + 1], aPl, b1);
            }
        }
    }

    // ---- epilogue: /l, write hi/lo bf16 to g_ah/g_al [M,H] ----
    const int r0 = lane >> 2;
#pragma unroll
    for (int r = 0; r < 2; r++) {
        const float inv = 1.0f / l_[r];
        const int srow = q0 + w * 16 + r0 + 8 * r;
        const size_t base = ((size_t)b * S_ + srow) * H_ + h * 64 + c01;
#pragma unroll
        for (int n = 0; n < 8; n++) {
            const float v0 = oacc[n][2 * r]     * inv;
            const float v1 = oacc[n][2 * r + 1] * inv;
            const __nv_bfloat16 h0 = __float2bfloat16(v0);
            const __nv_bfloat16 h1 = __float2bfloat16(v1);
            *(__nv_bfloat162*)&g_ah[base + n * 8] = __nv_bfloat162(h0, h1);
            *(__nv_bfloat162*)&g_al[base + n * 8] = __nv_bfloat162(
                __float2bfloat16(v0 - __bfloat162float(h0)),
                __float2bfloat16(v1 - __bfloat162float(h1)));
        }
    }
}

// ---------------------------------------------------------------------------
extern "C" void kernel_launch(void* const* d_in, const int* in_sizes, int n_in,
                              void* d_out, int out_size)
{
    const float* x    = (const float*)d_in[0];
    const int*   mask = (const int*)  d_in[1];
    const float* cosb = (const float*)d_in[2];
    const float* sinb = (const float*)d_in[3];
    const float* Wq   = (const float*)d_in[4];
    const float* bq   = (const float*)d_in[5];
    const float* Wk   = (const float*)d_in[6];
    const float* bk   = (const float*)d_in[7];
    const float* Wv   = (const float*)d_in[8];
    const float* bv   = (const float*)d_in[9];
    const float* Wo   = (const float*)d_in[10];
    const float* bo   = (const float*)d_in[11];
    float* out = (float*)d_out;

    cudaFuncSetAttribute(hgemm,
                         cudaFuncAttributeMaxDynamicSharedMemorySize, GEMM_SMEM);
    cudaFuncSetAttribute(attn_hmma,
                         cudaFuncAttributeMaxDynamicSharedMemorySize, ATT2_SMEM);

    cvt_all<<<(M_ * K_ + 4 * H_ * K_) / 1024, 256>>>(x, Wq, Wk, Wv, Wo);

    dim3 gqkv(H_ / 128, M_ / 128, 3);
    hgemm<<<gqkv, 256, GEMM_SMEM>>>(bq, bk, bv, nullptr, cosb, sinb, -1);

    dim3 ag(S_ / 128, B_ * NH_);
    attn_hmma<<<ag, 256, ATT2_SMEM>>>(mask);

    dim3 gg(H_ / 128, M_ / 128);
    hgemm<<<gg, 256, GEMM_SMEM>>>(bo, bo, bo, out, cosb, sinb, 3);
}

// round 11
// speedup vs baseline: 1.1633x; 1.0015x over previous
#include <cuda_runtime.h>
#include <cuda_bf16.h>
#include <math.h>
#include <stdint.h>

// Problem constants
constexpr int B_  = 2;
constexpr int S_  = 2048;
constexpr int H_  = 1024;
constexpr int NH_ = 16;
constexpr int HD_ = 64;
constexpr int M_  = B_ * S_;   // 4096
constexpr int K_  = H_;        // 1024

// ---------------- scratch (device globals; no allocation allowed) ----------
__device__ __align__(16) __nv_bfloat16 g_qh[(size_t)B_ * NH_ * S_ * HD_];
__device__ __align__(16) __nv_bfloat16 g_ql[(size_t)B_ * NH_ * S_ * HD_];
__device__ __align__(16) __nv_bfloat16 g_kh[(size_t)B_ * NH_ * S_ * HD_];
__device__ __align__(16) __nv_bfloat16 g_kl[(size_t)B_ * NH_ * S_ * HD_];
__device__ __align__(16) __nv_bfloat16 g_vh[(size_t)B_ * NH_ * HD_ * S_];
__device__ __align__(16) __nv_bfloat16 g_vl[(size_t)B_ * NH_ * HD_ * S_];

__device__ __align__(16) __nv_bfloat16 g_xh[(size_t)M_ * K_];
__device__ __align__(16) __nv_bfloat16 g_xl[(size_t)M_ * K_];
__device__ __align__(16) __nv_bfloat16 g_wh[4][(size_t)H_ * K_];   // q,k,v,o
__device__ __align__(16) __nv_bfloat16 g_wl[4][(size_t)H_ * K_];
__device__ __align__(16) __nv_bfloat16 g_ah[(size_t)M_ * H_];
__device__ __align__(16) __nv_bfloat16 g_al[(size_t)M_ * H_];

// ---------------- PTX helpers ----------------------------------------------
__device__ __forceinline__ uint32_t smem_u32(const void* p) {
    uint32_t a;
    asm("{ .reg .u64 t; cvta.to.shared.u64 t, %1; cvt.u32.u64 %0, t; }"
        : "=r"(a) : "l"(p));
    return a;
}

#define CPA16(dst, src) \
    asm volatile("cp.async.ca.shared.global [%0], [%1], 16;" \
                 :: "r"(dst), "l"(src) : "memory")
#define CP_COMMIT() asm volatile("cp.async.commit_group;" ::: "memory")
#define CP_WAIT(n)  asm volatile("cp.async.wait_group %0;" :: "n"(n) : "memory")

#define LDSM4(r, addr) \
    asm volatile("ldmatrix.sync.aligned.m8n8.x4.shared.b16 {%0,%1,%2,%3}, [%4];" \
                 : "=r"((r)[0]), "=r"((r)[1]), "=r"((r)[2]), "=r"((r)[3])        \
                 : "r"(addr))

#define MMA16816(c, a, b) \
    asm volatile("mma.sync.aligned.m16n8k16.row.col.f32.bf16.bf16.f32 "          \
                 "{%0,%1,%2,%3}, {%4,%5,%6,%7}, {%8,%9}, {%0,%1,%2,%3};"         \
                 : "+f"((c)[0]), "+f"((c)[1]), "+f"((c)[2]), "+f"((c)[3])        \
                 : "r"((a)[0]), "r"((a)[1]), "r"((a)[2]), "r"((a)[3]),           \
                   "r"((b)[0]), "r"((b)[1]))

__device__ __forceinline__ uint32_t bf2pack(float a, float b) {
    __nv_bfloat162 t = __floats2bfloat162_rn(a, b);
    return *(uint32_t*)&t;
}

// ---------------------------------------------------------------------------
// fp32 -> bf16 hi/lo split, all 5 inputs in one launch.
// ---------------------------------------------------------------------------
__global__ void __launch_bounds__(256) cvt_all(const float* __restrict__ x,
                                               const float* __restrict__ wq,
                                               const float* __restrict__ wk,
                                               const float* __restrict__ wv,
                                               const float* __restrict__ wo)
{
    int i = (blockIdx.x * blockDim.x + threadIdx.x) * 4;
    const float* s;
    __nv_bfloat16 *dh, *dl;
    int off;
    if (i < M_ * K_) {
        s = x; dh = g_xh; dl = g_xl; off = i;
    } else {
        const int j = i - M_ * K_;
        const int r = j >> 20;               // / (H_*K_)
        off = j & (H_ * K_ - 1);
        s = (r == 0) ? wq : (r == 1) ? wk : (r == 2) ? wv : wo;
        dh = g_wh[r]; dl = g_wl[r];
    }

    float4 v = *(const float4*)(s + off);
    float vv[4] = {v.x, v.y, v.z, v.w};
    __nv_bfloat16 h[4], l[4];
#pragma unroll
    for (int j = 0; j < 4; j++) {
        h[j] = __float2bfloat16(vv[j]);
        l[j] = __float2bfloat16(vv[j] - __bfloat162float(h[j]));
    }
    *(__nv_bfloat162*)&dh[off]     = __nv_bfloat162(h[0], h[1]);
    *(__nv_bfloat162*)&dh[off + 2] = __nv_bfloat162(h[2], h[3]);
    *(__nv_bfloat162*)&dl[off]     = __nv_bfloat162(l[0], l[1]);
    *(__nv_bfloat162*)&dl[off + 2] = __nv_bfloat162(l[2], l[3]);
}

// ---------------------------------------------------------------------------
// HMMA GEMM, bf16 3-way split. CTA 128x128, BK=32, 256 thr (8 warps),
// warp tile 64x32, cp.async double buffer, single barrier per chunk.
// (unchanged from round-10 winner)
// ---------------------------------------------------------------------------
constexpr int LDS_B  = 80;
constexpr int ASZ    = 128 * LDS_B;    // 10240
constexpr int STAGE  = 4 * ASZ;
constexpr int GEMM_SMEM = 2 * STAGE;   // 81920

__global__ void __launch_bounds__(256, 2) hgemm(const float* __restrict__ bias0,
                                                const float* __restrict__ bias1,
                                                const float* __restrict__ bias2,
                                                float* __restrict__ Cext,
                                                const float* __restrict__ cosb,
                                                const float* __restrict__ sinb,
                                                int fixed_mode)
{
    extern __shared__ char sm[];
    const int mode = (fixed_mode >= 0) ? fixed_mode : (int)blockIdx.z;
    const float* bias = (mode == 1) ? bias1 : (mode == 2) ? bias2 : bias0;

    const int tid  = threadIdx.x;
    const int lane = tid & 31;
    const int wid  = tid >> 5;
    const int wm   = (wid >> 2) * 64;
    const int wn   = (wid & 3) * 32;
    const int n0 = blockIdx.x * 128, m0 = blockIdx.y * 128;

    const __nv_bfloat16* Ah = (mode == 3) ? g_ah : g_xh;
    const __nv_bfloat16* Al = (mode == 3) ? g_al : g_xl;
    const __nv_bfloat16* Wh = g_wh[mode];
    const __nv_bfloat16* Wl = g_wl[mode];

    const uint32_t sbase = smem_u32(sm);

    const int lr = tid >> 1;
    const size_t gA = (size_t)(m0 + lr) * K_ + (tid & 1) * 16;
    const size_t gW = (size_t)(n0 + lr) * K_ + (tid & 1) * 16;
    const uint32_t srow = (uint32_t)(lr * LDS_B + (tid & 1) * 32);

    float acc[4][4][4];
#pragma unroll
    for (int a = 0; a < 4; a++)
#pragma unroll
        for (int b = 0; b < 4; b++)
#pragma unroll
            for (int c = 0; c < 4; c++) acc[a][b][c] = 0.0f;

#define LOAD_CHUNK(ch) do {                                                   \
    const uint32_t st = sbase + ((ch) & 1) * STAGE + srow;                    \
    const char* pa = (const char*)(Ah + gA + (ch) * 32);                      \
    const char* pl = (const char*)(Al + gA + (ch) * 32);                      \
    const char* pw = (const char*)(Wh + gW + (ch) * 32);                      \
    const char* pv = (const char*)(Wl + gW + (ch) * 32);                      \
    CPA16(st,               pa); CPA16(st + 16,           pa + 16);           \
    CPA16(st + ASZ,         pl); CPA16(st + ASZ + 16,     pl + 16);           \
    CPA16(st + 2 * ASZ,     pw); CPA16(st + 2 * ASZ + 16, pw + 16);           \
    CPA16(st + 3 * ASZ,     pv); CPA16(st + 3 * ASZ + 16, pv + 16);           \
    CP_COMMIT();                                                              \
} while (0)

    LOAD_CHUNK(0);

    for (int ch = 0; ch < 32; ch++) {
        CP_WAIT(0);
        __syncthreads();
        if (ch < 31) LOAD_CHUNK(ch + 1);

        const uint32_t stg = sbase + (ch & 1) * STAGE;
#pragma unroll
        for (int ks = 0; ks < 2; ks++) {
            const int kb = ks * 32;
            uint32_t bH[4][2], bL[4][2];
#pragma unroll
            for (int nh = 0; nh < 2; nh++) {
                uint32_t bd = stg + 2 * ASZ
                    + (uint32_t)((wn + nh * 16 + ((lane >> 4) << 3) + (lane & 7)) * LDS_B
                                 + kb + (((lane >> 3) & 1) << 4));
                uint32_t r[4];
                LDSM4(r, bd);
                bH[nh * 2][0] = r[0]; bH[nh * 2][1] = r[1];
                bH[nh * 2 + 1][0] = r[2]; bH[nh * 2 + 1][1] = r[3];
                LDSM4(r, bd + ASZ);
                bL[nh * 2][0] = r[0]; bL[nh * 2][1] = r[1];
                bL[nh * 2 + 1][0] = r[2]; bL[nh * 2 + 1][1] = r[3];
            }
#pragma unroll
            for (int mi = 0; mi < 4; mi++) {
                uint32_t aH[4], aL[4];
                const uint32_t ad = stg + (uint32_t)((wm + mi * 16 + (lane & 15)) * LDS_B
                                                     + kb + ((lane >> 4) << 4));
                LDSM4(aH, ad);
                LDSM4(aL, ad + ASZ);
#pragma unroll
                for (int ni = 0; ni < 4; ni++) MMA16816(acc[mi][ni], aH, bH[ni]);
#pragma unroll
                for (int ni = 0; ni < 4; ni++) MMA16816(acc[mi][ni], aH, bL[ni]);
#pragma unroll
                for (int ni = 0; ni < 4; ni++) MMA16816(acc[mi][ni], aL, bH[ni]);
            }
        }
    }
    __syncthreads();

    // ---- epilogue: stage C tile in smem, then fused writeout
    constexpr int LDC = 132;
    float* Csm = (float*)sm;
#pragma unroll
    for (int mi = 0; mi < 4; mi++) {
        const int row = wm + mi * 16 + (lane >> 2);
#pragma unroll
        for (int ni = 0; ni < 4; ni++) {
            const int col = wn + ni * 8 + (lane & 3) * 2;
            *(float2*)&Csm[row * LDC + col] =
                make_float2(acc[mi][ni][0], acc[mi][ni][1]);
            *(float2*)&Csm[(row + 8) * LDC + col] =
                make_float2(acc[mi][ni][2], acc[mi][ni][3]);
        }
    }
    __syncthreads();

    if (mode <= 1) {
        __nv_bfloat16* Ch = (mode == 0) ? g_qh : g_kh;
        __nv_bfloat16* Cl = (mode == 0) ? g_ql : g_kl;
#pragma unroll 2
        for (int i = 0; i < 16; i++) {
            const int id  = tid + 256 * i;
            const int dp  = id & 15;
            const int hh  = (id >> 4) & 1;
            const int row = id >> 5;
            const int d0  = dp * 2;
            const int m   = m0 + row;
            const int s   = m & (S_ - 1);
            const int bb  = m >> 11;
            float oA[2], oB[2];
#pragma unroll
            for (int e = 0; e < 2; e++) {
                const int d = d0 + e, c = hh * 64 + d;
                const float v0 = Csm[row * LDC + c]      + bias[n0 + c];
                const float v1 = Csm[row * LDC + c + 32] + bias[n0 + c + 32];
                const float cs0 = cosb[s * HD_ + d],      sn0 = sinb[s * HD_ + d];
                const float cs1 = cosb[s * HD_ + d + 32], sn1 = sinb[s * HD_ + d + 32];
                oA[e] = v0 * cs0 - v1 * sn0;
                oB[e] = v1 * cs1 + v0 * sn1;
            }
            const int hidx = (n0 >> 6) + hh;
            const size_t base = ((size_t)(bb * NH_ + hidx) * S_ + s) * HD_;
            const __nv_bfloat16 a0 = __float2bfloat16(oA[0]);
            const __nv_bfloat16 a1 = __float2bfloat16(oA[1]);
            const __nv_bfloat16 c0 = __float2bfloat16(oB[0]);
            const __nv_bfloat16 c1 = __float2bfloat16(oB[1]);
            *(__nv_bfloat162*)&Ch[base + d0]      = __nv_bfloat162(a0, a1);
            *(__nv_bfloat162*)&Ch[base + d0 + 32] = __nv_bfloat162(c0, c1);
            *(__nv_bfloat162*)&Cl[base + d0] = __nv_bfloat162(
                __float2bfloat16(oA[0] - __bfloat162float(a0)),
                __float2bfloat16(oA[1] - __bfloat162float(a1)));
            *(__nv_bfloat162*)&Cl[base + d0 + 32] = __nv_bfloat162(
                __float2bfloat16(oB[0] - __bfloat162float(c0)),
                __float2bfloat16(oB[1] - __bfloat162float(c1)));
        }
    } else if (mode == 2) {
#pragma unroll 2
        for (int i = 0; i < 32; i++) {
            const int id  = tid + 256 * i;
            const int sp  = id & 63;
            const int c   = id >> 6;
            const int row0 = sp * 2;
            const int m   = m0 + row0;
            const int s   = m & (S_ - 1);
            const int bb  = m >> 11;
            const int n   = n0 + c;
            const int hidx = n >> 6, d = n & 63;
            const float v0 = Csm[row0 * LDC + c]       + bias[n];
            const float v1 = Csm[(row0 + 1) * LDC + c] + bias[n];
            const __nv_bfloat16 h0 = __float2bfloat16(v0);
            const __nv_bfloat16 h1 = __float2bfloat16(v1);
            const size_t o = ((size_t)(bb * NH_ + hidx) * HD_ + d) * S_ + s;
            *(__nv_bfloat162*)&g_vh[o] = __nv_bfloat162(h0, h1);
            *(__nv_bfloat162*)&g_vl[o] = __nv_bfloat162(
                __float2bfloat16(v0 - __bfloat162float(h0)),
                __float2bfloat16(v1 - __bfloat162float(h1)));
        }
    } else {
#pragma unroll 4
        for (int i = 0; i < 16; i++) {
            const int id  = tid + 256 * i;
            const int c4  = (id & 31) * 4;
            const int row = id >> 5;
            const int m   = m0 + row;
            const int n   = n0 + c4;
            float4 v;
            v.x = Csm[row * LDC + c4 + 0] + bias[n + 0];
            v.y = Csm[row * LDC + c4 + 1] + bias[n + 1];
            v.z = Csm[row * LDC + c4 + 2] + bias[n + 2];
            v.w = Csm[row * LDC + c4 + 3] + bias[n + 3];
            *(float4*)&Cext[(size_t)m * H_ + n] = v;
        }
    }
}

// ---------------------------------------------------------------------------
// Flash attention, HMMA bf16 3-way split — SOFTWARE PIPELINED.
// Per step: QK(t+1) -> other S-buffer, then softmax(t) + PV(t). The QK MMA
// stream is independent of softmax(t), so ptxas hides MUFU/shfl under HMMA.
// 4-stage KV ring (tile t+1 resident when QK(t+1) issues), loop unrolled x2.
// ---------------------------------------------------------------------------
constexpr int LDSA     = 144;
constexpr int QBYTES   = 2 * 128 * LDSA;        // 36864
constexpr int KVSTAGE  = 4 * 64 * LDSA;         // 36864
constexpr int ATT3_SMEM = QBYTES + 4 * KVSTAGE; // 184320

__global__ void __launch_bounds__(256) attn_hmma(const int* __restrict__ mask)
{
    extern __shared__ char sm[];
    const uint32_t sb = smem_u32(sm);
    __shared__ int msk[4][64];

    const int tid = threadIdx.x, lane = tid & 31, w = tid >> 5;
    const int bh = blockIdx.y, b = bh >> 4, h = bh & 15;
    const int q0 = blockIdx.x * 128;

    const __nv_bfloat16* Qhp = g_qh + (size_t)bh * S_ * HD_;
    const __nv_bfloat16* Qlp = g_ql + (size_t)bh * S_ * HD_;
    const __nv_bfloat16* Khp = g_kh + (size_t)bh * S_ * HD_;
    const __nv_bfloat16* Klp = g_kl + (size_t)bh * S_ * HD_;
    const __nv_bfloat16* Vhp = g_vh + (size_t)bh * HD_ * S_;
    const __nv_bfloat16* Vlp = g_vl + (size_t)bh * HD_ * S_;
    const int* maskp = mask + b * S_;

    // Q tile loads (join commit group of LOADKV(0))
#pragma unroll
    for (int i = 0; i < 4; i++) {
        const int idx = tid + 256 * i;
        const int row = idx >> 3, chk = idx & 7;
        const uint32_t dst = sb + (uint32_t)(row * LDSA + chk * 16);
        CPA16(dst,         (const char*)(Qhp + (size_t)(q0 + row) * HD_ + chk * 8));
        CPA16(dst + 18432, (const char*)(Qlp + (size_t)(q0 + row) * HD_ + chk * 8));
    }

#define LOADKV(t) do {                                                          \
    const int kt_ = (t) * 64;                                                   \
    const uint32_t st = sb + QBYTES + ((t) & 3) * KVSTAGE;                      \
    _Pragma("unroll")                                                           \
    for (int i_ = 0; i_ < 2; i_++) {                                            \
        const int idx_ = tid + 256 * i_;                                        \
        const int row_ = idx_ >> 3, ch_ = idx_ & 7;                             \
        const uint32_t ro_ = (uint32_t)(row_ * LDSA + ch_ * 16);                \
        CPA16(st + ro_,          (const char*)(Khp + (size_t)(kt_ + row_) * HD_ + ch_ * 8)); \
        CPA16(st + 9216 + ro_,   (const char*)(Klp + (size_t)(kt_ + row_) * HD_ + ch_ * 8)); \
        CPA16(st + 18432 + ro_,  (const char*)(Vhp + (size_t)row_ * S_ + kt_ + ch_ * 8));    \
        CPA16(st + 27648 + ro_,  (const char*)(Vlp + (size_t)row_ * S_ + kt_ + ch_ * 8));    \
    }                                                                           \
    if (tid < 64) msk[(t) & 3][tid] = maskp[kt_ + tid];                         \
    CP_COMMIT();                                                                \
} while (0)

    LOADKV(0);    // includes Q loads in group 0
    LOADKV(1);
    LOADKV(2);

    float m_[2] = {-1e30f, -1e30f}, l_[2] = {0.0f, 0.0f};
    float oacc[8][4];
#pragma unroll
    for (int n = 0; n < 8; n++)
#pragma unroll
        for (int j = 0; j < 4; j++) oacc[n][j] = 0.0f;

    uint32_t qfh[4][4], qfl[4][4];
    const int c01 = (lane & 3) * 2;
    constexpr int NT = S_ / 64;            // 32 (even)

    float sA[8][4], sB[8][4];

    // ---- pipelined stage helpers ----
    auto QK = [&](float (&sacc)[8][4], int ti) {
        const uint32_t kst = sb + QBYTES + (ti & 3) * KVSTAGE;
#pragma unroll
        for (int n = 0; n < 8; n++)
#pragma unroll
            for (int j = 0; j < 4; j++) sacc[n][j] = 0.0f;
#pragma unroll
        for (int kk = 0; kk < 4; kk++) {
            uint32_t rh[4][4], rl[4][4];
#pragma unroll
            for (int nh = 0; nh < 4; nh++) {
                const uint32_t bd = kst
                    + (uint32_t)((nh * 16 + ((lane >> 4) << 3) + (lane & 7)) * LDSA
                                 + kk * 32 + (((lane >> 3) & 1) << 4));
                LDSM4(rh[nh], bd);
                LDSM4(rl[nh], bd + 9216);
            }
#pragma unroll
            for (int nh = 0; nh < 4; nh++) {
                uint32_t b0[2] = {rh[nh][0], rh[nh][1]}, b1[2] = {rh[nh][2], rh[nh][3]};
                MMA16816(sacc[nh * 2],     qfh[kk], b0);
                MMA16816(sacc[nh * 2 + 1], qfh[kk], b1);
            }
#pragma unroll
            for (int nh = 0; nh < 4; nh++) {
                uint32_t d0[2] = {rl[nh][0], rl[nh][1]}, d1[2] = {rl[nh][2], rl[nh][3]};
                MMA16816(sacc[nh * 2],     qfh[kk], d0);
                MMA16816(sacc[nh * 2 + 1], qfh[kk], d1);
            }
#pragma unroll
            for (int nh = 0; nh < 4; nh++) {
                uint32_t b0[2] = {rh[nh][0], rh[nh][1]}, b1[2] = {rh[nh][2], rh[nh][3]};
                MMA16816(sacc[nh * 2],     qfl[kk], b0);
                MMA16816(sacc[nh * 2 + 1], qfl[kk], b1);
            }
        }
    };

    auto SMAX = [&](float (&sacc)[8][4], int ti) {
        float mx[2] = {-1e30f, -1e30f};
#pragma unroll
        for (int n = 0; n < 8; n++) {
            const int cc = n * 8 + c01;
            const int mk0 = msk[ti & 3][cc], mk1 = msk[ti & 3][cc + 1];
#pragma unroll
            for (int j = 0; j < 4; j++) {
                float v = sacc[n][j] * 0.125f;
                v = ((j & 1) ? mk1 : mk0) ? v : -1e30f;
                sacc[n][j] = v;
                mx[j >> 1] = fmaxf(mx[j >> 1], v);
            }
        }
        float corr[2], rs[2] = {0.0f, 0.0f};
#pragma unroll
        for (int r = 0; r < 2; r++) {
            mx[r] = fmaxf(mx[r], __shfl_xor_sync(0xffffffffu, mx[r], 1, 4));
            mx[r] = fmaxf(mx[r], __shfl_xor_sync(0xffffffffu, mx[r], 2, 4));
            const float mn = fmaxf(m_[r], mx[r]);
            corr[r] = __expf(m_[r] - mn);
            m_[r] = mn;
        }
#pragma unroll
        for (int n = 0; n < 8; n++)
#pragma unroll
            for (int j = 0; j < 4; j++) {
                const float p = __expf(sacc[n][j] - m_[j >> 1]);
                sacc[n][j] = p;
                rs[j >> 1] += p;
            }
#pragma unroll
        for (int r = 0; r < 2; r++) {
            rs[r] += __shfl_xor_sync(0xffffffffu, rs[r], 1, 4);
            rs[r] += __shfl_xor_sync(0xffffffffu, rs[r], 2, 4);
            l_[r] = l_[r] * corr[r] + rs[r];
        }
#pragma unroll
        for (int n = 0; n < 8; n++)
#pragma unroll
            for (int j = 0; j < 4; j++) oacc[n][j] *= corr[j >> 1];
    };

    auto PV = [&](float (&sacc)[8][4], int ti) {
        const uint32_t kst = sb + QBYTES + (ti & 3) * KVSTAGE;
#pragma unroll
        for (int j = 0; j < 4; j++) {
            uint32_t aPh[4], aPl[4];
#pragma unroll
            for (int half = 0; half < 2; half++) {
                const float p0 = sacc[2 * j + half][0];
                const float p1 = sacc[2 * j + half][1];
                const float p2 = sacc[2 * j + half][2];
                const float p3 = sacc[2 * j + half][3];
                const float q0f = __bfloat162float(__float2bfloat16(p0));
                const float q1f = __bfloat162float(__float2bfloat16(p1));
                const float q2f = __bfloat162float(__float2bfloat16(p2));
                const float q3f = __bfloat162float(__float2bfloat16(p3));
                aPh[half * 2]     = bf2pack(p0, p1);
                aPh[half * 2 + 1] = bf2pack(p2, p3);
                aPl[half * 2]     = bf2pack(p0 - q0f, p1 - q1f);
                aPl[half * 2 + 1] = bf2pack(p2 - q2f, p3 - q3f);
            }
            uint32_t rh[4][4], rl[4][4];
#pragma unroll
            for (int nh = 0; nh < 4; nh++) {
                const uint32_t bd = kst + 18432
                    + (uint32_t)((nh * 16 + ((lane >> 4) << 3) + (lane & 7)) * LDSA
                                 + j * 32 + (((lane >> 3) & 1) << 4));
                LDSM4(rh[nh], bd);
                LDSM4(rl[nh], bd + 9216);
            }
#pragma unroll
            for (int nh = 0; nh < 4; nh++) {
                uint32_t b0[2] = {rh[nh][0], rh[nh][1]}, b1[2] = {rh[nh][2], rh[nh][3]};
                MMA16816(oacc[nh * 2],     aPh, b0);
                MMA16816(oacc[nh * 2 + 1], aPh, b1);
            }
#pragma unroll
            for (int nh = 0; nh < 4; nh++) {
                uint32_t d0[2] = {rl[nh][0], rl[nh][1]}, d1[2] = {rl[nh][2], rl[nh][3]};
                MMA16816(oacc[nh * 2],     aPh, d0);
                MMA16816(oacc[nh * 2 + 1], aPh, d1);
            }
#pragma unroll
            for (int nh = 0; nh < 4; nh++) {
                uint32_t b0[2] = {rh[nh][0], rh[nh][1]}, b1[2] = {rh[nh][2], rh[nh][3]};
                MMA16816(oacc[nh * 2],     aPl, b0);
                MMA16816(oacc[nh * 2 + 1], aPl, b1);
            }
        }
    };

    // ---- prologue: tile 0 resident, Q fragments, QK(0) ----
    CP_WAIT(2);            // group 0 (Q + KV0) done; groups 1,2 may pend
    __syncthreads();
#pragma unroll
    for (int kk = 0; kk < 4; kk++) {
        const uint32_t ad = sb + (uint32_t)((w * 16 + (lane & 15)) * LDSA
                                            + kk * 32 + ((lane >> 4) << 4));
        LDSM4(qfh[kk], ad);
        LDSM4(qfl[kk], ad + 18432);
    }
    QK(sA, 0);

    // ---- main loop, unrolled x2 (NT even) ----
    for (int t = 0; t < NT; t += 2) {
        // even half: process tile t (sA), prefetch-QK tile t+1 (sB)
        if (t + 3 < NT) { CP_WAIT(1); } else { CP_WAIT(0); }
        __syncthreads();                 // all warps done with buffer (t+3)&3 (tile t-1)
        if (t + 3 < NT) LOADKV(t + 3);
        QK(sB, t + 1);                   // independent of softmax(t) below
        SMAX(sA, t);
        PV(sA, t);

        // odd half: process tile t+1 (sB), prefetch-QK tile t+2 (sA)
        if (t + 4 < NT) { CP_WAIT(1); } else { CP_WAIT(0); }
        __syncthreads();                 // all warps done with buffer (t+4)&3 (tile t)
        if (t + 4 < NT) LOADKV(t + 4);
        if (t + 2 < NT) QK(sA, t + 2);
        SMAX(sB, t + 1);
        PV(sB, t + 1);
    }

    // ---- epilogue: /l, write hi/lo bf16 to g_ah/g_al [M,H] ----
    const int r0 = lane >> 2;
#pragma unroll
    for (int r = 0; r < 2; r++) {
        const float inv = 1.0f / l_[r];
        const int srow = q0 + w * 16 + r0 + 8 * r;
        const size_t base = ((size_t)b * S_ + srow) * H_ + h * 64 + c01;
#pragma unroll
        for (int n = 0; n < 8; n++) {
            const float v0 = oacc[n][2 * r]     * inv;
            const float v1 = oacc[n][2 * r + 1] * inv;
            const __nv_bfloat16 h0 = __float2bfloat16(v0);
            const __nv_bfloat16 h1 = __float2bfloat16(v1);
            *(__nv_bfloat162*)&g_ah[base + n * 8] = __nv_bfloat162(h0, h1);
            *(__nv_bfloat162*)&g_al[base + n * 8] = __nv_bfloat162(
                __float2bfloat16(v0 - __bfloat162float(h0)),
                __float2bfloat16(v1 - __bfloat162float(h1)));
        }
    }
}

// ---------------------------------------------------------------------------
extern "C" void kernel_launch(void* const* d_in, const int* in_sizes, int n_in,
                              void* d_out, int out_size)
{
    const float* x    = (const float*)d_in[0];
    const int*   mask = (const int*)  d_in[1];
    const float* cosb = (const float*)d_in[2];
    const float* sinb = (const float*)d_in[3];
    const float* Wq   = (const float*)d_in[4];
    const float* bq   = (const float*)d_in[5];
    const float* Wk   = (const float*)d_in[6];
    const float* bk   = (const float*)d_in[7];
    const float* Wv   = (const float*)d_in[8];
    const float* bv   = (const float*)d_in[9];
    const float* Wo   = (const float*)d_in[10];
    const float* bo   = (const float*)d_in[11];
    float* out = (float*)d_out;

    cudaFuncSetAttribute(hgemm,
                         cudaFuncAttributeMaxDynamicSharedMemorySize, GEMM_SMEM);
    cudaFuncSetAttribute(attn_hmma,
                         cudaFuncAttributeMaxDynamicSharedMemorySize, ATT3_SMEM);

    cvt_all<<<(M_ * K_ + 4 * H_ * K_) / 1024, 256>>>(x, Wq, Wk, Wv, Wo);

    dim3 gqkv(H_ / 128, M_ / 128, 3);
    hgemm<<<gqkv, 256, GEMM_SMEM>>>(bq, bk, bv, nullptr, cosb, sinb, -1);

    dim3 ag(S_ / 128, B_ * NH_);
    attn_hmma<<<ag, 256, ATT3_SMEM>>>(mask);

    dim3 gg(H_ / 128, M_ / 128);
    hgemm<<<gg, 256, GEMM_SMEM>>>(bo, bo, bo, out, cosb, sinb, 3);
}

// round 12
// speedup vs baseline: 1.1659x; 1.0022x over previous
#include <cuda_runtime.h>
#include <cuda_bf16.h>
#include <math.h>
#include <stdint.h>

// Problem constants
constexpr int B_  = 2;
constexpr int S_  = 2048;
constexpr int H_  = 1024;
constexpr int NH_ = 16;
constexpr int HD_ = 64;
constexpr int M_  = B_ * S_;   // 4096
constexpr int K_  = H_;        // 1024

// ---------------- scratch (device globals; no allocation allowed) ----------
__device__ __align__(16) __nv_bfloat16 g_qh[(size_t)B_ * NH_ * S_ * HD_];
__device__ __align__(16) __nv_bfloat16 g_ql[(size_t)B_ * NH_ * S_ * HD_];
__device__ __align__(16) __nv_bfloat16 g_kh[(size_t)B_ * NH_ * S_ * HD_];
__device__ __align__(16) __nv_bfloat16 g_kl[(size_t)B_ * NH_ * S_ * HD_];
__device__ __align__(16) __nv_bfloat16 g_vh[(size_t)B_ * NH_ * HD_ * S_];
__device__ __align__(16) __nv_bfloat16 g_vl[(size_t)B_ * NH_ * HD_ * S_];

__device__ __align__(16) __nv_bfloat16 g_xh[(size_t)M_ * K_];
__device__ __align__(16) __nv_bfloat16 g_xl[(size_t)M_ * K_];
__device__ __align__(16) __nv_bfloat16 g_wh[4][(size_t)H_ * K_];   // q,k,v,o
__device__ __align__(16) __nv_bfloat16 g_wl[4][(size_t)H_ * K_];
__device__ __align__(16) __nv_bfloat16 g_ah[(size_t)M_ * H_];
__device__ __align__(16) __nv_bfloat16 g_al[(size_t)M_ * H_];

// ---------------- PTX helpers ----------------------------------------------
__device__ __forceinline__ uint32_t smem_u32(const void* p) {
    uint32_t a;
    asm("{ .reg .u64 t; cvta.to.shared.u64 t, %1; cvt.u32.u64 %0, t; }"
        : "=r"(a) : "l"(p));
    return a;
}

#define CPA16(dst, src) \
    asm volatile("cp.async.ca.shared.global [%0], [%1], 16;" \
                 :: "r"(dst), "l"(src) : "memory")
#define CP_COMMIT() asm volatile("cp.async.commit_group;" ::: "memory")
#define CP_WAIT(n)  asm volatile("cp.async.wait_group %0;" :: "n"(n) : "memory")

#define LDSM4(r, addr) \
    asm volatile("ldmatrix.sync.aligned.m8n8.x4.shared.b16 {%0,%1,%2,%3}, [%4];" \
                 : "=r"((r)[0]), "=r"((r)[1]), "=r"((r)[2]), "=r"((r)[3])        \
                 : "r"(addr))

#define MMA16816(c, a, b) \
    asm volatile("mma.sync.aligned.m16n8k16.row.col.f32.bf16.bf16.f32 "          \
                 "{%0,%1,%2,%3}, {%4,%5,%6,%7}, {%8,%9}, {%0,%1,%2,%3};"         \
                 : "+f"((c)[0]), "+f"((c)[1]), "+f"((c)[2]), "+f"((c)[3])        \
                 : "r"((a)[0]), "r"((a)[1]), "r"((a)[2]), "r"((a)[3]),           \
                   "r"((b)[0]), "r"((b)[1]))

__device__ __forceinline__ uint32_t bf2pack(float a, float b) {
    __nv_bfloat162 t = __floats2bfloat162_rn(a, b);
    return *(uint32_t*)&t;
}

// ---------------------------------------------------------------------------
// fp32 -> bf16 hi/lo split, all 5 inputs in one launch.
// ---------------------------------------------------------------------------
__global__ void __launch_bounds__(256) cvt_all(const float* __restrict__ x,
                                               const float* __restrict__ wq,
                                               const float* __restrict__ wk,
                                               const float* __restrict__ wv,
                                               const float* __restrict__ wo)
{
    int i = (blockIdx.x * blockDim.x + threadIdx.x) * 4;
    const float* s;
    __nv_bfloat16 *dh, *dl;
    int off;
    if (i < M_ * K_) {
        s = x; dh = g_xh; dl = g_xl; off = i;
    } else {
        const int j = i - M_ * K_;
        const int r = j >> 20;               // / (H_*K_)
        off = j & (H_ * K_ - 1);
        s = (r == 0) ? wq : (r == 1) ? wk : (r == 2) ? wv : wo;
        dh = g_wh[r]; dl = g_wl[r];
    }

    float4 v = *(const float4*)(s + off);
    float vv[4] = {v.x, v.y, v.z, v.w};
    __nv_bfloat16 h[4], l[4];
#pragma unroll
    for (int j = 0; j < 4; j++) {
        h[j] = __float2bfloat16(vv[j]);
        l[j] = __float2bfloat16(vv[j] - __bfloat162float(h[j]));
    }
    *(__nv_bfloat162*)&dh[off]     = __nv_bfloat162(h[0], h[1]);
    *(__nv_bfloat162*)&dh[off + 2] = __nv_bfloat162(h[2], h[3]);
    *(__nv_bfloat162*)&dl[off]     = __nv_bfloat162(l[0], l[1]);
    *(__nv_bfloat162*)&dl[off + 2] = __nv_bfloat162(l[2], l[3]);
}

// ---------------------------------------------------------------------------
// HMMA GEMM, bf16 3-way split. CTA 128x128, BK=32, 256 thr (8 warps),
// warp tile 64x32, cp.async double buffer, single barrier per chunk.
// WARP DE-PHASING: warps 4-7 (the SMSP siblings of 0-3) traverse the ks
// sub-chunks in reverse order, so on every SMSP one warp is in its LDSM
// phase while the sibling is in its MMA phase -> crossbar/tensor overlap.
// ---------------------------------------------------------------------------
constexpr int LDS_B  = 80;
constexpr int ASZ    = 128 * LDS_B;    // 10240
constexpr int STAGE  = 4 * ASZ;
constexpr int GEMM_SMEM = 2 * STAGE;   // 81920

__global__ void __launch_bounds__(256, 2) hgemm(const float* __restrict__ bias0,
                                                const float* __restrict__ bias1,
                                                const float* __restrict__ bias2,
                                                float* __restrict__ Cext,
                                                const float* __restrict__ cosb,
                                                const float* __restrict__ sinb,
                                                int fixed_mode)
{
    extern __shared__ char sm[];
    const int mode = (fixed_mode >= 0) ? fixed_mode : (int)blockIdx.z;
    const float* bias = (mode == 1) ? bias1 : (mode == 2) ? bias2 : bias0;

    const int tid  = threadIdx.x;
    const int lane = tid & 31;
    const int wid  = tid >> 5;
    const int wm   = (wid >> 2) * 64;
    const int wn   = (wid & 3) * 32;
    const int phase = (wid >> 2) & 1;    // 0: warps 0-3, 1: warps 4-7
    const int n0 = blockIdx.x * 128, m0 = blockIdx.y * 128;

    const __nv_bfloat16* Ah = (mode == 3) ? g_ah : g_xh;
    const __nv_bfloat16* Al = (mode == 3) ? g_al : g_xl;
    const __nv_bfloat16* Wh = g_wh[mode];
    const __nv_bfloat16* Wl = g_wl[mode];

    const uint32_t sbase = smem_u32(sm);

    const int lr = tid >> 1;
    const size_t gA = (size_t)(m0 + lr) * K_ + (tid & 1) * 16;
    const size_t gW = (size_t)(n0 + lr) * K_ + (tid & 1) * 16;
    const uint32_t srow = (uint32_t)(lr * LDS_B + (tid & 1) * 32);

    float acc[4][4][4];
#pragma unroll
    for (int a = 0; a < 4; a++)
#pragma unroll
        for (int b = 0; b < 4; b++)
#pragma unroll
            for (int c = 0; c < 4; c++) acc[a][b][c] = 0.0f;

#define LOAD_CHUNK(ch) do {                                                   \
    const uint32_t st = sbase + ((ch) & 1) * STAGE + srow;                    \
    const char* pa = (const char*)(Ah + gA + (ch) * 32);                      \
    const char* pl = (const char*)(Al + gA + (ch) * 32);                      \
    const char* pw = (const char*)(Wh + gW + (ch) * 32);                      \
    const char* pv = (const char*)(Wl + gW + (ch) * 32);                      \
    CPA16(st,               pa); CPA16(st + 16,           pa + 16);           \
    CPA16(st + ASZ,         pl); CPA16(st + ASZ + 16,     pl + 16);           \
    CPA16(st + 2 * ASZ,     pw); CPA16(st + 2 * ASZ + 16, pw + 16);           \
    CPA16(st + 3 * ASZ,     pv); CPA16(st + 3 * ASZ + 16, pv + 16);           \
    CP_COMMIT();                                                              \
} while (0)

    LOAD_CHUNK(0);

    for (int ch = 0; ch < 32; ch++) {
        CP_WAIT(0);
        __syncthreads();
        if (ch < 31) LOAD_CHUNK(ch + 1);

        const uint32_t stg = sbase + (ch & 1) * STAGE;
#pragma unroll
        for (int ks2 = 0; ks2 < 2; ks2++) {
            const int ks = phase ? (1 - ks2) : ks2;   // de-phase SMSP siblings
            const int kb = ks * 32;
            uint32_t bH[4][2], bL[4][2];
#pragma unroll
            for (int nh = 0; nh < 2; nh++) {
                uint32_t bd = stg + 2 * ASZ
                    + (uint32_t)((wn + nh * 16 + ((lane >> 4) << 3) + (lane & 7)) * LDS_B
                                 + kb + (((lane >> 3) & 1) << 4));
                uint32_t r[4];
                LDSM4(r, bd);
                bH[nh * 2][0] = r[0]; bH[nh * 2][1] = r[1];
                bH[nh * 2 + 1][0] = r[2]; bH[nh * 2 + 1][1] = r[3];
                LDSM4(r, bd + ASZ);
                bL[nh * 2][0] = r[0]; bL[nh * 2][1] = r[1];
                bL[nh * 2 + 1][0] = r[2]; bL[nh * 2 + 1][1] = r[3];
            }
#pragma unroll
            for (int mi = 0; mi < 4; mi++) {
                uint32_t aH[4], aL[4];
                const uint32_t ad = stg + (uint32_t)((wm + mi * 16 + (lane & 15)) * LDS_B
                                                     + kb + ((lane >> 4) << 4));
                LDSM4(aH, ad);
                LDSM4(aL, ad + ASZ);
#pragma unroll
                for (int ni = 0; ni < 4; ni++) MMA16816(acc[mi][ni], aH, bH[ni]);
#pragma unroll
                for (int ni = 0; ni < 4; ni++) MMA16816(acc[mi][ni], aH, bL[ni]);
#pragma unroll
                for (int ni = 0; ni < 4; ni++) MMA16816(acc[mi][ni], aL, bH[ni]);
            }
        }
    }
    __syncthreads();

    // ---- epilogue: stage C tile in smem, then fused writeout
    constexpr int LDC = 132;
    float* Csm = (float*)sm;
#pragma unroll
    for (int mi = 0; mi < 4; mi++) {
        const int row = wm + mi * 16 + (lane >> 2);
#pragma unroll
        for (int ni = 0; ni < 4; ni++) {
            const int col = wn + ni * 8 + (lane & 3) * 2;
            *(float2*)&Csm[row * LDC + col] =
                make_float2(acc[mi][ni][0], acc[mi][ni][1]);
            *(float2*)&Csm[(row + 8) * LDC + col] =
                make_float2(acc[mi][ni][2], acc[mi][ni][3]);
        }
    }
    __syncthreads();

    if (mode <= 1) {
        __nv_bfloat16* Ch = (mode == 0) ? g_qh : g_kh;
        __nv_bfloat16* Cl = (mode == 0) ? g_ql : g_kl;
#pragma unroll 2
        for (int i = 0; i < 16; i++) {
            const int id  = tid + 256 * i;
            const int dp  = id & 15;
            const int hh  = (id >> 4) & 1;
            const int row = id >> 5;
            const int d0  = dp * 2;
            const int m   = m0 + row;
            const int s   = m & (S_ - 1);
            const int bb  = m >> 11;
            float oA[2], oB[2];
#pragma unroll
            for (int e = 0; e < 2; e++) {
                const int d = d0 + e, c = hh * 64 + d;
                const float v0 = Csm[row * LDC + c]      + bias[n0 + c];
                const float v1 = Csm[row * LDC + c + 32] + bias[n0 + c + 32];
                const float cs0 = cosb[s * HD_ + d],      sn0 = sinb[s * HD_ + d];
                const float cs1 = cosb[s * HD_ + d + 32], sn1 = sinb[s * HD_ + d + 32];
                oA[e] = v0 * cs0 - v1 * sn0;
                oB[e] = v1 * cs1 + v0 * sn1;
            }
            const int hidx = (n0 >> 6) + hh;
            const size_t base = ((size_t)(bb * NH_ + hidx) * S_ + s) * HD_;
            const __nv_bfloat16 a0 = __float2bfloat16(oA[0]);
            const __nv_bfloat16 a1 = __float2bfloat16(oA[1]);
            const __nv_bfloat16 c0 = __float2bfloat16(oB[0]);
            const __nv_bfloat16 c1 = __float2bfloat16(oB[1]);
            *(__nv_bfloat162*)&Ch[base + d0]      = __nv_bfloat162(a0, a1);
            *(__nv_bfloat162*)&Ch[base + d0 + 32] = __nv_bfloat162(c0, c1);
            *(__nv_bfloat162*)&Cl[base + d0] = __nv_bfloat162(
                __float2bfloat16(oA[0] - __bfloat162float(a0)),
                __float2bfloat16(oA[1] - __bfloat162float(a1)));
            *(__nv_bfloat162*)&Cl[base + d0 + 32] = __nv_bfloat162(
                __float2bfloat16(oB[0] - __bfloat162float(c0)),
                __float2bfloat16(oB[1] - __bfloat162float(c1)));
        }
    } else if (mode == 2) {
#pragma unroll 2
        for (int i = 0; i < 32; i++) {
            const int id  = tid + 256 * i;
            const int sp  = id & 63;
            const int c   = id >> 6;
            const int row0 = sp * 2;
            const int m   = m0 + row0;
            const int s   = m & (S_ - 1);
            const int bb  = m >> 11;
            const int n   = n0 + c;
            const int hidx = n >> 6, d = n & 63;
            const float v0 = Csm[row0 * LDC + c]       + bias[n];
            const float v1 = Csm[(row0 + 1) * LDC + c] + bias[n];
            const __nv_bfloat16 h0 = __float2bfloat16(v0);
            const __nv_bfloat16 h1 = __float2bfloat16(v1);
            const size_t o = ((size_t)(bb * NH_ + hidx) * HD_ + d) * S_ + s;
            *(__nv_bfloat162*)&g_vh[o] = __nv_bfloat162(h0, h1);
            *(__nv_bfloat162*)&g_vl[o] = __nv_bfloat162(
                __float2bfloat16(v0 - __bfloat162float(h0)),
                __float2bfloat16(v1 - __bfloat162float(h1)));
        }
    } else {
#pragma unroll 4
        for (int i = 0; i < 16; i++) {
            const int id  = tid + 256 * i;
            const int c4  = (id & 31) * 4;
            const int row = id >> 5;
            const int m   = m0 + row;
            const int n   = n0 + c4;
            float4 v;
            v.x = Csm[row * LDC + c4 + 0] + bias[n + 0];
            v.y = Csm[row * LDC + c4 + 1] + bias[n + 1];
            v.z = Csm[row * LDC + c4 + 2] + bias[n + 2];
            v.w = Csm[row * LDC + c4 + 3] + bias[n + 3];
            *(float4*)&Cext[(size_t)m * H_ + n] = v;
        }
    }
}

// ---------------------------------------------------------------------------
// Flash attention, HMMA bf16 3-way split — software pipelined (round-11).
// ---------------------------------------------------------------------------
constexpr int LDSA     = 144;
constexpr int QBYTES   = 2 * 128 * LDSA;        // 36864
constexpr int KVSTAGE  = 4 * 64 * LDSA;         // 36864
constexpr int ATT3_SMEM = QBYTES + 4 * KVSTAGE; // 184320

__global__ void __launch_bounds__(256) attn_hmma(const int* __restrict__ mask)
{
    extern __shared__ char sm[];
    const uint32_t sb = smem_u32(sm);
    __shared__ int msk[4][64];

    const int tid = threadIdx.x, lane = tid & 31, w = tid >> 5;
    const int bh = blockIdx.y, b = bh >> 4, h = bh & 15;
    const int q0 = blockIdx.x * 128;

    const __nv_bfloat16* Qhp = g_qh + (size_t)bh * S_ * HD_;
    const __nv_bfloat16* Qlp = g_ql + (size_t)bh * S_ * HD_;
    const __nv_bfloat16* Khp = g_kh + (size_t)bh * S_ * HD_;
    const __nv_bfloat16* Klp = g_kl + (size_t)bh * S_ * HD_;
    const __nv_bfloat16* Vhp = g_vh + (size_t)bh * HD_ * S_;
    const __nv_bfloat16* Vlp = g_vl + (size_t)bh * HD_ * S_;
    const int* maskp = mask + b * S_;

#pragma unroll
    for (int i = 0; i < 4; i++) {
        const int idx = tid + 256 * i;
        const int row = idx >> 3, chk = idx & 7;
        const uint32_t dst = sb + (uint32_t)(row * LDSA + chk * 16);
        CPA16(dst,         (const char*)(Qhp + (size_t)(q0 + row) * HD_ + chk * 8));
        CPA16(dst + 18432, (const char*)(Qlp + (size_t)(q0 + row) * HD_ + chk * 8));
    }

#define LOADKV(t) do {                                                          \
    const int kt_ = (t) * 64;                                                   \
    const uint32_t st = sb + QBYTES + ((t) & 3) * KVSTAGE;                      \
    _Pragma("unroll")                                                           \
    for (int i_ = 0; i_ < 2; i_++) {                                            \
        const int idx_ = tid + 256 * i_;                                        \
        const int row_ = idx_ >> 3, ch_ = idx_ & 7;                             \
        const uint32_t ro_ = (uint32_t)(row_ * LDSA + ch_ * 16);                \
        CPA16(st + ro_,          (const char*)(Khp + (size_t)(kt_ + row_) * HD_ + ch_ * 8)); \
        CPA16(st + 9216 + ro_,   (const char*)(Klp + (size_t)(kt_ + row_) * HD_ + ch_ * 8)); \
        CPA16(st + 18432 + ro_,  (const char*)(Vhp + (size_t)row_ * S_ + kt_ + ch_ * 8));    \
        CPA16(st + 27648 + ro_,  (const char*)(Vlp + (size_t)row_ * S_ + kt_ + ch_ * 8));    \
    }                                                                           \
    if (tid < 64) msk[(t) & 3][tid] = maskp[kt_ + tid];                         \
    CP_COMMIT();                                                                \
} while (0)

    LOADKV(0);
    LOADKV(1);
    LOADKV(2);

    float m_[2] = {-1e30f, -1e30f}, l_[2] = {0.0f, 0.0f};
    float oacc[8][4];
#pragma unroll
    for (int n = 0; n < 8; n++)
#pragma unroll
        for (int j = 0; j < 4; j++) oacc[n][j] = 0.0f;

    uint32_t qfh[4][4], qfl[4][4];
    const int c01 = (lane & 3) * 2;
    constexpr int NT = S_ / 64;

    float sA[8][4], sB[8][4];

    auto QK = [&](float (&sacc)[8][4], int ti) {
        const uint32_t kst = sb + QBYTES + (ti & 3) * KVSTAGE;
#pragma unroll
        for (int n = 0; n < 8; n++)
#pragma unroll
            for (int j = 0; j < 4; j++) sacc[n][j] = 0.0f;
#pragma unroll
        for (int kk = 0; kk < 4; kk++) {
            uint32_t rh[4][4], rl[4][4];
#pragma unroll
            for (int nh = 0; nh < 4; nh++) {
                const uint32_t bd = kst
                    + (uint32_t)((nh * 16 + ((lane >> 4) << 3) + (lane & 7)) * LDSA
                                 + kk * 32 + (((lane >> 3) & 1) << 4));
                LDSM4(rh[nh], bd);
                LDSM4(rl[nh], bd + 9216);
            }
#pragma unroll
            for (int nh = 0; nh < 4; nh++) {
                uint32_t b0[2] = {rh[nh][0], rh[nh][1]}, b1[2] = {rh[nh][2], rh[nh][3]};
                MMA16816(sacc[nh * 2],     qfh[kk], b0);
                MMA16816(sacc[nh * 2 + 1], qfh[kk], b1);
            }
#pragma unroll
            for (int nh = 0; nh < 4; nh++) {
                uint32_t d0[2] = {rl[nh][0], rl[nh][1]}, d1[2] = {rl[nh][2], rl[nh][3]};
                MMA16816(sacc[nh * 2],     qfh[kk], d0);
                MMA16816(sacc[nh * 2 + 1], qfh[kk], d1);
            }
#pragma unroll
            for (int nh = 0; nh < 4; nh++) {
                uint32_t b0[2] = {rh[nh][0], rh[nh][1]}, b1[2] = {rh[nh][2], rh[nh][3]};
                MMA16816(sacc[nh * 2],     qfl[kk], b0);
                MMA16816(sacc[nh * 2 + 1], qfl[kk], b1);
            }
        }
    };

    auto SMAX = [&](float (&sacc)[8][4], int ti) {
        float mx[2] = {-1e30f, -1e30f};
#pragma unroll
        for (int n = 0; n < 8; n++) {
            const int cc = n * 8 + c01;
            const int mk0 = msk[ti & 3][cc], mk1 = msk[ti & 3][cc + 1];
#pragma unroll
            for (int j = 0; j < 4; j++) {
                float v = sacc[n][j] * 0.125f;
                v = ((j & 1) ? mk1 : mk0) ? v : -1e30f;
                sacc[n][j] = v;
                mx[j >> 1] = fmaxf(mx[j >> 1], v);
            }
        }
        float corr[2], rs[2] = {0.0f, 0.0f};
#pragma unroll
        for (int r = 0; r < 2; r++) {
            mx[r] = fmaxf(mx[r], __shfl_xor_sync(0xffffffffu, mx[r], 1, 4));
            mx[r] = fmaxf(mx[r], __shfl_xor_sync(0xffffffffu, mx[r], 2, 4));
            const float mn = fmaxf(m_[r], mx[r]);
            corr[r] = __expf(m_[r] - mn);
            m_[r] = mn;
        }
#pragma unroll
        for (int n = 0; n < 8; n++)
#pragma unroll
            for (int j = 0; j < 4; j++) {
                const float p = __expf(sacc[n][j] - m_[j >> 1]);
                sacc[n][j] = p;
                rs[j >> 1] += p;
            }
#pragma unroll
        for (int r = 0; r < 2; r++) {
            rs[r] += __shfl_xor_sync(0xffffffffu, rs[r], 1, 4);
            rs[r] += __shfl_xor_sync(0xffffffffu, rs[r], 2, 4);
            l_[r] = l_[r] * corr[r] + rs[r];
        }
#pragma unroll
        for (int n = 0; n < 8; n++)
#pragma unroll
            for (int j = 0; j < 4; j++) oacc[n][j] *= corr[j >> 1];
    };

    auto PV = [&](float (&sacc)[8][4], int ti) {
        const uint32_t kst = sb + QBYTES + (ti & 3) * KVSTAGE;
#pragma unroll
        for (int j = 0; j < 4; j++) {
            uint32_t aPh[4], aPl[4];
#pragma unroll
            for (int half = 0; half < 2; half++) {
                const float p0 = sacc[2 * j + half][0];
                const float p1 = sacc[2 * j + half][1];
                const float p2 = sacc[2 * j + half][2];
                const float p3 = sacc[2 * j + half][3];
                const float q0f = __bfloat162float(__float2bfloat16(p0));
                const float q1f = __bfloat162float(__float2bfloat16(p1));
                const float q2f = __bfloat162float(__float2bfloat16(p2));
                const float q3f = __bfloat162float(__float2bfloat16(p3));
                aPh[half * 2]     = bf2pack(p0, p1);
                aPh[half * 2 + 1] = bf2pack(p2, p3);
                aPl[half * 2]     = bf2pack(p0 - q0f, p1 - q1f);
                aPl[half * 2 + 1] = bf2pack(p2 - q2f, p3 - q3f);
            }
            uint32_t rh[4][4], rl[4][4];
#pragma unroll
            for (int nh = 0; nh < 4; nh++) {
                const uint32_t bd = kst + 18432
                    + (uint32_t)((nh * 16 + ((lane >> 4) << 3) + (lane & 7)) * LDSA
                                 + j * 32 + (((lane >> 3) & 1) << 4));
                LDSM4(rh[nh], bd);
                LDSM4(rl[nh], bd + 9216);
            }
#pragma unroll
            for (int nh = 0; nh < 4; nh++) {
                uint32_t b0[2] = {rh[nh][0], rh[nh][1]}, b1[2] = {rh[nh][2], rh[nh][3]};
                MMA16816(oacc[nh * 2],     aPh, b0);
                MMA16816(oacc[nh * 2 + 1], aPh, b1);
            }
#pragma unroll
            for (int nh = 0; nh < 4; nh++) {
                uint32_t d0[2] = {rl[nh][0], rl[nh][1]}, d1[2] = {rl[nh][2], rl[nh][3]};
                MMA16816(oacc[nh * 2],     aPh, d0);
                MMA16816(oacc[nh * 2 + 1], aPh, d1);
            }
#pragma unroll
            for (int nh = 0; nh < 4; nh++) {
                uint32_t b0[2] = {rh[nh][0], rh[nh][1]}, b1[2] = {rh[nh][2], rh[nh][3]};
                MMA16816(oacc[nh * 2],     aPl, b0);
                MMA16816(oacc[nh * 2 + 1], aPl, b1);
            }
        }
    };

    // ---- prologue ----
    CP_WAIT(2);
    __syncthreads();
#pragma unroll
    for (int kk = 0; kk < 4; kk++) {
        const uint32_t ad = sb + (uint32_t)((w * 16 + (lane & 15)) * LDSA
                                            + kk * 32 + ((lane >> 4) << 4));
        LDSM4(qfh[kk], ad);
        LDSM4(qfl[kk], ad + 18432);
    }
    QK(sA, 0);

    // ---- main loop, unrolled x2 ----
    for (int t = 0; t < NT; t += 2) {
        if (t + 3 < NT) { CP_WAIT(1); } else { CP_WAIT(0); }
        __syncthreads();
        if (t + 3 < NT) LOADKV(t + 3);
        QK(sB, t + 1);
        SMAX(sA, t);
        PV(sA, t);

        if (t + 4 < NT) { CP_WAIT(1); } else { CP_WAIT(0); }
        __syncthreads();
        if (t + 4 < NT) LOADKV(t + 4);
        if (t + 2 < NT) QK(sA, t + 2);
        SMAX(sB, t + 1);
        PV(sB, t + 1);
    }

    // ---- epilogue ----
    const int r0 = lane >> 2;
#pragma unroll
    for (int r = 0; r < 2; r++) {
        const float inv = 1.0f / l_[r];
        const int srow = q0 + w * 16 + r0 + 8 * r;
        const size_t base = ((size_t)b * S_ + srow) * H_ + h * 64 + c01;
#pragma unroll
        for (int n = 0; n < 8; n++) {
            const float v0 = oacc[n][2 * r]     * inv;
            const float v1 = oacc[n][2 * r + 1] * inv;
            const __nv_bfloat16 h0 = __float2bfloat16(v0);
            const __nv_bfloat16 h1 = __float2bfloat16(v1);
            *(__nv_bfloat162*)&g_ah[base + n * 8] = __nv_bfloat162(h0, h1);
            *(__nv_bfloat162*)&g_al[base + n * 8] = __nv_bfloat162(
                __float2bfloat16(v0 - __bfloat162float(h0)),
                __float2bfloat16(v1 - __bfloat162float(h1)));
        }
    }
}

// ---------------------------------------------------------------------------
extern "C" void kernel_launch(void* const* d_in, const int* in_sizes, int n_in,
                              void* d_out, int out_size)
{
    const float* x    = (const float*)d_in[0];
    const int*   mask = (const int*)  d_in[1];
    const float* cosb = (const float*)d_in[2];
    const float* sinb = (const float*)d_in[3];
    const float* Wq   = (const float*)d_in[4];
    const float* bq   = (const float*)d_in[5];
    const float* Wk   = (const float*)d_in[6];
    const float* bk   = (const float*)d_in[7];
    const float* Wv   = (const float*)d_in[8];
    const float* bv   = (const float*)d_in[9];
    const float* Wo   = (const float*)d_in[10];
    const float* bo   = (const float*)d_in[11];
    float* out = (float*)d_out;

    cudaFuncSetAttribute(hgemm,
                         cudaFuncAttributeMaxDynamicSharedMemorySize, GEMM_SMEM);
    cudaFuncSetAttribute(attn_hmma,
                         cudaFuncAttributeMaxDynamicSharedMemorySize, ATT3_SMEM);

    cvt_all<<<(M_ * K_ + 4 * H_ * K_) / 1024, 256>>>(x, Wq, Wk, Wv, Wo);

    dim3 gqkv(H_ / 128, M_ / 128, 3);
    hgemm<<<gqkv, 256, GEMM_SMEM>>>(bq, bk, bv, nullptr, cosb, sinb, -1);

    dim3 ag(S_ / 128, B_ * NH_);
    attn_hmma<<<ag, 256, ATT3_SMEM>>>(mask);

    dim3 gg(H_ / 128, M_ / 128);
    hgemm<<<gg, 256, GEMM_SMEM>>>(bo, bo, bo, out, cosb, sinb, 3);
}

// round 13
// speedup vs baseline: 1.2107x; 1.0384x over previous
#include <cuda_runtime.h>
#include <cuda_bf16.h>
#include <cuda_fp16.h>
#include <math.h>
#include <stdint.h>

// Problem constants
constexpr int B_  = 2;
constexpr int S_  = 2048;
constexpr int H_  = 1024;
constexpr int NH_ = 16;
constexpr int HD_ = 64;
constexpr int M_  = B_ * S_;   // 4096
constexpr int K_  = H_;        // 1024

// split-trick constants (s = 256)
constexpr float SPLIT_S   = 256.0f;
constexpr float INV_S     = 1.0f / 256.0f;
constexpr float C1_       = 1.0f - INV_S;        // 0.99609375 (exact fp32)
constexpr float INV_C1    = 256.0f / 255.0f;

// ---------------- scratch (device globals; no allocation allowed) ----------
// Attention operands: fp16 (hi, mixed') pairs. Q/K [b,h,s,d]; V [b,h,d,s].
__device__ __align__(16) __half g_qh[(size_t)B_ * NH_ * S_ * HD_];
__device__ __align__(16) __half g_qp[(size_t)B_ * NH_ * S_ * HD_];   // Qh + s*Ql
__device__ __align__(16) __half g_kh[(size_t)B_ * NH_ * S_ * HD_];
__device__ __align__(16) __half g_kp[(size_t)B_ * NH_ * S_ * HD_];   // Kh/s + Kl
__device__ __align__(16) __half g_vh[(size_t)B_ * NH_ * HD_ * S_];
__device__ __align__(16) __half g_vp[(size_t)B_ * NH_ * HD_ * S_];   // Vh/s + Vl

// bf16 hi/lo split inputs (hgemm 3-term path, unchanged)
__device__ __align__(16) __nv_bfloat16 g_xh[(size_t)M_ * K_];
__device__ __align__(16) __nv_bfloat16 g_xl[(size_t)M_ * K_];
__device__ __align__(16) __nv_bfloat16 g_wh[4][(size_t)H_ * K_];   // q,k,v,o
__device__ __align__(16) __nv_bfloat16 g_wl[4][(size_t)H_ * K_];
__device__ __align__(16) __nv_bfloat16 g_ah[(size_t)M_ * H_];
__device__ __align__(16) __nv_bfloat16 g_al[(size_t)M_ * H_];

// ---------------- PTX helpers ----------------------------------------------
__device__ __forceinline__ uint32_t smem_u32(const void* p) {
    uint32_t a;
    asm("{ .reg .u64 t; cvta.to.shared.u64 t, %1; cvt.u32.u64 %0, t; }"
        : "=r"(a) : "l"(p));
    return a;
}

#define CPA16(dst, src) \
    asm volatile("cp.async.ca.shared.global [%0], [%1], 16;" \
                 :: "r"(dst), "l"(src) : "memory")
#define CP_COMMIT() asm volatile("cp.async.commit_group;" ::: "memory")
#define CP_WAIT(n)  asm volatile("cp.async.wait_group %0;" :: "n"(n) : "memory")

#define LDSM4(r, addr) \
    asm volatile("ldmatrix.sync.aligned.m8n8.x4.shared.b16 {%0,%1,%2,%3}, [%4];" \
                 : "=r"((r)[0]), "=r"((r)[1]), "=r"((r)[2]), "=r"((r)[3])        \
                 : "r"(addr))

// bf16 MMA (hgemm path)
#define MMA16816(c, a, b) \
    asm volatile("mma.sync.aligned.m16n8k16.row.col.f32.bf16.bf16.f32 "          \
                 "{%0,%1,%2,%3}, {%4,%5,%6,%7}, {%8,%9}, {%0,%1,%2,%3};"         \
                 : "+f"((c)[0]), "+f"((c)[1]), "+f"((c)[2]), "+f"((c)[3])        \
                 : "r"((a)[0]), "r"((a)[1]), "r"((a)[2]), "r"((a)[3]),           \
                   "r"((b)[0]), "r"((b)[1]))

// fp16 MMA (attention path)
#define MMAF16(c, a, b) \
    asm volatile("mma.sync.aligned.m16n8k16.row.col.f32.f16.f16.f32 "            \
                 "{%0,%1,%2,%3}, {%4,%5,%6,%7}, {%8,%9}, {%0,%1,%2,%3};"         \
                 : "+f"((c)[0]), "+f"((c)[1]), "+f"((c)[2]), "+f"((c)[3])        \
                 : "r"((a)[0]), "r"((a)[1]), "r"((a)[2]), "r"((a)[3]),           \
                   "r"((b)[0]), "r"((b)[1]))

__device__ __forceinline__ uint32_t h2pack(float a, float b) {
    __half2 t = __floats2half2_rn(a, b);
    return *(uint32_t*)&t;
}

// ---------------------------------------------------------------------------
// fp32 -> bf16 hi/lo split, all 5 inputs in one launch (unchanged).
// ---------------------------------------------------------------------------
__global__ void __launch_bounds__(256) cvt_all(const float* __restrict__ x,
                                               const float* __restrict__ wq,
                                               const float* __restrict__ wk,
                                               const float* __restrict__ wv,
                                               const float* __restrict__ wo)
{
    int i = (blockIdx.x * blockDim.x + threadIdx.x) * 4;
    const float* s;
    __nv_bfloat16 *dh, *dl;
    int off;
    if (i < M_ * K_) {
        s = x; dh = g_xh; dl = g_xl; off = i;
    } else {
        const int j = i - M_ * K_;
        const int r = j >> 20;
        off = j & (H_ * K_ - 1);
        s = (r == 0) ? wq : (r == 1) ? wk : (r == 2) ? wv : wo;
        dh = g_wh[r]; dl = g_wl[r];
    }

    float4 v = *(const float4*)(s + off);
    float vv[4] = {v.x, v.y, v.z, v.w};
    __nv_bfloat16 h[4], l[4];
#pragma unroll
    for (int j = 0; j < 4; j++) {
        h[j] = __float2bfloat16(vv[j]);
        l[j] = __float2bfloat16(vv[j] - __bfloat162float(h[j]));
    }
    *(__nv_bfloat162*)&dh[off]     = __nv_bfloat162(h[0], h[1]);
    *(__nv_bfloat162*)&dh[off + 2] = __nv_bfloat162(h[2], h[3]);
    *(__nv_bfloat162*)&dl[off]     = __nv_bfloat162(l[0], l[1]);
    *(__nv_bfloat162*)&dl[off + 2] = __nv_bfloat162(l[2], l[3]);
}

// ---------------------------------------------------------------------------
// HMMA GEMM, bf16 3-way split (round-10 winner). Epilogues now emit fp16
// (hi, mixed') operand pairs for the attention 2-MMA scheme.
// ---------------------------------------------------------------------------
constexpr int LDS_B  = 80;
constexpr int ASZ    = 128 * LDS_B;    // 10240
constexpr int STAGE  = 4 * ASZ;
constexpr int GEMM_SMEM = 2 * STAGE;   // 81920

__global__ void __launch_bounds__(256, 2) hgemm(const float* __restrict__ bias0,
                                                const float* __restrict__ bias1,
                                                const float* __restrict__ bias2,
                                                float* __restrict__ Cext,
                                                const float* __restrict__ cosb,
                                                const float* __restrict__ sinb,
                                                int fixed_mode)
{
    extern __shared__ char sm[];
    const int mode = (fixed_mode >= 0) ? fixed_mode : (int)blockIdx.z;
    const float* bias = (mode == 1) ? bias1 : (mode == 2) ? bias2 : bias0;

    const int tid  = threadIdx.x;
    const int lane = tid & 31;
    const int wid  = tid >> 5;
    const int wm   = (wid >> 2) * 64;
    const int wn   = (wid & 3) * 32;
    const int n0 = blockIdx.x * 128, m0 = blockIdx.y * 128;

    const __nv_bfloat16* Ah = (mode == 3) ? g_ah : g_xh;
    const __nv_bfloat16* Al = (mode == 3) ? g_al : g_xl;
    const __nv_bfloat16* Wh = g_wh[mode];
    const __nv_bfloat16* Wl = g_wl[mode];

    const uint32_t sbase = smem_u32(sm);

    const int lr = tid >> 1;
    const size_t gA = (size_t)(m0 + lr) * K_ + (tid & 1) * 16;
    const size_t gW = (size_t)(n0 + lr) * K_ + (tid & 1) * 16;
    const uint32_t srow = (uint32_t)(lr * LDS_B + (tid & 1) * 32);

    float acc[4][4][4];
#pragma unroll
    for (int a = 0; a < 4; a++)
#pragma unroll
        for (int b = 0; b < 4; b++)
#pragma unroll
            for (int c = 0; c < 4; c++) acc[a][b][c] = 0.0f;

#define LOAD_CHUNK(ch) do {                                                   \
    const uint32_t st = sbase + ((ch) & 1) * STAGE + srow;                    \
    const char* pa = (const char*)(Ah + gA + (ch) * 32);                      \
    const char* pl = (const char*)(Al + gA + (ch) * 32);                      \
    const char* pw = (const char*)(Wh + gW + (ch) * 32);                      \
    const char* pv = (const char*)(Wl + gW + (ch) * 32);                      \
    CPA16(st,               pa); CPA16(st + 16,           pa + 16);           \
    CPA16(st + ASZ,         pl); CPA16(st + ASZ + 16,     pl + 16);           \
    CPA16(st + 2 * ASZ,     pw); CPA16(st + 2 * ASZ + 16, pw + 16);           \
    CPA16(st + 3 * ASZ,     pv); CPA16(st + 3 * ASZ + 16, pv + 16);           \
    CP_COMMIT();                                                              \
} while (0)

    LOAD_CHUNK(0);

    for (int ch = 0; ch < 32; ch++) {
        CP_WAIT(0);
        __syncthreads();
        if (ch < 31) LOAD_CHUNK(ch + 1);

        const uint32_t stg = sbase + (ch & 1) * STAGE;
#pragma unroll
        for (int ks = 0; ks < 2; ks++) {
            const int kb = ks * 32;
            uint32_t bH[4][2], bL[4][2];
#pragma unroll
            for (int nh = 0; nh < 2; nh++) {
                uint32_t bd = stg + 2 * ASZ
                    + (uint32_t)((wn + nh * 16 + ((lane >> 4) << 3) + (lane & 7)) * LDS_B
                                 + kb + (((lane >> 3) & 1) << 4));
                uint32_t r[4];
                LDSM4(r, bd);
                bH[nh * 2][0] = r[0]; bH[nh * 2][1] = r[1];
                bH[nh * 2 + 1][0] = r[2]; bH[nh * 2 + 1][1] = r[3];
                LDSM4(r, bd + ASZ);
                bL[nh * 2][0] = r[0]; bL[nh * 2][1] = r[1];
                bL[nh * 2 + 1][0] = r[2]; bL[nh * 2 + 1][1] = r[3];
            }
#pragma unroll
            for (int mi = 0; mi < 4; mi++) {
                uint32_t aH[4], aL[4];
                const uint32_t ad = stg + (uint32_t)((wm + mi * 16 + (lane & 15)) * LDS_B
                                                     + kb + ((lane >> 4) << 4));
                LDSM4(aH, ad);
                LDSM4(aL, ad + ASZ);
#pragma unroll
                for (int ni = 0; ni < 4; ni++) MMA16816(acc[mi][ni], aH, bH[ni]);
#pragma unroll
                for (int ni = 0; ni < 4; ni++) MMA16816(acc[mi][ni], aH, bL[ni]);
#pragma unroll
                for (int ni = 0; ni < 4; ni++) MMA16816(acc[mi][ni], aL, bH[ni]);
            }
        }
    }
    __syncthreads();

    // ---- epilogue: stage C tile in smem, then fused writeout
    constexpr int LDC = 132;
    float* Csm = (float*)sm;
#pragma unroll
    for (int mi = 0; mi < 4; mi++) {
        const int row = wm + mi * 16 + (lane >> 2);
#pragma unroll
        for (int ni = 0; ni < 4; ni++) {
            const int col = wn + ni * 8 + (lane & 3) * 2;
            *(float2*)&Csm[row * LDC + col] =
                make_float2(acc[mi][ni][0], acc[mi][ni][1]);
            *(float2*)&Csm[(row + 8) * LDC + col] =
                make_float2(acc[mi][ni][2], acc[mi][ni][3]);
        }
    }
    __syncthreads();

    if (mode <= 1) {
        // RoPE + fp16 (hi, mixed') pairs -> [b,h,s,d]
        __half* Ch = (mode == 0) ? g_qh : g_kh;
        __half* Cp = (mode == 0) ? g_qp : g_kp;
        const bool isq = (mode == 0);
#pragma unroll 2
        for (int i = 0; i < 16; i++) {
            const int id  = tid + 256 * i;
            const int dp  = id & 15;
            const int hh  = (id >> 4) & 1;
            const int row = id >> 5;
            const int d0  = dp * 2;
            const int m   = m0 + row;
            const int s   = m & (S_ - 1);
            const int bb  = m >> 11;
            float oA[2], oB[2];
#pragma unroll
            for (int e = 0; e < 2; e++) {
                const int d = d0 + e, c = hh * 64 + d;
                const float v0 = Csm[row * LDC + c]      + bias[n0 + c];
                const float v1 = Csm[row * LDC + c + 32] + bias[n0 + c + 32];
                const float cs0 = cosb[s * HD_ + d],      sn0 = sinb[s * HD_ + d];
                const float cs1 = cosb[s * HD_ + d + 32], sn1 = sinb[s * HD_ + d + 32];
                oA[e] = v0 * cs0 - v1 * sn0;
                oB[e] = v1 * cs1 + v0 * sn1;
            }
            const int hidx = (n0 >> 6) + hh;
            const size_t base = ((size_t)(bb * NH_ + hidx) * S_ + s) * HD_;
            float hA[2], hB[2], pA[2], pB[2];
#pragma unroll
            for (int e = 0; e < 2; e++) {
                const __half a = __float2half_rn(oA[e]);
                const __half c = __float2half_rn(oB[e]);
                hA[e] = __half2float(a); hB[e] = __half2float(c);
                const float rA = oA[e] - hA[e], rB = oB[e] - hB[e];
                if (isq) { pA[e] = hA[e] + SPLIT_S * rA; pB[e] = hB[e] + SPLIT_S * rB; }
                else     { pA[e] = hA[e] * INV_S + rA;   pB[e] = hB[e] * INV_S + rB; }
            }
            *(uint32_t*)&Ch[base + d0]      = h2pack(hA[0], hA[1]);
            *(uint32_t*)&Ch[base + d0 + 32] = h2pack(hB[0], hB[1]);
            *(uint32_t*)&Cp[base + d0]      = h2pack(pA[0], pA[1]);
            *(uint32_t*)&Cp[base + d0 + 32] = h2pack(pB[0], pB[1]);
        }
    } else if (mode == 2) {
        // V: fp16 (Vh, Vh/s + Vl) -> [b,h,d,s]
#pragma unroll 2
        for (int i = 0; i < 32; i++) {
            const int id  = tid + 256 * i;
            const int sp  = id & 63;
            const int c   = id >> 6;
            const int row0 = sp * 2;
            const int m   = m0 + row0;
            const int s   = m & (S_ - 1);
            const int bb  = m >> 11;
            const int n   = n0 + c;
            const int hidx = n >> 6, d = n & 63;
            const float v0 = Csm[row0 * LDC + c]       + bias[n];
            const float v1 = Csm[(row0 + 1) * LDC + c] + bias[n];
            const float h0 = __half2float(__float2half_rn(v0));
            const float h1 = __half2float(__float2half_rn(v1));
            const size_t o = ((size_t)(bb * NH_ + hidx) * HD_ + d) * S_ + s;
            *(uint32_t*)&g_vh[o] = h2pack(h0, h1);
            *(uint32_t*)&g_vp[o] = h2pack(h0 * INV_S + (v0 - h0),
                                          h1 * INV_S + (v1 - h1));
        }
    } else {
#pragma unroll 4
        for (int i = 0; i < 16; i++) {
            const int id  = tid + 256 * i;
            const int c4  = (id & 31) * 4;
            const int row = id >> 5;
            const int m   = m0 + row;
            const int n   = n0 + c4;
            float4 v;
            v.x = Csm[row * LDC + c4 + 0] + bias[n + 0];
            v.y = Csm[row * LDC + c4 + 1] + bias[n + 1];
            v.z = Csm[row * LDC + c4 + 2] + bias[n + 2];
            v.w = Csm[row * LDC + c4 + 3] + bias[n + 3];
            *(float4*)&Cext[(size_t)m * H_ + n] = v;
        }
    }
}

// ---------------------------------------------------------------------------
// Flash attention, fp16 2-MMA exact-split scheme.
// C = M1*(1-1/s) + M2;  M1 = Xh*Yh, M2 = (Xh+s*Xl)*(Yh/s+Yl).
// QK: sacc pass1(M1) -> *=C1 -> pass2(M2).
// PV: oacc *= corr*INV_C1 -> pass1(M1) -> *=C1 -> pass2(M2).
// 3-stage KV ring, one barrier per tile.
// ---------------------------------------------------------------------------
constexpr int LDSA     = 144;
constexpr int QBYTES   = 2 * 128 * LDSA;        // 36864 (Qh | Q')
constexpr int KVSTAGE  = 4 * 64 * LDSA;         // 36864 (Kh|K'|Vh|V')
constexpr int ATT2_SMEM = QBYTES + 3 * KVSTAGE; // 147456

__global__ void __launch_bounds__(256) attn_hmma(const int* __restrict__ mask)
{
    extern __shared__ char sm[];
    const uint32_t sb = smem_u32(sm);
    __shared__ int msk[3][64];

    const int tid = threadIdx.x, lane = tid & 31, w = tid >> 5;
    const int bh = blockIdx.y, b = bh >> 4, h = bh & 15;
    const int q0 = blockIdx.x * 128;

    const __half* Qhp = g_qh + (size_t)bh * S_ * HD_;
    const __half* Qpp = g_qp + (size_t)bh * S_ * HD_;
    const __half* Khp = g_kh + (size_t)bh * S_ * HD_;
    const __half* Kpp = g_kp + (size_t)bh * S_ * HD_;
    const __half* Vhp = g_vh + (size_t)bh * HD_ * S_;
    const __half* Vpp = g_vp + (size_t)bh * HD_ * S_;
    const int* maskp = mask + b * S_;

#pragma unroll
    for (int i = 0; i < 4; i++) {
        const int idx = tid + 256 * i;
        const int row = idx >> 3, chk = idx & 7;
        const uint32_t dst = sb + (uint32_t)(row * LDSA + chk * 16);
        CPA16(dst,         (const char*)(Qhp + (size_t)(q0 + row) * HD_ + chk * 8));
        CPA16(dst + 18432, (const char*)(Qpp + (size_t)(q0 + row) * HD_ + chk * 8));
    }

#define LOADKV(t) do {                                                          \
    const int kt_ = (t) * 64;                                                   \
    const uint32_t st = sb + QBYTES + ((t) % 3) * KVSTAGE;                      \
    _Pragma("unroll")                                                           \
    for (int i_ = 0; i_ < 2; i_++) {                                            \
        const int idx_ = tid + 256 * i_;                                        \
        const int row_ = idx_ >> 3, ch_ = idx_ & 7;                             \
        const uint32_t ro_ = (uint32_t)(row_ * LDSA + ch_ * 16);                \
        CPA16(st + ro_,          (const char*)(Khp + (size_t)(kt_ + row_) * HD_ + ch_ * 8)); \
        CPA16(st + 9216 + ro_,   (const char*)(Kpp + (size_t)(kt_ + row_) * HD_ + ch_ * 8)); \
        CPA16(st + 18432 + ro_,  (const char*)(Vhp + (size_t)row_ * S_ + kt_ + ch_ * 8));    \
        CPA16(st + 27648 + ro_,  (const char*)(Vpp + (size_t)row_ * S_ + kt_ + ch_ * 8));    \
    }                                                                           \
    if (tid < 64) msk[(t) % 3][tid] = maskp[kt_ + tid];                         \
    CP_COMMIT();                                                                \
} while (0)

    LOADKV(0);
    LOADKV(1);

    float m_[2] = {-1e30f, -1e30f}, l_[2] = {0.0f, 0.0f};
    float oacc[8][4];
#pragma unroll
    for (int n = 0; n < 8; n++)
#pragma unroll
        for (int j = 0; j < 4; j++) oacc[n][j] = 0.0f;

    uint32_t qfh[4][4], qfp[4][4];
    const int c01 = (lane & 3) * 2;
    constexpr int NT = S_ / 64;

    for (int t = 0; t < NT; t++) {
        if (t >= NT - 2) { CP_WAIT(0); }
        else             { CP_WAIT(1); }
        __syncthreads();
        if (t + 2 < NT) LOADKV(t + 2);

        if (t == 0) {
#pragma unroll
            for (int kk = 0; kk < 4; kk++) {
                const uint32_t ad = sb + (uint32_t)((w * 16 + (lane & 15)) * LDSA
                                                    + kk * 32 + ((lane >> 4) << 4));
                LDSM4(qfh[kk], ad);
                LDSM4(qfp[kk], ad + 18432);
            }
        }

        const uint32_t kst = sb + QBYTES + (t % 3) * KVSTAGE;

        // ---- S: pass1 M1 = Qh*Kh ----
        float sacc[8][4];
#pragma unroll
        for (int n = 0; n < 8; n++)
#pragma unroll
            for (int j = 0; j < 4; j++) sacc[n][j] = 0.0f;

#pragma unroll
        for (int kk = 0; kk < 4; kk++) {
            uint32_t rh[4][4];
#pragma unroll
            for (int nh = 0; nh < 4; nh++) {
                const uint32_t bd = kst
                    + (uint32_t)((nh * 16 + ((lane >> 4) << 3) + (lane & 7)) * LDSA
                                 + kk * 32 + (((lane >> 3) & 1) << 4));
                LDSM4(rh[nh], bd);
            }
#pragma unroll
            for (int nh = 0; nh < 4; nh++) {
                uint32_t b0[2] = {rh[nh][0], rh[nh][1]}, b1[2] = {rh[nh][2], rh[nh][3]};
                MMAF16(sacc[nh * 2],     qfh[kk], b0);
                MMAF16(sacc[nh * 2 + 1], qfh[kk], b1);
            }
        }
        // scale: sacc *= (1 - 1/s)
#pragma unroll
        for (int n = 0; n < 8; n++)
#pragma unroll
            for (int j = 0; j < 4; j++) sacc[n][j] *= C1_;
        // ---- S: pass2 M2 = Q'*K' ----
#pragma unroll
        for (int kk = 0; kk < 4; kk++) {
            uint32_t rp[4][4];
#pragma unroll
            for (int nh = 0; nh < 4; nh++) {
                const uint32_t bd = kst + 9216
                    + (uint32_t)((nh * 16 + ((lane >> 4) << 3) + (lane & 7)) * LDSA
                                 + kk * 32 + (((lane >> 3) & 1) << 4));
                LDSM4(rp[nh], bd);
            }
#pragma unroll
            for (int nh = 0; nh < 4; nh++) {
                uint32_t b0[2] = {rp[nh][0], rp[nh][1]}, b1[2] = {rp[nh][2], rp[nh][3]};
                MMAF16(sacc[nh * 2],     qfp[kk], b0);
                MMAF16(sacc[nh * 2 + 1], qfp[kk], b1);
            }
        }

        // ---- scale + mask + online softmax ----
        float mx[2] = {-1e30f, -1e30f};
#pragma unroll
        for (int n = 0; n < 8; n++) {
            const int cc = n * 8 + c01;
            const int mk0 = msk[t % 3][cc], mk1 = msk[t % 3][cc + 1];
#pragma unroll
            for (int j = 0; j < 4; j++) {
                float v = sacc[n][j] * 0.125f;
                v = ((j & 1) ? mk1 : mk0) ? v : -1e30f;
                sacc[n][j] = v;
                mx[j >> 1] = fmaxf(mx[j >> 1], v);
            }
        }
        float corr[2], rs[2] = {0.0f, 0.0f};
#pragma unroll
        for (int r = 0; r < 2; r++) {
            mx[r] = fmaxf(mx[r], __shfl_xor_sync(0xffffffffu, mx[r], 1, 4));
            mx[r] = fmaxf(mx[r], __shfl_xor_sync(0xffffffffu, mx[r], 2, 4));
            const float mn = fmaxf(m_[r], mx[r]);
            corr[r] = __expf(m_[r] - mn);
            m_[r] = mn;
        }
#pragma unroll
        for (int n = 0; n < 8; n++)
#pragma unroll
            for (int j = 0; j < 4; j++) {
                const float p = __expf(sacc[n][j] - m_[j >> 1]);
                sacc[n][j] = p;
                rs[j >> 1] += p;
            }
#pragma unroll
        for (int r = 0; r < 2; r++) {
            rs[r] += __shfl_xor_sync(0xffffffffu, rs[r], 1, 4);
            rs[r] += __shfl_xor_sync(0xffffffffu, rs[r], 2, 4);
            l_[r] = l_[r] * corr[r] + rs[r];
        }
        // fold INV_C1 into the softmax rescale: oacc_pre = oacc*corr/C1
#pragma unroll
        for (int n = 0; n < 8; n++)
#pragma unroll
            for (int j = 0; j < 4; j++) oacc[n][j] *= corr[j >> 1] * INV_C1;

        // ---- O: pass1 M1 = Ph*Vh ----
#pragma unroll
        for (int j = 0; j < 4; j++) {
            uint32_t aPh[4];
#pragma unroll
            for (int half = 0; half < 2; half++) {
                aPh[half * 2]     = h2pack(sacc[2 * j + half][0], sacc[2 * j + half][1]);
                aPh[half * 2 + 1] = h2pack(sacc[2 * j + half][2], sacc[2 * j + half][3]);
            }
            uint32_t rh[4][4];
#pragma unroll
            for (int nh = 0; nh < 4; nh++) {
                const uint32_t bd = kst + 18432
                    + (uint32_t)((nh * 16 + ((lane >> 4) << 3) + (lane & 7)) * LDSA
                                 + j * 32 + (((lane >> 3) & 1) << 4));
                LDSM4(rh[nh], bd);
            }
#pragma unroll
            for (int nh = 0; nh < 4; nh++) {
                uint32_t b0[2] = {rh[nh][0], rh[nh][1]}, b1[2] = {rh[nh][2], rh[nh][3]};
                MMAF16(oacc[nh * 2],     aPh, b0);
                MMAF16(oacc[nh * 2 + 1], aPh, b1);
            }
        }
        // oacc *= (1 - 1/s)
#pragma unroll
        for (int n = 0; n < 8; n++)
#pragma unroll
            for (int j = 0; j < 4; j++) oacc[n][j] *= C1_;
        // ---- O: pass2 M2 = P'*V' ----
#pragma unroll
        for (int j = 0; j < 4; j++) {
            uint32_t aPp[4];
#pragma unroll
            for (int half = 0; half < 2; half++) {
                float pv[4];
#pragma unroll
                for (int e = 0; e < 4; e++) {
                    const float p = sacc[2 * j + half][e];
                    const float ph = __half2float(__float2half_rn(p));
                    pv[e] = ph + SPLIT_S * (p - ph);
                }
                aPp[half * 2]     = h2pack(pv[0], pv[1]);
                aPp[half * 2 + 1] = h2pack(pv[2], pv[3]);
            }
            uint32_t rp[4][4];
#pragma unroll
            for (int nh = 0; nh < 4; nh++) {
                const uint32_t bd = kst + 27648
                    + (uint32_t)((nh * 16 + ((lane >> 4) << 3) + (lane & 7)) * LDSA
                                 + j * 32 + (((lane >> 3) & 1) << 4));
                LDSM4(rp[nh], bd);
            }
#pragma unroll
            for (int nh = 0; nh < 4; nh++) {
                uint32_t b0[2] = {rp[nh][0], rp[nh][1]}, b1[2] = {rp[nh][2], rp[nh][3]};
                MMAF16(oacc[nh * 2],     aPp, b0);
                MMAF16(oacc[nh * 2 + 1], aPp, b1);
            }
        }
    }

    // ---- epilogue: /l, write hi/lo bf16 to g_ah/g_al [M,H] ----
    const int r0 = lane >> 2;
#pragma unroll
    for (int r = 0; r < 2; r++) {
        const float inv = 1.0f / l_[r];
        const int srow = q0 + w * 16 + r0 + 8 * r;
        const size_t base = ((size_t)b * S_ + srow) * H_ + h * 64 + c01;
#pragma unroll
        for (int n = 0; n < 8; n++) {
            const float v0 = oacc[n][2 * r]     * inv;
            const float v1 = oacc[n][2 * r + 1] * inv;
            const __nv_bfloat16 h0 = __float2bfloat16(v0);
            const __nv_bfloat16 h1 = __float2bfloat16(v1);
            *(__nv_bfloat162*)&g_ah[base + n * 8] = __nv_bfloat162(h0, h1);
            *(__nv_bfloat162*)&g_al[base + n * 8] = __nv_bfloat162(
                __float2bfloat16(v0 - __bfloat162float(h0)),
                __float2bfloat16(v1 - __bfloat162float(h1)));
        }
    }
}

// ---------------------------------------------------------------------------
extern "C" void kernel_launch(void* const* d_in, const int* in_sizes, int n_in,
                              void* d_out, int out_size)
{
    const float* x    = (const float*)d_in[0];
    const int*   mask = (const int*)  d_in[1];
    const float* cosb = (const float*)d_in[2];
    const float* sinb = (const float*)d_in[3];
    const float* Wq   = (const float*)d_in[4];
    const float* bq   = (const float*)d_in[5];
    const float* Wk   = (const float*)d_in[6];
    const float* bk   = (const float*)d_in[7];
    const float* Wv   = (const float*)d_in[8];
    const float* bv   = (const float*)d_in[9];
    const float* Wo   = (const float*)d_in[10];
    const float* bo   = (const float*)d_in[11];
    float* out = (float*)d_out;

    cudaFuncSetAttribute(hgemm,
                         cudaFuncAttributeMaxDynamicSharedMemorySize, GEMM_SMEM);
    cudaFuncSetAttribute(attn_hmma,
                         cudaFuncAttributeMaxDynamicSharedMemorySize, ATT2_SMEM);

    cvt_all<<<(M_ * K_ + 4 * H_ * K_) / 1024, 256>>>(x, Wq, Wk, Wv, Wo);

    dim3 gqkv(H_ / 128, M_ / 128, 3);
    hgemm<<<gqkv, 256, GEMM_SMEM>>>(bq, bk, bv, nullptr, cosb, sinb, -1);

    dim3 ag(S_ / 128, B_ * NH_);
    attn_hmma<<<ag, 256, ATT2_SMEM>>>(mask);

    dim3 gg(H_ / 128, M_ / 128);
    hgemm<<<gg, 256, GEMM_SMEM>>>(bo, bo, bo, out, cosb, sinb, 3);
}

// round 14
// speedup vs baseline: 1.2608x; 1.0414x over previous
#include <cuda_runtime.h>
#include <cuda_bf16.h>
#include <cuda_fp16.h>
#include <math.h>
#include <stdint.h>

// Problem constants
constexpr int B_  = 2;
constexpr int S_  = 2048;
constexpr int H_  = 1024;
constexpr int NH_ = 16;
constexpr int HD_ = 64;
constexpr int M_  = B_ * S_;   // 4096
constexpr int K_  = H_;        // 1024

// split-trick constants (s = 256):  C = (1-1/s)*Xh*Yh + (Xh+s*Xl)*(Yh/s+Yl)
constexpr float SPLIT_S = 256.0f;
constexpr float INV_S   = 1.0f / 256.0f;
constexpr float C1_     = 1.0f - INV_S;        // exact in fp32
constexpr float INV_C1  = 256.0f / 255.0f;

// ---------------- scratch (device globals; no allocation allowed) ----------
// All operands fp16 (hi, mixed') pairs.
// A-side mixed: Xh + s*Xl.  B-side mixed: Yh/s + Yl.
__device__ __align__(16) __half g_qh[(size_t)B_ * NH_ * S_ * HD_];   // A-side (QK)
__device__ __align__(16) __half g_qp[(size_t)B_ * NH_ * S_ * HD_];
__device__ __align__(16) __half g_kh[(size_t)B_ * NH_ * S_ * HD_];   // B-side (QK)
__device__ __align__(16) __half g_kp[(size_t)B_ * NH_ * S_ * HD_];
__device__ __align__(16) __half g_vh[(size_t)B_ * NH_ * HD_ * S_];   // B-side (PV)
__device__ __align__(16) __half g_vp[(size_t)B_ * NH_ * HD_ * S_];

__device__ __align__(16) __half g_xh[(size_t)M_ * K_];               // A-side
__device__ __align__(16) __half g_xp[(size_t)M_ * K_];
__device__ __align__(16) __half g_wh[4][(size_t)H_ * K_];            // B-side
__device__ __align__(16) __half g_wp[4][(size_t)H_ * K_];
__device__ __align__(16) __half g_ah[(size_t)M_ * H_];               // A-side (O-proj)
__device__ __align__(16) __half g_ap[(size_t)M_ * H_];

// ---------------- PTX helpers ----------------------------------------------
__device__ __forceinline__ uint32_t smem_u32(const void* p) {
    uint32_t a;
    asm("{ .reg .u64 t; cvta.to.shared.u64 t, %1; cvt.u32.u64 %0, t; }"
        : "=r"(a) : "l"(p));
    return a;
}

#define CPA16(dst, src) \
    asm volatile("cp.async.ca.shared.global [%0], [%1], 16;" \
                 :: "r"(dst), "l"(src) : "memory")
#define CP_COMMIT() asm volatile("cp.async.commit_group;" ::: "memory")
#define CP_WAIT(n)  asm volatile("cp.async.wait_group %0;" :: "n"(n) : "memory")

#define LDSM4(r, addr) \
    asm volatile("ldmatrix.sync.aligned.m8n8.x4.shared.b16 {%0,%1,%2,%3}, [%4];" \
                 : "=r"((r)[0]), "=r"((r)[1]), "=r"((r)[2]), "=r"((r)[3])        \
                 : "r"(addr))

#define MMAF16(c, a, b) \
    asm volatile("mma.sync.aligned.m16n8k16.row.col.f32.f16.f16.f32 "            \
                 "{%0,%1,%2,%3}, {%4,%5,%6,%7}, {%8,%9}, {%0,%1,%2,%3};"         \
                 : "+f"((c)[0]), "+f"((c)[1]), "+f"((c)[2]), "+f"((c)[3])        \
                 : "r"((a)[0]), "r"((a)[1]), "r"((a)[2]), "r"((a)[3]),           \
                   "r"((b)[0]), "r"((b)[1]))

__device__ __forceinline__ uint32_t h2pack(float a, float b) {
    __half2 t = __floats2half2_rn(a, b);
    return *(uint32_t*)&t;
}

// ---------------------------------------------------------------------------
// fp32 -> fp16 (hi, mixed') split, all 5 inputs in one launch.
// x -> A-side; weights -> B-side.
// ---------------------------------------------------------------------------
__global__ void __launch_bounds__(256) cvt_all(const float* __restrict__ x,
                                               const float* __restrict__ wq,
                                               const float* __restrict__ wk,
                                               const float* __restrict__ wv,
                                               const float* __restrict__ wo)
{
    int i = (blockIdx.x * blockDim.x + threadIdx.x) * 4;
    const float* s;
    __half *dh, *dp;
    int off;
    bool aside;
    if (i < M_ * K_) {
        s = x; dh = g_xh; dp = g_xp; off = i; aside = true;
    } else {
        const int j = i - M_ * K_;
        const int r = j >> 20;
        off = j & (H_ * K_ - 1);
        s = (r == 0) ? wq : (r == 1) ? wk : (r == 2) ? wv : wo;
        dh = g_wh[r]; dp = g_wp[r]; aside = false;
    }

    float4 v = *(const float4*)(s + off);
    float vv[4] = {v.x, v.y, v.z, v.w};
    float hh[4], pp[4];
#pragma unroll
    for (int j = 0; j < 4; j++) {
        hh[j] = __half2float(__float2half_rn(vv[j]));
        const float r = vv[j] - hh[j];
        pp[j] = aside ? (hh[j] + SPLIT_S * r) : (hh[j] * INV_S + r);
    }
    *(uint32_t*)&dh[off]     = h2pack(hh[0], hh[1]);
    *(uint32_t*)&dh[off + 2] = h2pack(hh[2], hh[3]);
    *(uint32_t*)&dp[off]     = h2pack(pp[0], pp[1]);
    *(uint32_t*)&dp[off + 2] = h2pack(pp[2], pp[3]);
}

// ---------------------------------------------------------------------------
// fp16 2-MMA GEMM: C = C1*sum(Ah*Wh) + sum(A'*W').
// Two-phase K sweep (64 chunk-iterations; arrays switch at 32, acc*=C1 at the
// boundary). CTA 128x128, BK=32, 256 thr (8 warps), warp tile 64x32,
// cp.async double buffer, single barrier per chunk, 2 CTAs/SM.
// ---------------------------------------------------------------------------
constexpr int LDS_B  = 80;
constexpr int ASZ    = 128 * LDS_B;    // 10240 per operand array
constexpr int STAGE2 = 2 * ASZ;        // A + W
constexpr int GEMM_SMEM = 128 * 132 * 4;  // 67584 (epilogue dominates; 2*STAGE2=40960)

__global__ void __launch_bounds__(256, 2) hgemm(const float* __restrict__ bias0,
                                                const float* __restrict__ bias1,
                                                const float* __restrict__ bias2,
                                                float* __restrict__ Cext,
                                                const float* __restrict__ cosb,
                                                const float* __restrict__ sinb,
                                                int fixed_mode)
{
    extern __shared__ char sm[];
    const int mode = (fixed_mode >= 0) ? fixed_mode : (int)blockIdx.z;
    const float* bias = (mode == 1) ? bias1 : (mode == 2) ? bias2 : bias0;

    const int tid  = threadIdx.x;
    const int lane = tid & 31;
    const int wid  = tid >> 5;
    const int wm   = (wid >> 2) * 64;
    const int wn   = (wid & 3) * 32;
    const int n0 = blockIdx.x * 128, m0 = blockIdx.y * 128;

    const __half* Ahp = (mode == 3) ? g_ah : g_xh;
    const __half* App = (mode == 3) ? g_ap : g_xp;
    const __half* Whp = g_wh[mode];
    const __half* Wpp = g_wp[mode];

    const uint32_t sbase = smem_u32(sm);

    const int lr = tid >> 1;
    const size_t gA = (size_t)(m0 + lr) * K_ + (tid & 1) * 16;
    const size_t gW = (size_t)(n0 + lr) * K_ + (tid & 1) * 16;
    const uint32_t srow = (uint32_t)(lr * LDS_B + (tid & 1) * 32);

    float acc[4][4][4];
#pragma unroll
    for (int a = 0; a < 4; a++)
#pragma unroll
        for (int b = 0; b < 4; b++)
#pragma unroll
            for (int c = 0; c < 4; c++) acc[a][b][c] = 0.0f;

#define LOAD_CHUNK2(cq) do {                                                  \
    const __half* pa_ = ((cq) & 32) ? App : Ahp;                              \
    const __half* pw_ = ((cq) & 32) ? Wpp : Whp;                              \
    const int k0_ = ((cq) & 31) * 32;                                         \
    const uint32_t st = sbase + ((cq) & 1) * STAGE2 + srow;                   \
    const char* pa = (const char*)(pa_ + gA + k0_);                           \
    const char* pw = (const char*)(pw_ + gW + k0_);                           \
    CPA16(st,        pa); CPA16(st + 16,        pa + 16);                     \
    CPA16(st + ASZ,  pw); CPA16(st + ASZ + 16,  pw + 16);                     \
    CP_COMMIT();                                                              \
} while (0)

    LOAD_CHUNK2(0);

    for (int cq = 0; cq < 64; cq++) {
        CP_WAIT(0);
        __syncthreads();
        if (cq < 63) LOAD_CHUNK2(cq + 1);

        const uint32_t stg = sbase + (cq & 1) * STAGE2;
#pragma unroll
        for (int ks = 0; ks < 2; ks++) {
            const int kb = ks * 32;
            uint32_t bF[4][2];
#pragma unroll
            for (int nh = 0; nh < 2; nh++) {
                const uint32_t bd = stg + ASZ
                    + (uint32_t)((wn + nh * 16 + ((lane >> 4) << 3) + (lane & 7)) * LDS_B
                                 + kb + (((lane >> 3) & 1) << 4));
                uint32_t r[4];
                LDSM4(r, bd);
                bF[nh * 2][0] = r[0]; bF[nh * 2][1] = r[1];
                bF[nh * 2 + 1][0] = r[2]; bF[nh * 2 + 1][1] = r[3];
            }
#pragma unroll
            for (int mi = 0; mi < 4; mi++) {
                uint32_t aF[4];
                const uint32_t ad = stg + (uint32_t)((wm + mi * 16 + (lane & 15)) * LDS_B
                                                     + kb + ((lane >> 4) << 4));
                LDSM4(aF, ad);
#pragma unroll
                for (int ni = 0; ni < 4; ni++) MMAF16(acc[mi][ni], aF, bF[ni]);
            }
        }
        if (cq == 31) {     // phase boundary: C1 * sum(M1)
#pragma unroll
            for (int a = 0; a < 4; a++)
#pragma unroll
                for (int b = 0; b < 4; b++)
#pragma unroll
                    for (int c = 0; c < 4; c++) acc[a][b][c] *= C1_;
        }
    }
    __syncthreads();

    // ---- epilogue: stage C tile in smem, then fused writeout
    constexpr int LDC = 132;
    float* Csm = (float*)sm;
#pragma unroll
    for (int mi = 0; mi < 4; mi++) {
        const int row = wm + mi * 16 + (lane >> 2);
#pragma unroll
        for (int ni = 0; ni < 4; ni++) {
            const int col = wn + ni * 8 + (lane & 3) * 2;
            *(float2*)&Csm[row * LDC + col] =
                make_float2(acc[mi][ni][0], acc[mi][ni][1]);
            *(float2*)&Csm[(row + 8) * LDC + col] =
                make_float2(acc[mi][ni][2], acc[mi][ni][3]);
        }
    }
    __syncthreads();

    if (mode <= 1) {
        // RoPE + fp16 (hi, mixed') pairs -> [b,h,s,d]
        __half* Ch = (mode == 0) ? g_qh : g_kh;
        __half* Cp = (mode == 0) ? g_qp : g_kp;
        const bool isq = (mode == 0);     // Q: A-side, K: B-side
#pragma unroll 2
        for (int i = 0; i < 16; i++) {
            const int id  = tid + 256 * i;
            const int dp  = id & 15;
            const int hh  = (id >> 4) & 1;
            const int row = id >> 5;
            const int d0  = dp * 2;
            const int m   = m0 + row;
            const int s   = m & (S_ - 1);
            const int bb  = m >> 11;
            float oA[2], oB[2];
#pragma unroll
            for (int e = 0; e < 2; e++) {
                const int d = d0 + e, c = hh * 64 + d;
                const float v0 = Csm[row * LDC + c]      + bias[n0 + c];
                const float v1 = Csm[row * LDC + c + 32] + bias[n0 + c + 32];
                const float cs0 = cosb[s * HD_ + d],      sn0 = sinb[s * HD_ + d];
                const float cs1 = cosb[s * HD_ + d + 32], sn1 = sinb[s * HD_ + d + 32];
                oA[e] = v0 * cs0 - v1 * sn0;
                oB[e] = v1 * cs1 + v0 * sn1;
            }
            const int hidx = (n0 >> 6) + hh;
            const size_t base = ((size_t)(bb * NH_ + hidx) * S_ + s) * HD_;
            float hA[2], hB[2], pA[2], pB[2];
#pragma unroll
            for (int e = 0; e < 2; e++) {
                hA[e] = __half2float(__float2half_rn(oA[e]));
                hB[e] = __half2float(__float2half_rn(oB[e]));
                const float rA = oA[e] - hA[e], rB = oB[e] - hB[e];
                if (isq) { pA[e] = hA[e] + SPLIT_S * rA; pB[e] = hB[e] + SPLIT_S * rB; }
                else     { pA[e] = hA[e] * INV_S + rA;   pB[e] = hB[e] * INV_S + rB; }
            }
            *(uint32_t*)&Ch[base + d0]      = h2pack(hA[0], hA[1]);
            *(uint32_t*)&Ch[base + d0 + 32] = h2pack(hB[0], hB[1]);
            *(uint32_t*)&Cp[base + d0]      = h2pack(pA[0], pA[1]);
            *(uint32_t*)&Cp[base + d0 + 32] = h2pack(pB[0], pB[1]);
        }
    } else if (mode == 2) {
        // V: fp16 (Vh, Vh/s + Vl) B-side -> [b,h,d,s]
#pragma unroll 2
        for (int i = 0; i < 32; i++) {
            const int id  = tid + 256 * i;
            const int sp  = id & 63;
            const int c   = id >> 6;
            const int row0 = sp * 2;
            const int m   = m0 + row0;
            const int s   = m & (S_ - 1);
            const int bb  = m >> 11;
            const int n   = n0 + c;
            const int hidx = n >> 6, d = n & 63;
            const float v0 = Csm[row0 * LDC + c]       + bias[n];
            const float v1 = Csm[(row0 + 1) * LDC + c] + bias[n];
            const float h0 = __half2float(__float2half_rn(v0));
            const float h1 = __half2float(__float2half_rn(v1));
            const size_t o = ((size_t)(bb * NH_ + hidx) * HD_ + d) * S_ + s;
            *(uint32_t*)&g_vh[o] = h2pack(h0, h1);
            *(uint32_t*)&g_vp[o] = h2pack(h0 * INV_S + (v0 - h0),
                                          h1 * INV_S + (v1 - h1));
        }
    } else {
#pragma unroll 4
        for (int i = 0; i < 16; i++) {
            const int id  = tid + 256 * i;
            const int c4  = (id & 31) * 4;
            const int row = id >> 5;
            const int m   = m0 + row;
            const int n   = n0 + c4;
            float4 v;
            v.x = Csm[row * LDC + c4 + 0] + bias[n + 0];
            v.y = Csm[row * LDC + c4 + 1] + bias[n + 1];
            v.z = Csm[row * LDC + c4 + 2] + bias[n + 2];
            v.w = Csm[row * LDC + c4 + 3] + bias[n + 3];
            *(float4*)&Cext[(size_t)m * H_ + n] = v;
        }
    }
}

// ---------------------------------------------------------------------------
// Flash attention, fp16 2-MMA exact-split scheme (round-13 winner).
// Epilogue now writes fp16 A-side pairs for the O-projection.
// ---------------------------------------------------------------------------
constexpr int LDSA     = 144;
constexpr int QBYTES   = 2 * 128 * LDSA;        // 36864 (Qh | Q')
constexpr int KVSTAGE  = 4 * 64 * LDSA;         // 36864 (Kh|K'|Vh|V')
constexpr int ATT2_SMEM = QBYTES + 3 * KVSTAGE; // 147456

__global__ void __launch_bounds__(256) attn_hmma(const int* __restrict__ mask)
{
    extern __shared__ char sm[];
    const uint32_t sb = smem_u32(sm);
    __shared__ int msk[3][64];

    const int tid = threadIdx.x, lane = tid & 31, w = tid >> 5;
    const int bh = blockIdx.y, b = bh >> 4, h = bh & 15;
    const int q0 = blockIdx.x * 128;

    const __half* Qhp = g_qh + (size_t)bh * S_ * HD_;
    const __half* Qpp = g_qp + (size_t)bh * S_ * HD_;
    const __half* Khp = g_kh + (size_t)bh * S_ * HD_;
    const __half* Kpp = g_kp + (size_t)bh * S_ * HD_;
    const __half* Vhp = g_vh + (size_t)bh * HD_ * S_;
    const __half* Vpp = g_vp + (size_t)bh * HD_ * S_;
    const int* maskp = mask + b * S_;

#pragma unroll
    for (int i = 0; i < 4; i++) {
        const int idx = tid + 256 * i;
        const int row = idx >> 3, chk = idx & 7;
        const uint32_t dst = sb + (uint32_t)(row * LDSA + chk * 16);
        CPA16(dst,         (const char*)(Qhp + (size_t)(q0 + row) * HD_ + chk * 8));
        CPA16(dst + 18432, (const char*)(Qpp + (size_t)(q0 + row) * HD_ + chk * 8));
    }

#define LOADKV(t) do {                                                          \
    const int kt_ = (t) * 64;                                                   \
    const uint32_t st = sb + QBYTES + ((t) % 3) * KVSTAGE;                      \
    _Pragma("unroll")                                                           \
    for (int i_ = 0; i_ < 2; i_++) {                                            \
        const int idx_ = tid + 256 * i_;                                        \
        const int row_ = idx_ >> 3, ch_ = idx_ & 7;                             \
        const uint32_t ro_ = (uint32_t)(row_ * LDSA + ch_ * 16);                \
        CPA16(st + ro_,          (const char*)(Khp + (size_t)(kt_ + row_) * HD_ + ch_ * 8)); \
        CPA16(st + 9216 + ro_,   (const char*)(Kpp + (size_t)(kt_ + row_) * HD_ + ch_ * 8)); \
        CPA16(st + 18432 + ro_,  (const char*)(Vhp + (size_t)row_ * S_ + kt_ + ch_ * 8));    \
        CPA16(st + 27648 + ro_,  (const char*)(Vpp + (size_t)row_ * S_ + kt_ + ch_ * 8));    \
    }                                                                           \
    if (tid < 64) msk[(t) % 3][tid] = maskp[kt_ + tid];                         \
    CP_COMMIT();                                                                \
} while (0)

    LOADKV(0);
    LOADKV(1);

    float m_[2] = {-1e30f, -1e30f}, l_[2] = {0.0f, 0.0f};
    float oacc[8][4];
#pragma unroll
    for (int n = 0; n < 8; n++)
#pragma unroll
        for (int j = 0; j < 4; j++) oacc[n][j] = 0.0f;

    uint32_t qfh[4][4], qfp[4][4];
    const int c01 = (lane & 3) * 2;
    constexpr int NT = S_ / 64;

    for (int t = 0; t < NT; t++) {
        if (t >= NT - 2) { CP_WAIT(0); }
        else             { CP_WAIT(1); }
        __syncthreads();
        if (t + 2 < NT) LOADKV(t + 2);

        if (t == 0) {
#pragma unroll
            for (int kk = 0; kk < 4; kk++) {
                const uint32_t ad = sb + (uint32_t)((w * 16 + (lane & 15)) * LDSA
                                                    + kk * 32 + ((lane >> 4) << 4));
                LDSM4(qfh[kk], ad);
                LDSM4(qfp[kk], ad + 18432);
            }
        }

        const uint32_t kst = sb + QBYTES + (t % 3) * KVSTAGE;

        // ---- S: pass1 M1 = Qh*Kh ----
        float sacc[8][4];
#pragma unroll
        for (int n = 0; n < 8; n++)
#pragma unroll
            for (int j = 0; j < 4; j++) sacc[n][j] = 0.0f;

#pragma unroll
        for (int kk = 0; kk < 4; kk++) {
            uint32_t rh[4][4];
#pragma unroll
            for (int nh = 0; nh < 4; nh++) {
                const uint32_t bd = kst
                    + (uint32_t)((nh * 16 + ((lane >> 4) << 3) + (lane & 7)) * LDSA
                                 + kk * 32 + (((lane >> 3) & 1) << 4));
                LDSM4(rh[nh], bd);
            }
#pragma unroll
            for (int nh = 0; nh < 4; nh++) {
                uint32_t b0[2] = {rh[nh][0], rh[nh][1]}, b1[2] = {rh[nh][2], rh[nh][3]};
                MMAF16(sacc[nh * 2],     qfh[kk], b0);
                MMAF16(sacc[nh * 2 + 1], qfh[kk], b1);
            }
        }
#pragma unroll
        for (int n = 0; n < 8; n++)
#pragma unroll
            for (int j = 0; j < 4; j++) sacc[n][j] *= C1_;
        // ---- S: pass2 M2 = Q'*K' ----
#pragma unroll
        for (int kk = 0; kk < 4; kk++) {
            uint32_t rp[4][4];
#pragma unroll
            for (int nh = 0; nh < 4; nh++) {
                const uint32_t bd = kst + 9216
                    + (uint32_t)((nh * 16 + ((lane >> 4) << 3) + (lane & 7)) * LDSA
                                 + kk * 32 + (((lane >> 3) & 1) << 4));
                LDSM4(rp[nh], bd);
            }
#pragma unroll
            for (int nh = 0; nh < 4; nh++) {
                uint32_t b0[2] = {rp[nh][0], rp[nh][1]}, b1[2] = {rp[nh][2], rp[nh][3]};
                MMAF16(sacc[nh * 2],     qfp[kk], b0);
                MMAF16(sacc[nh * 2 + 1], qfp[kk], b1);
            }
        }

        // ---- scale + mask + online softmax ----
        float mx[2] = {-1e30f, -1e30f};
#pragma unroll
        for (int n = 0; n < 8; n++) {
            const int cc = n * 8 + c01;
            const int mk0 = msk[t % 3][cc], mk1 = msk[t % 3][cc + 1];
#pragma unroll
            for (int j = 0; j < 4; j++) {
                float v = sacc[n][j] * 0.125f;
                v = ((j & 1) ? mk1 : mk0) ? v : -1e30f;
                sacc[n][j] = v;
                mx[j >> 1] = fmaxf(mx[j >> 1], v);
            }
        }
        float corr[2], rs[2] = {0.0f, 0.0f};
#pragma unroll
        for (int r = 0; r < 2; r++) {
            mx[r] = fmaxf(mx[r], __shfl_xor_sync(0xffffffffu, mx[r], 1, 4));
            mx[r] = fmaxf(mx[r], __shfl_xor_sync(0xffffffffu, mx[r], 2, 4));
            const float mn = fmaxf(m_[r], mx[r]);
            corr[r] = __expf(m_[r] - mn);
            m_[r] = mn;
        }
#pragma unroll
        for (int n = 0; n < 8; n++)
#pragma unroll
            for (int j = 0; j < 4; j++) {
                const float p = __expf(sacc[n][j] - m_[j >> 1]);
                sacc[n][j] = p;
                rs[j >> 1] += p;
            }
#pragma unroll
        for (int r = 0; r < 2; r++) {
            rs[r] += __shfl_xor_sync(0xffffffffu, rs[r], 1, 4);
            rs[r] += __shfl_xor_sync(0xffffffffu, rs[r], 2, 4);
            l_[r] = l_[r] * corr[r] + rs[r];
        }
#pragma unroll
        for (int n = 0; n < 8; n++)
#pragma unroll
            for (int j = 0; j < 4; j++) oacc[n][j] *= corr[j >> 1] * INV_C1;

        // ---- O: pass1 M1 = Ph*Vh ----
#pragma unroll
        for (int j = 0; j < 4; j++) {
            uint32_t aPh[4];
#pragma unroll
            for (int half = 0; half < 2; half++) {
                aPh[half * 2]     = h2pack(sacc[2 * j + half][0], sacc[2 * j + half][1]);
                aPh[half * 2 + 1] = h2pack(sacc[2 * j + half][2], sacc[2 * j + half][3]);
            }
            uint32_t rh[4][4];
#pragma unroll
            for (int nh = 0; nh < 4; nh++) {
                const uint32_t bd = kst + 18432
                    + (uint32_t)((nh * 16 + ((lane >> 4) << 3) + (lane & 7)) * LDSA
                                 + j * 32 + (((lane >> 3) & 1) << 4));
                LDSM4(rh[nh], bd);
            }
#pragma unroll
            for (int nh = 0; nh < 4; nh++) {
                uint32_t b0[2] = {rh[nh][0], rh[nh][1]}, b1[2] = {rh[nh][2], rh[nh][3]};
                MMAF16(oacc[nh * 2],     aPh, b0);
                MMAF16(oacc[nh * 2 + 1], aPh, b1);
            }
        }
#pragma unroll
        for (int n = 0; n < 8; n++)
#pragma unroll
            for (int j = 0; j < 4; j++) oacc[n][j] *= C1_;
        // ---- O: pass2 M2 = P'*V' ----
#pragma unroll
        for (int j = 0; j < 4; j++) {
            uint32_t aPp[4];
#pragma unroll
            for (int half = 0; half < 2; half++) {
                float pv[4];
#pragma unroll
                for (int e = 0; e < 4; e++) {
                    const float p = sacc[2 * j + half][e];
                    const float ph = __half2float(__float2half_rn(p));
                    pv[e] = ph + SPLIT_S * (p - ph);
                }
                aPp[half * 2]     = h2pack(pv[0], pv[1]);
                aPp[half * 2 + 1] = h2pack(pv[2], pv[3]);
            }
            uint32_t rp[4][4];
#pragma unroll
            for (int nh = 0; nh < 4; nh++) {
                const uint32_t bd = kst + 27648
                    + (uint32_t)((nh * 16 + ((lane >> 4) << 3) + (lane & 7)) * LDSA
                                 + j * 32 + (((lane >> 3) & 1) << 4));
                LDSM4(rp[nh], bd);
            }
#pragma unroll
            for (int nh = 0; nh < 4; nh++) {
                uint32_t b0[2] = {rp[nh][0], rp[nh][1]}, b1[2] = {rp[nh][2], rp[nh][3]};
                MMAF16(oacc[nh * 2],     aPp, b0);
                MMAF16(oacc[nh * 2 + 1], aPp, b1);
            }
        }
    }

    // ---- epilogue: /l, write fp16 A-side pairs to g_ah/g_ap [M,H] ----
    const int r0 = lane >> 2;
#pragma unroll
    for (int r = 0; r < 2; r++) {
        const float inv = 1.0f / l_[r];
        const int srow = q0 + w * 16 + r0 + 8 * r;
        const size_t base = ((size_t)b * S_ + srow) * H_ + h * 64 + c01;
#pragma unroll
        for (int n = 0; n < 8; n++) {
            const float v0 = oacc[n][2 * r]     * inv;
            const float v1 = oacc[n][2 * r + 1] * inv;
            const float h0 = __half2float(__float2half_rn(v0));
            const float h1 = __half2float(__float2half_rn(v1));
            *(uint32_t*)&g_ah[base + n * 8] = h2pack(h0, h1);
            *(uint32_t*)&g_ap[base + n * 8] = h2pack(h0 + SPLIT_S * (v0 - h0),
                                                     h1 + SPLIT_S * (v1 - h1));
        }
    }
}

// ---------------------------------------------------------------------------
extern "C" void kernel_launch(void* const* d_in, const int* in_sizes, int n_in,
                              void* d_out, int out_size)
{
    const float* x    = (const float*)d_in[0];
    const int*   mask = (const int*)  d_in[1];
    const float* cosb = (const float*)d_in[2];
    const float* sinb = (const float*)d_in[3];
    const float* Wq   = (const float*)d_in[4];
    const float* bq   = (const float*)d_in[5];
    const float* Wk   = (const float*)d_in[6];
    const float* bk   = (const float*)d_in[7];
    const float* Wv   = (const float*)d_in[8];
    const float* bv   = (const float*)d_in[9];
    const float* Wo   = (const float*)d_in[10];
    const float* bo   = (const float*)d_in[11];
    float* out = (float*)d_out;

    cudaFuncSetAttribute(hgemm,
                         cudaFuncAttributeMaxDynamicSharedMemorySize, GEMM_SMEM);
    cudaFuncSetAttribute(attn_hmma,
                         cudaFuncAttributeMaxDynamicSharedMemorySize, ATT2_SMEM);

    cvt_all<<<(M_ * K_ + 4 * H_ * K_) / 1024, 256>>>(x, Wq, Wk, Wv, Wo);

    dim3 gqkv(H_ / 128, M_ / 128, 3);
    hgemm<<<gqkv, 256, GEMM_SMEM>>>(bq, bk, bv, nullptr, cosb, sinb, -1);

    dim3 ag(S_ / 128, B_ * NH_);
    attn_hmma<<<ag, 256, ATT2_SMEM>>>(mask);

    dim3 gg(H_ / 128, M_ / 128);
    hgemm<<<gg, 256, GEMM_SMEM>>>(bo, bo, bo, out, cosb, sinb, 3);
}

// round 15
// speedup vs baseline: 1.3920x; 1.1041x over previous
#include <cuda_runtime.h>
#include <cuda_bf16.h>
#include <cuda_fp16.h>
#include <math.h>
#include <stdint.h>

// Problem constants
constexpr int B_  = 2;
constexpr int S_  = 2048;
constexpr int H_  = 1024;
constexpr int NH_ = 16;
constexpr int HD_ = 64;
constexpr int M_  = B_ * S_;   // 4096
constexpr int K_  = H_;        // 1024

// split-trick constants (s = 256):  C = (1-1/s)*Xh*Yh + (Xh+s*Xl)*(Yh/s+Yl)
constexpr float SPLIT_S = 256.0f;
constexpr float INV_S   = 1.0f / 256.0f;
constexpr float C1_     = 1.0f - INV_S;        // exact in fp32
constexpr float INV_C1  = 256.0f / 255.0f;

// ---------------- scratch (device globals; no allocation allowed) ----------
__device__ __align__(16) __half g_qh[(size_t)B_ * NH_ * S_ * HD_];   // A-side (QK)
__device__ __align__(16) __half g_qp[(size_t)B_ * NH_ * S_ * HD_];
__device__ __align__(16) __half g_kh[(size_t)B_ * NH_ * S_ * HD_];   // B-side (QK)
__device__ __align__(16) __half g_kp[(size_t)B_ * NH_ * S_ * HD_];
__device__ __align__(16) __half g_vh[(size_t)B_ * NH_ * HD_ * S_];   // B-side (PV)
__device__ __align__(16) __half g_vp[(size_t)B_ * NH_ * HD_ * S_];

__device__ __align__(16) __half g_xh[(size_t)M_ * K_];               // A-side
__device__ __align__(16) __half g_xp[(size_t)M_ * K_];
__device__ __align__(16) __half g_wh[4][(size_t)H_ * K_];            // B-side
__device__ __align__(16) __half g_wp[4][(size_t)H_ * K_];
__device__ __align__(16) __half g_ah[(size_t)M_ * H_];               // A-side (O-proj)
__device__ __align__(16) __half g_ap[(size_t)M_ * H_];

// ---------------- PTX helpers ----------------------------------------------
__device__ __forceinline__ uint32_t smem_u32(const void* p) {
    uint32_t a;
    asm("{ .reg .u64 t; cvta.to.shared.u64 t, %1; cvt.u32.u64 %0, t; }"
        : "=r"(a) : "l"(p));
    return a;
}

#define CPA16(dst, src) \
    asm volatile("cp.async.ca.shared.global [%0], [%1], 16;" \
                 :: "r"(dst), "l"(src) : "memory")
#define CP_COMMIT() asm volatile("cp.async.commit_group;" ::: "memory")
#define CP_WAIT(n)  asm volatile("cp.async.wait_group %0;" :: "n"(n) : "memory")

#define LDSM4(r, addr) \
    asm volatile("ldmatrix.sync.aligned.m8n8.x4.shared.b16 {%0,%1,%2,%3}, [%4];" \
                 : "=r"((r)[0]), "=r"((r)[1]), "=r"((r)[2]), "=r"((r)[3])        \
                 : "r"(addr))

#define MMAF16(c, a, b) \
    asm volatile("mma.sync.aligned.m16n8k16.row.col.f32.f16.f16.f32 "            \
                 "{%0,%1,%2,%3}, {%4,%5,%6,%7}, {%8,%9}, {%0,%1,%2,%3};"         \
                 : "+f"((c)[0]), "+f"((c)[1]), "+f"((c)[2]), "+f"((c)[3])        \
                 : "r"((a)[0]), "r"((a)[1]), "r"((a)[2]), "r"((a)[3]),           \
                   "r"((b)[0]), "r"((b)[1]))

__device__ __forceinline__ uint32_t h2pack(float a, float b) {
    __half2 t = __floats2half2_rn(a, b);
    return *(uint32_t*)&t;
}

// ---------------------------------------------------------------------------
// fp32 -> fp16 (hi, mixed') split, all 5 inputs in one launch.
// ---------------------------------------------------------------------------
__global__ void __launch_bounds__(256) cvt_all(const float* __restrict__ x,
                                               const float* __restrict__ wq,
                                               const float* __restrict__ wk,
                                               const float* __restrict__ wv,
                                               const float* __restrict__ wo)
{
    int i = (blockIdx.x * blockDim.x + threadIdx.x) * 4;
    const float* s;
    __half *dh, *dp;
    int off;
    bool aside;
    if (i < M_ * K_) {
        s = x; dh = g_xh; dp = g_xp; off = i; aside = true;
    } else {
        const int j = i - M_ * K_;
        const int r = j >> 20;
        off = j & (H_ * K_ - 1);
        s = (r == 0) ? wq : (r == 1) ? wk : (r == 2) ? wv : wo;
        dh = g_wh[r]; dp = g_wp[r]; aside = false;
    }

    float4 v = *(const float4*)(s + off);
    float vv[4] = {v.x, v.y, v.z, v.w};
    float hh[4], pp[4];
#pragma unroll
    for (int j = 0; j < 4; j++) {
        hh[j] = __half2float(__float2half_rn(vv[j]));
        const float r = vv[j] - hh[j];
        pp[j] = aside ? (hh[j] + SPLIT_S * r) : (hh[j] * INV_S + r);
    }
    *(uint32_t*)&dh[off]     = h2pack(hh[0], hh[1]);
    *(uint32_t*)&dh[off + 2] = h2pack(hh[2], hh[3]);
    *(uint32_t*)&dp[off]     = h2pack(pp[0], pp[1]);
    *(uint32_t*)&dp[off + 2] = h2pack(pp[2], pp[3]);
}

// ---------------------------------------------------------------------------
// fp16 2-MMA GEMM (round-14 winner, unchanged).
// ---------------------------------------------------------------------------
constexpr int LDS_B  = 80;
constexpr int ASZ    = 128 * LDS_B;    // 10240 per operand array
constexpr int STAGE2 = 2 * ASZ;        // A + W
constexpr int GEMM_SMEM = 128 * 132 * 4;  // 67584

__global__ void __launch_bounds__(256, 2) hgemm(const float* __restrict__ bias0,
                                                const float* __restrict__ bias1,
                                                const float* __restrict__ bias2,
                                                float* __restrict__ Cext,
                                                const float* __restrict__ cosb,
                                                const float* __restrict__ sinb,
                                                int fixed_mode)
{
    extern __shared__ char sm[];
    const int mode = (fixed_mode >= 0) ? fixed_mode : (int)blockIdx.z;
    const float* bias = (mode == 1) ? bias1 : (mode == 2) ? bias2 : bias0;

    const int tid  = threadIdx.x;
    const int lane = tid & 31;
    const int wid  = tid >> 5;
    const int wm   = (wid >> 2) * 64;
    const int wn   = (wid & 3) * 32;
    const int n0 = blockIdx.x * 128, m0 = blockIdx.y * 128;

    const __half* Ahp = (mode == 3) ? g_ah : g_xh;
    const __half* App = (mode == 3) ? g_ap : g_xp;
    const __half* Whp = g_wh[mode];
    const __half* Wpp = g_wp[mode];

    const uint32_t sbase = smem_u32(sm);

    const int lr = tid >> 1;
    const size_t gA = (size_t)(m0 + lr) * K_ + (tid & 1) * 16;
    const size_t gW = (size_t)(n0 + lr) * K_ + (tid & 1) * 16;
    const uint32_t srow = (uint32_t)(lr * LDS_B + (tid & 1) * 32);

    float acc[4][4][4];
#pragma unroll
    for (int a = 0; a < 4; a++)
#pragma unroll
        for (int b = 0; b < 4; b++)
#pragma unroll
            for (int c = 0; c < 4; c++) acc[a][b][c] = 0.0f;

#define LOAD_CHUNK2(cq) do {                                                  \
    const __half* pa_ = ((cq) & 32) ? App : Ahp;                              \
    const __half* pw_ = ((cq) & 32) ? Wpp : Whp;                              \
    const int k0_ = ((cq) & 31) * 32;                                         \
    const uint32_t st = sbase + ((cq) & 1) * STAGE2 + srow;                   \
    const char* pa = (const char*)(pa_ + gA + k0_);                           \
    const char* pw = (const char*)(pw_ + gW + k0_);                           \
    CPA16(st,        pa); CPA16(st + 16,        pa + 16);                     \
    CPA16(st + ASZ,  pw); CPA16(st + ASZ + 16,  pw + 16);                     \
    CP_COMMIT();                                                              \
} while (0)

    LOAD_CHUNK2(0);

    for (int cq = 0; cq < 64; cq++) {
        CP_WAIT(0);
        __syncthreads();
        if (cq < 63) LOAD_CHUNK2(cq + 1);

        const uint32_t stg = sbase + (cq & 1) * STAGE2;
#pragma unroll
        for (int ks = 0; ks < 2; ks++) {
            const int kb = ks * 32;
            uint32_t bF[4][2];
#pragma unroll
            for (int nh = 0; nh < 2; nh++) {
                const uint32_t bd = stg + ASZ
                    + (uint32_t)((wn + nh * 16 + ((lane >> 4) << 3) + (lane & 7)) * LDS_B
                                 + kb + (((lane >> 3) & 1) << 4));
                uint32_t r[4];
                LDSM4(r, bd);
                bF[nh * 2][0] = r[0]; bF[nh * 2][1] = r[1];
                bF[nh * 2 + 1][0] = r[2]; bF[nh * 2 + 1][1] = r[3];
            }
#pragma unroll
            for (int mi = 0; mi < 4; mi++) {
                uint32_t aF[4];
                const uint32_t ad = stg + (uint32_t)((wm + mi * 16 + (lane & 15)) * LDS_B
                                                     + kb + ((lane >> 4) << 4));
                LDSM4(aF, ad);
#pragma unroll
                for (int ni = 0; ni < 4; ni++) MMAF16(acc[mi][ni], aF, bF[ni]);
            }
        }
        if (cq == 31) {
#pragma unroll
            for (int a = 0; a < 4; a++)
#pragma unroll
                for (int b = 0; b < 4; b++)
#pragma unroll
                    for (int c = 0; c < 4; c++) acc[a][b][c] *= C1_;
        }
    }
    __syncthreads();

    // ---- epilogue
    constexpr int LDC = 132;
    float* Csm = (float*)sm;
#pragma unroll
    for (int mi = 0; mi < 4; mi++) {
        const int row = wm + mi * 16 + (lane >> 2);
#pragma unroll
        for (int ni = 0; ni < 4; ni++) {
            const int col = wn + ni * 8 + (lane & 3) * 2;
            *(float2*)&Csm[row * LDC + col] =
                make_float2(acc[mi][ni][0], acc[mi][ni][1]);
            *(float2*)&Csm[(row + 8) * LDC + col] =
                make_float2(acc[mi][ni][2], acc[mi][ni][3]);
        }
    }
    __syncthreads();

    if (mode <= 1) {
        __half* Ch = (mode == 0) ? g_qh : g_kh;
        __half* Cp = (mode == 0) ? g_qp : g_kp;
        const bool isq = (mode == 0);
#pragma unroll 2
        for (int i = 0; i < 16; i++) {
            const int id  = tid + 256 * i;
            const int dp  = id & 15;
            const int hh  = (id >> 4) & 1;
            const int row = id >> 5;
            const int d0  = dp * 2;
            const int m   = m0 + row;
            const int s   = m & (S_ - 1);
            const int bb  = m >> 11;
            float oA[2], oB[2];
#pragma unroll
            for (int e = 0; e < 2; e++) {
                const int d = d0 + e, c = hh * 64 + d;
                const float v0 = Csm[row * LDC + c]      + bias[n0 + c];
                const float v1 = Csm[row * LDC + c + 32] + bias[n0 + c + 32];
                const float cs0 = cosb[s * HD_ + d],      sn0 = sinb[s * HD_ + d];
                const float cs1 = cosb[s * HD_ + d + 32], sn1 = sinb[s * HD_ + d + 32];
                oA[e] = v0 * cs0 - v1 * sn0;
                oB[e] = v1 * cs1 + v0 * sn1;
            }
            const int hidx = (n0 >> 6) + hh;
            const size_t base = ((size_t)(bb * NH_ + hidx) * S_ + s) * HD_;
            float hA[2], hB[2], pA[2], pB[2];
#pragma unroll
            for (int e = 0; e < 2; e++) {
                hA[e] = __half2float(__float2half_rn(oA[e]));
                hB[e] = __half2float(__float2half_rn(oB[e]));
                const float rA = oA[e] - hA[e], rB = oB[e] - hB[e];
                if (isq) { pA[e] = hA[e] + SPLIT_S * rA; pB[e] = hB[e] + SPLIT_S * rB; }
                else     { pA[e] = hA[e] * INV_S + rA;   pB[e] = hB[e] * INV_S + rB; }
            }
            *(uint32_t*)&Ch[base + d0]      = h2pack(hA[0], hA[1]);
            *(uint32_t*)&Ch[base + d0 + 32] = h2pack(hB[0], hB[1]);
            *(uint32_t*)&Cp[base + d0]      = h2pack(pA[0], pA[1]);
            *(uint32_t*)&Cp[base + d0 + 32] = h2pack(pB[0], pB[1]);
        }
    } else if (mode == 2) {
#pragma unroll 2
        for (int i = 0; i < 32; i++) {
            const int id  = tid + 256 * i;
            const int sp  = id & 63;
            const int c   = id >> 6;
            const int row0 = sp * 2;
            const int m   = m0 + row0;
            const int s   = m & (S_ - 1);
            const int bb  = m >> 11;
            const int n   = n0 + c;
            const int hidx = n >> 6, d = n & 63;
            const float v0 = Csm[row0 * LDC + c]       + bias[n];
            const float v1 = Csm[(row0 + 1) * LDC + c] + bias[n];
            const float h0 = __half2float(__float2half_rn(v0));
            const float h1 = __half2float(__float2half_rn(v1));
            const size_t o = ((size_t)(bb * NH_ + hidx) * HD_ + d) * S_ + s;
            *(uint32_t*)&g_vh[o] = h2pack(h0, h1);
            *(uint32_t*)&g_vp[o] = h2pack(h0 * INV_S + (v0 - h0),
                                          h1 * INV_S + (v1 - h1));
        }
    } else {
#pragma unroll 4
        for (int i = 0; i < 16; i++) {
            const int id  = tid + 256 * i;
            const int c4  = (id & 31) * 4;
            const int row = id >> 5;
            const int m   = m0 + row;
            const int n   = n0 + c4;
            float4 v;
            v.x = Csm[row * LDC + c4 + 0] + bias[n + 0];
            v.y = Csm[row * LDC + c4 + 1] + bias[n + 1];
            v.z = Csm[row * LDC + c4 + 2] + bias[n + 2];
            v.w = Csm[row * LDC + c4 + 3] + bias[n + 3];
            *(float4*)&Cext[(size_t)m * H_ + n] = v;
        }
    }
}

// ---------------------------------------------------------------------------
// Flash attention, fp16 2-MMA split, 256-ROW Q TILE: 8 warps x 32 q-rows
// (2 m-fragments). Each K/V fragment LDSM feeds 4 MMAs (2 mf x 2 n) -> B
// traffic per MMA halved vs 128-row tile; KV global traffic also halved.
// ---------------------------------------------------------------------------
constexpr int LDSA     = 144;
constexpr int QARR     = 256 * LDSA;            // 36864 per Q array
constexpr int QBYTES   = 2 * QARR;              // 73728 (Qh | Q')
constexpr int KVSTAGE  = 4 * 64 * LDSA;         // 36864 (Kh|K'|Vh|V')
constexpr int ATT2_SMEM = QBYTES + 3 * KVSTAGE; // 184320

__global__ void __launch_bounds__(256) attn_hmma(const int* __restrict__ mask)
{
    extern __shared__ char sm[];
    const uint32_t sb = smem_u32(sm);
    __shared__ int msk[3][64];

    const int tid = threadIdx.x, lane = tid & 31, w = tid >> 5;
    const int bh = blockIdx.y, b = bh >> 4, h = bh & 15;
    const int q0 = blockIdx.x * 256;

    const __half* Qhp = g_qh + (size_t)bh * S_ * HD_;
    const __half* Qpp = g_qp + (size_t)bh * S_ * HD_;
    const __half* Khp = g_kh + (size_t)bh * S_ * HD_;
    const __half* Kpp = g_kp + (size_t)bh * S_ * HD_;
    const __half* Vhp = g_vh + (size_t)bh * HD_ * S_;
    const __half* Vpp = g_vp + (size_t)bh * HD_ * S_;
    const int* maskp = mask + b * S_;

    // Q tile load: 256 rows x 2 arrays
#pragma unroll
    for (int i = 0; i < 8; i++) {
        const int idx = tid + 256 * i;          // 0..2047
        const int row = idx >> 3, chk = idx & 7;
        const uint32_t dst = sb + (uint32_t)(row * LDSA + chk * 16);
        CPA16(dst,        (const char*)(Qhp + (size_t)(q0 + row) * HD_ + chk * 8));
        CPA16(dst + QARR, (const char*)(Qpp + (size_t)(q0 + row) * HD_ + chk * 8));
    }

#define LOADKV(t) do {                                                          \
    const int kt_ = (t) * 64;                                                   \
    const uint32_t st = sb + QBYTES + ((t) % 3) * KVSTAGE;                      \
    _Pragma("unroll")                                                           \
    for (int i_ = 0; i_ < 2; i_++) {                                            \
        const int idx_ = tid + 256 * i_;                                        \
        const int row_ = idx_ >> 3, ch_ = idx_ & 7;                             \
        const uint32_t ro_ = (uint32_t)(row_ * LDSA + ch_ * 16);                \
        CPA16(st + ro_,          (const char*)(Khp + (size_t)(kt_ + row_) * HD_ + ch_ * 8)); \
        CPA16(st + 9216 + ro_,   (const char*)(Kpp + (size_t)(kt_ + row_) * HD_ + ch_ * 8)); \
        CPA16(st + 18432 + ro_,  (const char*)(Vhp + (size_t)row_ * S_ + kt_ + ch_ * 8));    \
        CPA16(st + 27648 + ro_,  (const char*)(Vpp + (size_t)row_ * S_ + kt_ + ch_ * 8));    \
    }                                                                           \
    if (tid < 64) msk[(t) % 3][tid] = maskp[kt_ + tid];                         \
    CP_COMMIT();                                                                \
} while (0)

    LOADKV(0);
    LOADKV(1);

    float m_[2][2], l_[2][2];
#pragma unroll
    for (int mf = 0; mf < 2; mf++) {
        m_[mf][0] = m_[mf][1] = -1e30f;
        l_[mf][0] = l_[mf][1] = 0.0f;
    }
    float oacc[2][8][4];
#pragma unroll
    for (int mf = 0; mf < 2; mf++)
#pragma unroll
        for (int n = 0; n < 8; n++)
#pragma unroll
            for (int j = 0; j < 4; j++) oacc[mf][n][j] = 0.0f;

    uint32_t qfh[2][4][4], qfp[2][4][4];
    const int c01 = (lane & 3) * 2;
    constexpr int NT = S_ / 64;

    for (int t = 0; t < NT; t++) {
        if (t >= NT - 2) { CP_WAIT(0); }
        else             { CP_WAIT(1); }
        __syncthreads();
        if (t + 2 < NT) LOADKV(t + 2);

        if (t == 0) {
#pragma unroll
            for (int mf = 0; mf < 2; mf++)
#pragma unroll
                for (int kk = 0; kk < 4; kk++) {
                    const uint32_t ad = sb
                        + (uint32_t)((w * 32 + mf * 16 + (lane & 15)) * LDSA
                                     + kk * 32 + ((lane >> 4) << 4));
                    LDSM4(qfh[mf][kk], ad);
                    LDSM4(qfp[mf][kk], ad + QARR);
                }
        }

        const uint32_t kst = sb + QBYTES + (t % 3) * KVSTAGE;

        // ---- S: pass1 M1 = Qh*Kh ----
        float sacc[2][8][4];
#pragma unroll
        for (int mf = 0; mf < 2; mf++)
#pragma unroll
            for (int n = 0; n < 8; n++)
#pragma unroll
                for (int j = 0; j < 4; j++) sacc[mf][n][j] = 0.0f;

#pragma unroll
        for (int kk = 0; kk < 4; kk++) {
            uint32_t rh[4][4];
#pragma unroll
            for (int nh = 0; nh < 4; nh++) {
                const uint32_t bd = kst
                    + (uint32_t)((nh * 16 + ((lane >> 4) << 3) + (lane & 7)) * LDSA
                                 + kk * 32 + (((lane >> 3) & 1) << 4));
                LDSM4(rh[nh], bd);
            }
#pragma unroll
            for (int nh = 0; nh < 4; nh++) {
                uint32_t b0[2] = {rh[nh][0], rh[nh][1]}, b1[2] = {rh[nh][2], rh[nh][3]};
                MMAF16(sacc[0][nh * 2],     qfh[0][kk], b0);
                MMAF16(sacc[0][nh * 2 + 1], qfh[0][kk], b1);
                MMAF16(sacc[1][nh * 2],     qfh[1][kk], b0);
                MMAF16(sacc[1][nh * 2 + 1], qfh[1][kk], b1);
            }
        }
#pragma unroll
        for (int mf = 0; mf < 2; mf++)
#pragma unroll
            for (int n = 0; n < 8; n++)
#pragma unroll
                for (int j = 0; j < 4; j++) sacc[mf][n][j] *= C1_;
        // ---- S: pass2 M2 = Q'*K' ----
#pragma unroll
        for (int kk = 0; kk < 4; kk++) {
            uint32_t rp[4][4];
#pragma unroll
            for (int nh = 0; nh < 4; nh++) {
                const uint32_t bd = kst + 9216
                    + (uint32_t)((nh * 16 + ((lane >> 4) << 3) + (lane & 7)) * LDSA
                                 + kk * 32 + (((lane >> 3) & 1) << 4));
                LDSM4(rp[nh], bd);
            }
#pragma unroll
            for (int nh = 0; nh < 4; nh++) {
                uint32_t b0[2] = {rp[nh][0], rp[nh][1]}, b1[2] = {rp[nh][2], rp[nh][3]};
                MMAF16(sacc[0][nh * 2],     qfp[0][kk], b0);
                MMAF16(sacc[0][nh * 2 + 1], qfp[0][kk], b1);
                MMAF16(sacc[1][nh * 2],     qfp[1][kk], b0);
                MMAF16(sacc[1][nh * 2 + 1], qfp[1][kk], b1);
            }
        }

        // ---- scale + mask + online softmax (per m-fragment) ----
#pragma unroll
        for (int mf = 0; mf < 2; mf++) {
            float mx[2] = {-1e30f, -1e30f};
#pragma unroll
            for (int n = 0; n < 8; n++) {
                const int cc = n * 8 + c01;
                const int mk0 = msk[t % 3][cc], mk1 = msk[t % 3][cc + 1];
#pragma unroll
                for (int j = 0; j < 4; j++) {
                    float v = sacc[mf][n][j] * 0.125f;
                    v = ((j & 1) ? mk1 : mk0) ? v : -1e30f;
                    sacc[mf][n][j] = v;
                    mx[j >> 1] = fmaxf(mx[j >> 1], v);
                }
            }
            float corr[2], rs[2] = {0.0f, 0.0f};
#pragma unroll
            for (int r = 0; r < 2; r++) {
                mx[r] = fmaxf(mx[r], __shfl_xor_sync(0xffffffffu, mx[r], 1, 4));
                mx[r] = fmaxf(mx[r], __shfl_xor_sync(0xffffffffu, mx[r], 2, 4));
                const float mn = fmaxf(m_[mf][r], mx[r]);
                corr[r] = __expf(m_[mf][r] - mn);
                m_[mf][r] = mn;
            }
#pragma unroll
            for (int n = 0; n < 8; n++)
#pragma unroll
                for (int j = 0; j < 4; j++) {
                    const float p = __expf(sacc[mf][n][j] - m_[mf][j >> 1]);
                    sacc[mf][n][j] = p;
                    rs[j >> 1] += p;
                }
#pragma unroll
            for (int r = 0; r < 2; r++) {
                rs[r] += __shfl_xor_sync(0xffffffffu, rs[r], 1, 4);
                rs[r] += __shfl_xor_sync(0xffffffffu, rs[r], 2, 4);
                l_[mf][r] = l_[mf][r] * corr[r] + rs[r];
            }
#pragma unroll
            for (int n = 0; n < 8; n++)
#pragma unroll
                for (int j = 0; j < 4; j++)
                    oacc[mf][n][j] *= corr[j >> 1] * INV_C1;
        }

        // ---- O: pass1 M1 = Ph*Vh ----
#pragma unroll
        for (int j = 0; j < 4; j++) {
            uint32_t aPh[2][4];
#pragma unroll
            for (int mf = 0; mf < 2; mf++)
#pragma unroll
                for (int half = 0; half < 2; half++) {
                    aPh[mf][half * 2]     = h2pack(sacc[mf][2 * j + half][0],
                                                   sacc[mf][2 * j + half][1]);
                    aPh[mf][half * 2 + 1] = h2pack(sacc[mf][2 * j + half][2],
                                                   sacc[mf][2 * j + half][3]);
                }
            uint32_t rh[4][4];
#pragma unroll
            for (int nh = 0; nh < 4; nh++) {
                const uint32_t bd = kst + 18432
                    + (uint32_t)((nh * 16 + ((lane >> 4) << 3) + (lane & 7)) * LDSA
                                 + j * 32 + (((lane >> 3) & 1) << 4));
                LDSM4(rh[nh], bd);
            }
#pragma unroll
            for (int nh = 0; nh < 4; nh++) {
                uint32_t b0[2] = {rh[nh][0], rh[nh][1]}, b1[2] = {rh[nh][2], rh[nh][3]};
                MMAF16(oacc[0][nh * 2],     aPh[0], b0);
                MMAF16(oacc[0][nh * 2 + 1], aPh[0], b1);
                MMAF16(oacc[1][nh * 2],     aPh[1], b0);
                MMAF16(oacc[1][nh * 2 + 1], aPh[1], b1);
            }
        }
#pragma unroll
        for (int mf = 0; mf < 2; mf++)
#pragma unroll
            for (int n = 0; n < 8; n++)
#pragma unroll
                for (int j = 0; j < 4; j++) oacc[mf][n][j] *= C1_;
        // ---- O: pass2 M2 = P'*V' ----
#pragma unroll
        for (int j = 0; j < 4; j++) {
            uint32_t aPp[2][4];
#pragma unroll
            for (int mf = 0; mf < 2; mf++)
#pragma unroll
                for (int half = 0; half < 2; half++) {
                    float pv[4];
#pragma unroll
                    for (int e = 0; e < 4; e++) {
                        const float p = sacc[mf][2 * j + half][e];
                        const float ph = __half2float(__float2half_rn(p));
                        pv[e] = ph + SPLIT_S * (p - ph);
                    }
                    aPp[mf][half * 2]     = h2pack(pv[0], pv[1]);
                    aPp[mf][half * 2 + 1] = h2pack(pv[2], pv[3]);
                }
            uint32_t rp[4][4];
#pragma unroll
            for (int nh = 0; nh < 4; nh++) {
                const uint32_t bd = kst + 27648
                    + (uint32_t)((nh * 16 + ((lane >> 4) << 3) + (lane & 7)) * LDSA
                                 + j * 32 + (((lane >> 3) & 1) << 4));
                LDSM4(rp[nh], bd);
            }
#pragma unroll
            for (int nh = 0; nh < 4; nh++) {
                uint32_t b0[2] = {rp[nh][0], rp[nh][1]}, b1[2] = {rp[nh][2], rp[nh][3]};
                MMAF16(oacc[0][nh * 2],     aPp[0], b0);
                MMAF16(oacc[0][nh * 2 + 1], aPp[0], b1);
                MMAF16(oacc[1][nh * 2],     aPp[1], b0);
                MMAF16(oacc[1][nh * 2 + 1], aPp[1], b1);
            }
        }
    }

    // ---- epilogue: /l, write fp16 A-side pairs to g_ah/g_ap [M,H] ----
    const int r0 = lane >> 2;
#pragma unroll
    for (int mf = 0; mf < 2; mf++)
#pragma unroll
        for (int r = 0; r < 2; r++) {
            const float inv = 1.0f / l_[mf][r];
            const int srow = q0 + w * 32 + mf * 16 + r0 + 8 * r;
            const size_t base = ((size_t)b * S_ + srow) * H_ + h * 64 + c01;
#pragma unroll
            for (int n = 0; n < 8; n++) {
                const float v0 = oacc[mf][n][2 * r]     * inv;
                const float v1 = oacc[mf][n][2 * r + 1] * inv;
                const float h0 = __half2float(__float2half_rn(v0));
                const float h1 = __half2float(__float2half_rn(v1));
                *(uint32_t*)&g_ah[base + n * 8] = h2pack(h0, h1);
                *(uint32_t*)&g_ap[base + n * 8] = h2pack(h0 + SPLIT_S * (v0 - h0),
                                                         h1 + SPLIT_S * (v1 - h1));
            }
        }
}

// ---------------------------------------------------------------------------
extern "C" void kernel_launch(void* const* d_in, const int* in_sizes, int n_in,
                              void* d_out, int out_size)
{
    const float* x    = (const float*)d_in[0];
    const int*   mask = (const int*)  d_in[1];
    const float* cosb = (const float*)d_in[2];
    const float* sinb = (const float*)d_in[3];
    const float* Wq   = (const float*)d_in[4];
    const float* bq   = (const float*)d_in[5];
    const float* Wk   = (const float*)d_in[6];
    const float* bk   = (const float*)d_in[7];
    const float* Wv   = (const float*)d_in[8];
    const float* bv   = (const float*)d_in[9];
    const float* Wo   = (const float*)d_in[10];
    const float* bo   = (const float*)d_in[11];
    float* out = (float*)d_out;

    cudaFuncSetAttribute(hgemm,
                         cudaFuncAttributeMaxDynamicSharedMemorySize, GEMM_SMEM);
    cudaFuncSetAttribute(attn_hmma,
                         cudaFuncAttributeMaxDynamicSharedMemorySize, ATT2_SMEM);

    cvt_all<<<(M_ * K_ + 4 * H_ * K_) / 1024, 256>>>(x, Wq, Wk, Wv, Wo);

    dim3 gqkv(H_ / 128, M_ / 128, 3);
    hgemm<<<gqkv, 256, GEMM_SMEM>>>(bq, bk, bv, nullptr, cosb, sinb, -1);

    dim3 ag(S_ / 256, B_ * NH_);   // (8, 32)
    attn_hmma<<<ag, 256, ATT2_SMEM>>>(mask);

    dim3 gg(H_ / 128, M_ / 128);
    hgemm<<<gg, 256, GEMM_SMEM>>>(bo, bo, bo, out, cosb, sinb, 3);
}